// round 1
// baseline (speedup 1.0000x reference)
#include <cuda_runtime.h>

#define HID 128
#define MAXN 50048
#define LN_EPS 1e-5f

// Scratch (no allocations allowed): aggregated messages per node.
__device__ float g_agg[(size_t)MAXN * HID];
__device__ int g_idx64;

// Detect whether edge_index arrived as int64 (JAX x64 on) or int32 (x64 off).
// int64 little-endian non-negative values < 2^31 => odd int32 words are 0.
__global__ void detect_kernel(const int* __restrict__ ei) {
    g_idx64 = (ei[1] == 0 && ei[3] == 0 && ei[5] == 0 && ei[7] == 0) ? 1 : 0;
}

__global__ void zero_kernel(int n4) {
    int i = blockIdx.x * blockDim.x + threadIdx.x;
    if (i < n4) ((float4*)g_agg)[i] = make_float4(0.f, 0.f, 0.f, 0.f);
}

// ---------------------------------------------------------------------------
// Edge kernel: per block, 32 edges.
//   msg_in[32][384] = concat(x[src], x[dst], edge_attr)
//   h = relu(msg_in @ W1 + b1)   (384 -> 128)
//   m = h @ W2 + b2              (128 -> 128)
//   atomicAdd into g_agg[dst]
// Thread tile: 4 edges x 4 cols (float4 weights).
// ---------------------------------------------------------------------------
#define EDGE_SMEM ((32*384 + 32*128 + 32*128 + 64) * 4)

__global__ __launch_bounds__(256, 2)
void edge_kernel(const float* __restrict__ x,
                 const void*  __restrict__ eidx,
                 const float* __restrict__ eattr,
                 const float* __restrict__ W1, const float* __restrict__ b1,
                 const float* __restrict__ W2, const float* __restrict__ b2,
                 int E)
{
    extern __shared__ float smem[];
    float* s_in = smem;                       // 32*384
    float* s_h  = smem + 32*384;              // 32*128
    float* s_w  = s_h  + 32*128;              // 32*128
    int*   s_src = (int*)(s_w + 32*128);      // 32
    int*   s_dst = s_src + 32;                // 32

    const int tid = threadIdx.x;
    const int e0  = blockIdx.x * 32;

    if (tid < 32) {
        int e = e0 + tid;
        int s = 0, d = -1;
        if (e < E) {
            if (g_idx64) {
                s = (int)((const long long*)eidx)[e];
                d = (int)((const long long*)eidx)[(size_t)E + e];
            } else {
                s = ((const int*)eidx)[e];
                d = ((const int*)eidx)[(size_t)E + e];
            }
        }
        s_src[tid] = s;
        s_dst[tid] = d;
    }
    __syncthreads();

    // Stage msg_in (float4). Row layout: [x_src(128) | x_dst(128) | eattr(128)]
    {
        const float4* x4  = (const float4*)x;
        const float4* ea4 = (const float4*)eattr;
        float4* s_in4 = (float4*)s_in;
        for (int i = tid; i < 32 * 96; i += 256) {
            int e = i / 96;
            int q = i - e * 96;
            float4 v = make_float4(0.f, 0.f, 0.f, 0.f);
            if (e0 + e < E) {
                if (q < 32)      v = x4[(size_t)s_src[e] * 32 + q];
                else if (q < 64) v = x4[(size_t)s_dst[e] * 32 + (q - 32)];
                else             v = ea4[(size_t)(e0 + e) * 32 + (q - 64)];
            }
            s_in4[i] = v;
        }
    }

    const int cg = tid & 31;   // 32 col groups * 4 cols
    const int eg = tid >> 5;   // 8 edge groups * 4 edges
    const int eb = eg * 4;
    float4* s_w4 = (float4*)s_w;

    // ---- Layer 1: 384 -> 128 ----
    float acc[4][4];
    #pragma unroll
    for (int a = 0; a < 4; a++)
        #pragma unroll
        for (int b = 0; b < 4; b++) acc[a][b] = 0.f;

    {
        const float4* W1_4 = (const float4*)W1;
        for (int kt = 0; kt < 384; kt += 32) {
            __syncthreads();
            #pragma unroll 4
            for (int i = tid; i < 1024; i += 256)
                s_w4[i] = W1_4[(size_t)(kt + (i >> 5)) * 32 + (i & 31)];
            __syncthreads();
            #pragma unroll 8
            for (int kk = 0; kk < 32; kk++) {
                float4 w = s_w4[kk * 32 + cg];
                #pragma unroll
                for (int e = 0; e < 4; e++) {
                    float xv = s_in[(eb + e) * 384 + kt + kk];
                    acc[e][0] = fmaf(xv, w.x, acc[e][0]);
                    acc[e][1] = fmaf(xv, w.y, acc[e][1]);
                    acc[e][2] = fmaf(xv, w.z, acc[e][2]);
                    acc[e][3] = fmaf(xv, w.w, acc[e][3]);
                }
            }
        }
    }
    // bias + relu -> s_h
    {
        float4 bv = ((const float4*)b1)[cg];
        float4* s_h4 = (float4*)s_h;
        #pragma unroll
        for (int e = 0; e < 4; e++) {
            float4 v;
            v.x = fmaxf(acc[e][0] + bv.x, 0.f);
            v.y = fmaxf(acc[e][1] + bv.y, 0.f);
            v.z = fmaxf(acc[e][2] + bv.z, 0.f);
            v.w = fmaxf(acc[e][3] + bv.w, 0.f);
            s_h4[(eb + e) * 32 + cg] = v;
        }
    }

    // ---- Layer 2: 128 -> 128 ----
    float acc2[4][4];
    #pragma unroll
    for (int a = 0; a < 4; a++)
        #pragma unroll
        for (int b = 0; b < 4; b++) acc2[a][b] = 0.f;

    {
        const float4* W2_4 = (const float4*)W2;
        for (int kt = 0; kt < 128; kt += 32) {
            __syncthreads();
            #pragma unroll 4
            for (int i = tid; i < 1024; i += 256)
                s_w4[i] = W2_4[(size_t)(kt + (i >> 5)) * 32 + (i & 31)];
            __syncthreads();
            #pragma unroll 8
            for (int kk = 0; kk < 32; kk++) {
                float4 w = s_w4[kk * 32 + cg];
                #pragma unroll
                for (int e = 0; e < 4; e++) {
                    float hv = s_h[(eb + e) * 128 + kt + kk];
                    acc2[e][0] = fmaf(hv, w.x, acc2[e][0]);
                    acc2[e][1] = fmaf(hv, w.y, acc2[e][1]);
                    acc2[e][2] = fmaf(hv, w.z, acc2[e][2]);
                    acc2[e][3] = fmaf(hv, w.w, acc2[e][3]);
                }
            }
        }
    }

    // bias + scatter-add
    {
        float4 bv = ((const float4*)b2)[cg];
        #pragma unroll
        for (int e = 0; e < 4; e++) {
            int d = s_dst[eb + e];
            if (d >= 0) {
                float* dst = g_agg + (size_t)d * HID + cg * 4;
                atomicAdd(dst + 0, acc2[e][0] + bv.x);
                atomicAdd(dst + 1, acc2[e][1] + bv.y);
                atomicAdd(dst + 2, acc2[e][2] + bv.z);
                atomicAdd(dst + 3, acc2[e][3] + bv.w);
            }
        }
    }
}

// ---------------------------------------------------------------------------
// Node kernel: per block, 32 nodes.
//   upd_in[32][256] = concat(x, agg); u = relu(upd_in@W1+b1); upd = u@W2+b2
//   out = LayerNorm(x + upd) * gamma + beta
// ---------------------------------------------------------------------------
#define NODE_SMEM ((32*256 + 32*128 + 32*128 + 64) * 4)

__global__ __launch_bounds__(256, 2)
void node_kernel(const float* __restrict__ x,
                 const float* __restrict__ W1, const float* __restrict__ b1,
                 const float* __restrict__ W2, const float* __restrict__ b2,
                 const float* __restrict__ gamma, const float* __restrict__ beta,
                 float* __restrict__ out, int N)
{
    extern __shared__ float smem[];
    float* s_in = smem;                       // 32*256 (reused as s_out)
    float* s_h  = smem + 32*256;              // 32*128
    float* s_w  = s_h  + 32*128;              // 32*128
    float* s_mu = s_w  + 32*128;              // 32
    float* s_rs = s_mu + 32;                  // 32

    const int tid = threadIdx.x;
    const int n0  = blockIdx.x * 32;

    // Stage upd_in: [x(128) | agg(128)]
    {
        const float4* x4 = (const float4*)x;
        const float4* g4 = (const float4*)g_agg;
        float4* s_in4 = (float4*)s_in;
        for (int i = tid; i < 32 * 64; i += 256) {
            int n = i >> 6, q = i & 63;
            float4 v = make_float4(0.f, 0.f, 0.f, 0.f);
            if (n0 + n < N) {
                if (q < 32) v = x4[(size_t)(n0 + n) * 32 + q];
                else        v = g4[(size_t)(n0 + n) * 32 + (q - 32)];
            }
            s_in4[i] = v;
        }
    }

    const int cg = tid & 31;
    const int eg = tid >> 5;
    const int nb = eg * 4;
    float4* s_w4 = (float4*)s_w;

    // ---- Layer 1: 256 -> 128 ----
    float acc[4][4];
    #pragma unroll
    for (int a = 0; a < 4; a++)
        #pragma unroll
        for (int b = 0; b < 4; b++) acc[a][b] = 0.f;

    {
        const float4* W1_4 = (const float4*)W1;
        for (int kt = 0; kt < 256; kt += 32) {
            __syncthreads();
            #pragma unroll 4
            for (int i = tid; i < 1024; i += 256)
                s_w4[i] = W1_4[(size_t)(kt + (i >> 5)) * 32 + (i & 31)];
            __syncthreads();
            #pragma unroll 8
            for (int kk = 0; kk < 32; kk++) {
                float4 w = s_w4[kk * 32 + cg];
                #pragma unroll
                for (int e = 0; e < 4; e++) {
                    float xv = s_in[(nb + e) * 256 + kt + kk];
                    acc[e][0] = fmaf(xv, w.x, acc[e][0]);
                    acc[e][1] = fmaf(xv, w.y, acc[e][1]);
                    acc[e][2] = fmaf(xv, w.z, acc[e][2]);
                    acc[e][3] = fmaf(xv, w.w, acc[e][3]);
                }
            }
        }
    }
    {
        float4 bv = ((const float4*)b1)[cg];
        float4* s_h4 = (float4*)s_h;
        #pragma unroll
        for (int e = 0; e < 4; e++) {
            float4 v;
            v.x = fmaxf(acc[e][0] + bv.x, 0.f);
            v.y = fmaxf(acc[e][1] + bv.y, 0.f);
            v.z = fmaxf(acc[e][2] + bv.z, 0.f);
            v.w = fmaxf(acc[e][3] + bv.w, 0.f);
            s_h4[(nb + e) * 32 + cg] = v;
        }
    }

    // ---- Layer 2: 128 -> 128 ----
    float acc2[4][4];
    #pragma unroll
    for (int a = 0; a < 4; a++)
        #pragma unroll
        for (int b = 0; b < 4; b++) acc2[a][b] = 0.f;

    {
        const float4* W2_4 = (const float4*)W2;
        for (int kt = 0; kt < 128; kt += 32) {
            __syncthreads();
            #pragma unroll 4
            for (int i = tid; i < 1024; i += 256)
                s_w4[i] = W2_4[(size_t)(kt + (i >> 5)) * 32 + (i & 31)];
            __syncthreads();
            #pragma unroll 8
            for (int kk = 0; kk < 32; kk++) {
                float4 w = s_w4[kk * 32 + cg];
                #pragma unroll
                for (int e = 0; e < 4; e++) {
                    float hv = s_h[(nb + e) * 128 + kt + kk];
                    acc2[e][0] = fmaf(hv, w.x, acc2[e][0]);
                    acc2[e][1] = fmaf(hv, w.y, acc2[e][1]);
                    acc2[e][2] = fmaf(hv, w.z, acc2[e][2]);
                    acc2[e][3] = fmaf(hv, w.w, acc2[e][3]);
                }
            }
        }
    }

    // residual: y = x + upd  (overwrite s_in as s_out; all s_in reads are done)
    float* s_out = s_in;
    {
        const float4* x4 = (const float4*)x;
        float4 bv = ((const float4*)b2)[cg];
        float4* s_out4 = (float4*)s_out;
        #pragma unroll
        for (int e = 0; e < 4; e++) {
            int n = n0 + nb + e;
            float4 xv = make_float4(0.f, 0.f, 0.f, 0.f);
            if (n < N) xv = x4[(size_t)n * 32 + cg];
            float4 v;
            v.x = acc2[e][0] + bv.x + xv.x;
            v.y = acc2[e][1] + bv.y + xv.y;
            v.z = acc2[e][2] + bv.z + xv.z;
            v.w = acc2[e][3] + bv.w + xv.w;
            s_out4[(nb + e) * 32 + cg] = v;
        }
    }
    __syncthreads();

    // LayerNorm stats: 8 threads per node
    {
        int n  = tid >> 3;
        int l8 = tid & 7;
        const float* row = s_out + n * 128;
        float sum = 0.f;
        #pragma unroll
        for (int c = 0; c < 16; c++) sum += row[l8 * 16 + c];
        sum += __shfl_xor_sync(0xffffffffu, sum, 4);
        sum += __shfl_xor_sync(0xffffffffu, sum, 2);
        sum += __shfl_xor_sync(0xffffffffu, sum, 1);
        float mu = sum * (1.f / 128.f);
        float ss = 0.f;
        #pragma unroll
        for (int c = 0; c < 16; c++) {
            float d = row[l8 * 16 + c] - mu;
            ss = fmaf(d, d, ss);
        }
        ss += __shfl_xor_sync(0xffffffffu, ss, 4);
        ss += __shfl_xor_sync(0xffffffffu, ss, 2);
        ss += __shfl_xor_sync(0xffffffffu, ss, 1);
        float rs = rsqrtf(ss * (1.f / 128.f) + LN_EPS);
        if (l8 == 0) { s_mu[n] = mu; s_rs[n] = rs; }
    }
    __syncthreads();

    // write output
    {
        float4* out4 = (float4*)out;
        const float4* gm4 = (const float4*)gamma;
        const float4* bt4 = (const float4*)beta;
        float4* s_out4 = (float4*)s_out;
        for (int i = tid; i < 32 * 32; i += 256) {
            int n = i >> 5, c4 = i & 31;
            if (n0 + n < N) {
                float4 v = s_out4[i];
                float mu = s_mu[n], rs = s_rs[n];
                float4 g = gm4[c4], bt = bt4[c4];
                v.x = fmaf((v.x - mu) * rs, g.x, bt.x);
                v.y = fmaf((v.y - mu) * rs, g.y, bt.y);
                v.z = fmaf((v.z - mu) * rs, g.z, bt.z);
                v.w = fmaf((v.w - mu) * rs, g.w, bt.w);
                out4[(size_t)(n0 + n) * 32 + c4] = v;
            }
        }
    }
}

extern "C" void kernel_launch(void* const* d_in, const int* in_sizes, int n_in,
                              void* d_out, int out_size) {
    const float* x     = (const float*)d_in[0];
    const void*  eidx  = d_in[1];
    const float* eattr = (const float*)d_in[2];
    const float* mW1 = (const float*)d_in[3];
    const float* mb1 = (const float*)d_in[4];
    const float* mW2 = (const float*)d_in[5];
    const float* mb2 = (const float*)d_in[6];
    const float* uW1 = (const float*)d_in[7];
    const float* ub1 = (const float*)d_in[8];
    const float* uW2 = (const float*)d_in[9];
    const float* ub2 = (const float*)d_in[10];
    const float* gamma = (const float*)d_in[11];
    const float* beta  = (const float*)d_in[12];
    float* out = (float*)d_out;

    const int N = in_sizes[0] / HID;          // 50000
    const int E = in_sizes[2] / HID;          // 640000 (edge_attr count, dtype-safe)

    cudaFuncSetAttribute(edge_kernel, cudaFuncAttributeMaxDynamicSharedMemorySize, EDGE_SMEM);
    cudaFuncSetAttribute(node_kernel, cudaFuncAttributeMaxDynamicSharedMemorySize, NODE_SMEM);

    detect_kernel<<<1, 1>>>((const int*)eidx);

    int zcnt = (N * HID) / 4;
    zero_kernel<<<(zcnt + 255) / 256, 256>>>(zcnt);

    edge_kernel<<<(E + 31) / 32, 256, EDGE_SMEM>>>(x, eidx, eattr,
                                                   mW1, mb1, mW2, mb2, E);

    node_kernel<<<(N + 31) / 32, 256, NODE_SMEM>>>(x, uW1, ub1, uW2, ub2,
                                                   gamma, beta, out, N);
}

// round 3
// speedup vs baseline: 3.3235x; 3.3235x over previous
#include <cuda_runtime.h>
#include <cuda_pipeline.h>

#define HID 128
#define MAXN 50048
#define LN_EPS 1e-5f

__device__ __align__(256) float g_agg[(size_t)MAXN * HID];
__device__ int g_idx64;

__global__ void detect_kernel(const int* __restrict__ ei) {
    g_idx64 = (ei[1] == 0 && ei[3] == 0 && ei[5] == 0 && ei[7] == 0) ? 1 : 0;
}

__global__ void zero_kernel(int n4) {
    int i = blockIdx.x * blockDim.x + threadIdx.x;
    if (i < n4) ((float4*)g_agg)[i] = make_float4(0.f, 0.f, 0.f, 0.f);
}

// ---- tiling ----
#define BM 64          // rows (edges/nodes) per block
#define KT 32          // K chunk
#define PADA 36        // sA row stride (floats): bank=(4g+t)%32 conflict-free
#define PADB 136       // sB row stride: bank=(8t+g)%32 conflict-free
#define PADH 132       // sH row stride: bank=(4g+t)%32 conflict-free, 16B-aligned rows

#define OFF_A 0
#define SZ_A  (2*BM*PADA)        // 4608
#define OFF_B (OFF_A + SZ_A)
#define SZ_B  (2*KT*PADB)        // 8704
#define OFF_H (OFF_B + SZ_B)     // 13312
#define SZ_H  (BM*PADH)          // 8448
#define OFF_X (OFF_H + SZ_H)     // 21760
#define SMEM_FLOATS (OFF_X + 160)
#define SMEM_BYTES  (SMEM_FLOATS * 4)

// ---- tf32 helpers ----
__device__ __forceinline__ void tf32_split(float v, unsigned& hi, unsigned& lo) {
    unsigned h = __float_as_uint(v) & 0xffffe000u;
    hi = h;
    lo = __float_as_uint(v - __uint_as_float(h));
}

__device__ __forceinline__ void mma8(float d[4], const unsigned a[4], const unsigned b[2]) {
    asm volatile(
        "mma.sync.aligned.m16n8k8.row.col.f32.tf32.tf32.f32 "
        "{%0,%1,%2,%3}, {%4,%5,%6,%7}, {%8,%9}, {%0,%1,%2,%3};\n"
        : "+f"(d[0]), "+f"(d[1]), "+f"(d[2]), "+f"(d[3])
        : "r"(a[0]), "r"(a[1]), "r"(a[2]), "r"(a[3]), "r"(b[0]), "r"(b[1]));
}

__device__ __forceinline__ void red2(float* p, float a, float b) {
    asm volatile("red.global.add.v2.f32 [%0], {%1, %2};" :: "l"(p), "f"(a), "f"(b) : "memory");
}

// One KT=32 chunk of the GEMM: acc[2][4][4] += A(64xKT) * B(KTx128), 3xTF32.
__device__ __forceinline__ void gemm_chunk(const float* __restrict__ Ab, int astr,
                                           const float* __restrict__ Bb,
                                           int g, int t, int wm, int wn,
                                           float acc[2][4][4])
{
    #pragma unroll
    for (int k8 = 0; k8 < 4; k8++) {
        unsigned ah[2][4], al[2][4];
        #pragma unroll
        for (int i = 0; i < 2; i++) {
            const float* ap = Ab + (wm*32 + i*16 + g) * astr + k8*8 + t;
            float v0 = ap[0];
            float v1 = ap[8*astr];
            float v2 = ap[4];
            float v3 = ap[8*astr + 4];
            tf32_split(v0, ah[i][0], al[i][0]);
            tf32_split(v1, ah[i][1], al[i][1]);
            tf32_split(v2, ah[i][2], al[i][2]);
            tf32_split(v3, ah[i][3], al[i][3]);
        }
        unsigned bh[4][2], bl[4][2];
        #pragma unroll
        for (int j = 0; j < 4; j++) {
            const float* bp = Bb + (k8*8 + t) * PADB + wn*32 + j*8 + g;
            float u0 = bp[0];
            float u1 = bp[4*PADB];
            tf32_split(u0, bh[j][0], bl[j][0]);
            tf32_split(u1, bh[j][1], bl[j][1]);
        }
        #pragma unroll
        for (int i = 0; i < 2; i++)
            #pragma unroll
            for (int j = 0; j < 4; j++) {
                mma8(acc[i][j], ah[i], bh[j]);
                mma8(acc[i][j], al[i], bh[j]);
                mma8(acc[i][j], ah[i], bl[j]);
            }
    }
}

// ---------------------------------------------------------------------------
// Edge kernel: 64 edges/block.  h=relu([x_s|x_d|ea]@W1+b1); m=h@W2+b2; red->agg
// ---------------------------------------------------------------------------
__global__ __launch_bounds__(256)
void edge_kernel(const float* __restrict__ x, const void* __restrict__ eidx,
                 const float* __restrict__ eattr,
                 const float* __restrict__ W1, const float* __restrict__ b1,
                 const float* __restrict__ W2, const float* __restrict__ b2,
                 int E)
{
    extern __shared__ float sm[];
    float* sA = sm + OFF_A;
    float* sB = sm + OFF_B;
    float* sH = sm + OFF_H;
    int* s_src = (int*)(sm + OFF_X);
    int* s_dst = s_src + BM;

    const int tid  = threadIdx.x;
    const int e0   = blockIdx.x * BM;
    const int lane = tid & 31;
    const int wid  = tid >> 5;
    const int wm   = wid >> 2;
    const int wn   = wid & 3;
    const int g    = lane >> 2;
    const int t    = lane & 3;

    if (tid < BM) {
        int e = e0 + tid;
        int s = 0, d = 0;
        if (e < E) {
            if (g_idx64) {
                s = (int)((const long long*)eidx)[e];
                d = (int)((const long long*)eidx)[(size_t)E + e];
            } else {
                s = ((const int*)eidx)[e];
                d = ((const int*)eidx)[(size_t)E + e];
            }
        }
        s_src[tid] = s; s_dst[tid] = d;
    }
    __syncthreads();

    auto stageA = [&](int c, int buf) {
        const int kt = c * KT;
        float* dst = sA + buf * (BM * PADA);
        #pragma unroll
        for (int i = tid; i < BM * 8; i += 256) {
            int e = i >> 3, q = (i & 7) << 2;
            const float* src;
            if (kt < 128)       src = x + (size_t)s_src[e] * HID + kt + q;
            else if (kt < 256)  src = x + (size_t)s_dst[e] * HID + (kt - 128) + q;
            else {
                int ge = e0 + e; if (ge >= E) ge = E - 1;
                src = eattr + (size_t)ge * HID + (kt - 256) + q;
            }
            __pipeline_memcpy_async(dst + e * PADA + q, src, 16);
        }
    };
    auto stageB = [&](const float* W, int c, int buf) {
        const int kt = c * KT;
        float* dst = sB + buf * (KT * PADB);
        #pragma unroll
        for (int i = tid; i < KT * 32; i += 256) {
            int r = i >> 5, q = (i & 31) << 2;
            __pipeline_memcpy_async(dst + r * PADB + q, W + (size_t)(kt + r) * HID + q, 16);
        }
    };

    // ---- Layer 1: K = 384, 12 chunks ----
    float acc[2][4][4];
    #pragma unroll
    for (int i = 0; i < 2; i++)
        #pragma unroll
        for (int j = 0; j < 4; j++)
            #pragma unroll
            for (int r = 0; r < 4; r++) acc[i][j][r] = 0.f;

    stageA(0, 0); stageB(W1, 0, 0); __pipeline_commit();
    #pragma unroll 1
    for (int c = 0; c < 12; c++) {
        if (c + 1 < 12) {
            stageA(c + 1, (c + 1) & 1); stageB(W1, c + 1, (c + 1) & 1);
            __pipeline_commit();
            __pipeline_wait_prior(1);
        } else {
            __pipeline_wait_prior(0);
        }
        __syncthreads();
        gemm_chunk(sA + (c & 1) * (BM * PADA), PADA, sB + (c & 1) * (KT * PADB),
                   g, t, wm, wn, acc);
        __syncthreads();
    }

    // prefetch W2 chunk 0 while writing sH
    stageB(W2, 0, 0); __pipeline_commit();

    // bias + relu -> sH
    #pragma unroll
    for (int i = 0; i < 2; i++) {
        int r0 = wm * 32 + i * 16;
        #pragma unroll
        for (int j = 0; j < 4; j++) {
            int c0 = wn * 32 + j * 8 + 2 * t;
            float2 bb = *(const float2*)(b1 + c0);
            float* h0 = sH + (r0 + g) * PADH + c0;
            h0[0] = fmaxf(acc[i][j][0] + bb.x, 0.f);
            h0[1] = fmaxf(acc[i][j][1] + bb.y, 0.f);
            float* h1 = sH + (r0 + g + 8) * PADH + c0;
            h1[0] = fmaxf(acc[i][j][2] + bb.x, 0.f);
            h1[1] = fmaxf(acc[i][j][3] + bb.y, 0.f);
        }
    }
    __syncthreads();

    // ---- Layer 2: K = 128, 4 chunks, A = sH ----
    float acc2[2][4][4];
    #pragma unroll
    for (int i = 0; i < 2; i++)
        #pragma unroll
        for (int j = 0; j < 4; j++)
            #pragma unroll
            for (int r = 0; r < 4; r++) acc2[i][j][r] = 0.f;

    #pragma unroll 1
    for (int c = 0; c < 4; c++) {
        if (c + 1 < 4) {
            stageB(W2, c + 1, (c + 1) & 1);
            __pipeline_commit();
            __pipeline_wait_prior(1);
        } else {
            __pipeline_wait_prior(0);
        }
        __syncthreads();
        gemm_chunk(sH + c * KT, PADH, sB + (c & 1) * (KT * PADB), g, t, wm, wn, acc2);
        __syncthreads();
    }

    // bias + scatter-add (vector red)
    #pragma unroll
    for (int i = 0; i < 2; i++) {
        int r0 = wm * 32 + i * 16;
        #pragma unroll
        for (int j = 0; j < 4; j++) {
            int c0 = wn * 32 + j * 8 + 2 * t;
            float2 bb = *(const float2*)(b2 + c0);
            int ra = r0 + g, rb = ra + 8;
            if (e0 + ra < E)
                red2(g_agg + (size_t)s_dst[ra] * HID + c0,
                     acc2[i][j][0] + bb.x, acc2[i][j][1] + bb.y);
            if (e0 + rb < E)
                red2(g_agg + (size_t)s_dst[rb] * HID + c0,
                     acc2[i][j][2] + bb.x, acc2[i][j][3] + bb.y);
        }
    }
}

// ---------------------------------------------------------------------------
// Node kernel: 64 nodes/block. u=relu([x|agg]@W1+b1); upd=u@W2+b2; LN(x+upd)
// ---------------------------------------------------------------------------
__global__ __launch_bounds__(256)
void node_kernel(const float* __restrict__ x,
                 const float* __restrict__ W1, const float* __restrict__ b1,
                 const float* __restrict__ W2, const float* __restrict__ b2,
                 const float* __restrict__ gamma, const float* __restrict__ beta,
                 float* __restrict__ out, int N)
{
    extern __shared__ float sm[];
    float* sA = sm + OFF_A;
    float* sB = sm + OFF_B;
    float* sH = sm + OFF_H;
    float* s_mu = sm + OFF_X;
    float* s_rs = s_mu + BM;

    const int tid  = threadIdx.x;
    const int n0   = blockIdx.x * BM;
    const int lane = tid & 31;
    const int wid  = tid >> 5;
    const int wm   = wid >> 2;
    const int wn   = wid & 3;
    const int g    = lane >> 2;
    const int t    = lane & 3;

    auto stageA = [&](int c, int buf) {
        const int kt = c * KT;
        float* dst = sA + buf * (BM * PADA);
        #pragma unroll
        for (int i = tid; i < BM * 8; i += 256) {
            int e = i >> 3, q = (i & 7) << 2;
            int n = n0 + e; if (n >= N) n = N - 1;
            const float* src = (kt < 128) ? (x + (size_t)n * HID + kt + q)
                                          : (g_agg + (size_t)n * HID + (kt - 128) + q);
            __pipeline_memcpy_async(dst + e * PADA + q, src, 16);
        }
    };
    auto stageB = [&](const float* W, int c, int buf) {
        const int kt = c * KT;
        float* dst = sB + buf * (KT * PADB);
        #pragma unroll
        for (int i = tid; i < KT * 32; i += 256) {
            int r = i >> 5, q = (i & 31) << 2;
            __pipeline_memcpy_async(dst + r * PADB + q, W + (size_t)(kt + r) * HID + q, 16);
        }
    };

    // ---- Layer 1: K = 256, 8 chunks ----
    float acc[2][4][4];
    #pragma unroll
    for (int i = 0; i < 2; i++)
        #pragma unroll
        for (int j = 0; j < 4; j++)
            #pragma unroll
            for (int r = 0; r < 4; r++) acc[i][j][r] = 0.f;

    stageA(0, 0); stageB(W1, 0, 0); __pipeline_commit();
    #pragma unroll 1
    for (int c = 0; c < 8; c++) {
        if (c + 1 < 8) {
            stageA(c + 1, (c + 1) & 1); stageB(W1, c + 1, (c + 1) & 1);
            __pipeline_commit();
            __pipeline_wait_prior(1);
        } else {
            __pipeline_wait_prior(0);
        }
        __syncthreads();
        gemm_chunk(sA + (c & 1) * (BM * PADA), PADA, sB + (c & 1) * (KT * PADB),
                   g, t, wm, wn, acc);
        __syncthreads();
    }

    stageB(W2, 0, 0); __pipeline_commit();

    #pragma unroll
    for (int i = 0; i < 2; i++) {
        int r0 = wm * 32 + i * 16;
        #pragma unroll
        for (int j = 0; j < 4; j++) {
            int c0 = wn * 32 + j * 8 + 2 * t;
            float2 bb = *(const float2*)(b1 + c0);
            float* h0 = sH + (r0 + g) * PADH + c0;
            h0[0] = fmaxf(acc[i][j][0] + bb.x, 0.f);
            h0[1] = fmaxf(acc[i][j][1] + bb.y, 0.f);
            float* h1 = sH + (r0 + g + 8) * PADH + c0;
            h1[0] = fmaxf(acc[i][j][2] + bb.x, 0.f);
            h1[1] = fmaxf(acc[i][j][3] + bb.y, 0.f);
        }
    }
    __syncthreads();

    // ---- Layer 2: K = 128, 4 chunks ----
    float acc2[2][4][4];
    #pragma unroll
    for (int i = 0; i < 2; i++)
        #pragma unroll
        for (int j = 0; j < 4; j++)
            #pragma unroll
            for (int r = 0; r < 4; r++) acc2[i][j][r] = 0.f;

    #pragma unroll 1
    for (int c = 0; c < 4; c++) {
        if (c + 1 < 4) {
            stageB(W2, c + 1, (c + 1) & 1);
            __pipeline_commit();
            __pipeline_wait_prior(1);
        } else {
            __pipeline_wait_prior(0);
        }
        __syncthreads();
        gemm_chunk(sH + c * KT, PADH, sB + (c & 1) * (KT * PADB), g, t, wm, wn, acc2);
        __syncthreads();
    }

    // residual + bias -> sY (overlaps sA/sB, both dead now)
    float* sY = sm;
    #pragma unroll
    for (int i = 0; i < 2; i++) {
        int r0 = wm * 32 + i * 16;
        #pragma unroll
        for (int j = 0; j < 4; j++) {
            int c0 = wn * 32 + j * 8 + 2 * t;
            float2 bb = *(const float2*)(b2 + c0);
            int ra = r0 + g, rb = ra + 8;
            int na = n0 + ra; if (na >= N) na = N - 1;
            int nb = n0 + rb; if (nb >= N) nb = N - 1;
            float2 xa = *(const float2*)(x + (size_t)na * HID + c0);
            float2 xb = *(const float2*)(x + (size_t)nb * HID + c0);
            float* y0 = sY + ra * PADH + c0;
            y0[0] = acc2[i][j][0] + bb.x + xa.x;
            y0[1] = acc2[i][j][1] + bb.y + xa.y;
            float* y1 = sY + rb * PADH + c0;
            y1[0] = acc2[i][j][2] + bb.x + xb.x;
            y1[1] = acc2[i][j][3] + bb.y + xb.y;
        }
    }
    __syncthreads();

    // LayerNorm stats: 4 threads per row
    {
        int r  = tid >> 2;
        int l4 = tid & 3;
        const float* row = sY + r * PADH;
        float s = 0.f;
        #pragma unroll
        for (int c = 0; c < 32; c++) s += row[l4 * 32 + c];
        s += __shfl_xor_sync(0xffffffffu, s, 2);
        s += __shfl_xor_sync(0xffffffffu, s, 1);
        float mu = s * (1.f / 128.f);
        float ss = 0.f;
        #pragma unroll
        for (int c = 0; c < 32; c++) {
            float d = row[l4 * 32 + c] - mu;
            ss = fmaf(d, d, ss);
        }
        ss += __shfl_xor_sync(0xffffffffu, ss, 2);
        ss += __shfl_xor_sync(0xffffffffu, ss, 1);
        float rs = rsqrtf(ss * (1.f / 128.f) + LN_EPS);
        if (l4 == 0) { s_mu[r] = mu; s_rs[r] = rs; }
    }
    __syncthreads();

    // write output
    {
        float4* out4 = (float4*)out;
        const float4* gm4 = (const float4*)gamma;
        const float4* bt4 = (const float4*)beta;
        for (int i = tid; i < BM * 32; i += 256) {
            int r = i >> 5, c4 = i & 31;
            if (n0 + r < N) {
                float4 v = ((const float4*)(sY + r * PADH))[c4];
                float mu = s_mu[r], rs = s_rs[r];
                float4 gv = gm4[c4], bv = bt4[c4];
                v.x = fmaf((v.x - mu) * rs, gv.x, bv.x);
                v.y = fmaf((v.y - mu) * rs, gv.y, bv.y);
                v.z = fmaf((v.z - mu) * rs, gv.z, bv.z);
                v.w = fmaf((v.w - mu) * rs, gv.w, bv.w);
                out4[(size_t)(n0 + r) * 32 + c4] = v;
            }
        }
    }
}

extern "C" void kernel_launch(void* const* d_in, const int* in_sizes, int n_in,
                              void* d_out, int out_size) {
    const float* x     = (const float*)d_in[0];
    const void*  eidx  = d_in[1];
    const float* eattr = (const float*)d_in[2];
    const float* mW1 = (const float*)d_in[3];
    const float* mb1 = (const float*)d_in[4];
    const float* mW2 = (const float*)d_in[5];
    const float* mb2 = (const float*)d_in[6];
    const float* uW1 = (const float*)d_in[7];
    const float* ub1 = (const float*)d_in[8];
    const float* uW2 = (const float*)d_in[9];
    const float* ub2 = (const float*)d_in[10];
    const float* gamma = (const float*)d_in[11];
    const float* beta  = (const float*)d_in[12];
    float* out = (float*)d_out;

    const int N = in_sizes[0] / HID;   // 50000
    const int E = in_sizes[2] / HID;   // 640000

    cudaFuncSetAttribute(edge_kernel, cudaFuncAttributeMaxDynamicSharedMemorySize, SMEM_BYTES);
    cudaFuncSetAttribute(node_kernel, cudaFuncAttributeMaxDynamicSharedMemorySize, SMEM_BYTES);

    detect_kernel<<<1, 1>>>((const int*)eidx);

    int zcnt = (N * HID) / 4;
    zero_kernel<<<(zcnt + 255) / 256, 256>>>(zcnt);

    edge_kernel<<<(E + BM - 1) / BM, 256, SMEM_BYTES>>>(x, eidx, eattr,
                                                        mW1, mb1, mW2, mb2, E);

    node_kernel<<<(N + BM - 1) / BM, 256, SMEM_BYTES>>>(x, uW1, ub1, uW2, ub2,
                                                        gamma, beta, out, N);
}

// round 4
// speedup vs baseline: 4.4851x; 1.3495x over previous
#include <cuda_runtime.h>
#include <cuda_pipeline.h>

#define HID 128
#define MAXN 50048
#define LN_EPS 1e-5f

#define BM 128
#define KT 32
#define SA_STR 20      // uint32 stride per A row (16 + 4 pad)
#define SB_STR 132     // uint32 stride per B k2-row (128 + 4 pad)
#define SH_STR 68      // uint32 stride per H row (64 + 4 pad)

// smem layout (uint32 units)
#define OFF_AH 0
#define OFF_AL (OFF_AH + 2*BM*SA_STR)   // 5120
#define OFF_BH (OFF_AL + 2*BM*SA_STR)   // 10240
#define OFF_BL (OFF_BH + 2*16*SB_STR)   // 14464
#define OFF_HH (OFF_BL + 2*16*SB_STR)   // 18688
#define OFF_HL (OFF_HH + BM*SH_STR)     // 27392
#define OFF_IX (OFF_HL + BM*SH_STR)     // 36096
#define SMEM_U (OFF_IX + 2*BM)          // 36352
#define SMEM_BYTES (SMEM_U * 4)         // 145408

__device__ __align__(256) float g_agg[(size_t)MAXN * HID];
__device__ int g_idx64;

// pre-packed bf16x2 (hi,lo) weights, k-pair packed: [k2][n]
__device__ unsigned w1h[192*128], w1l[192*128];
__device__ unsigned w2h[ 64*128], w2l[ 64*128];
__device__ unsigned u1h[128*128], u1l[128*128];
__device__ unsigned u2h[ 64*128], u2l[ 64*128];

__global__ void detect_kernel(const int* __restrict__ ei) {
    g_idx64 = (ei[1] == 0 && ei[3] == 0 && ei[5] == 0 && ei[7] == 0) ? 1 : 0;
}

__global__ void zero_kernel(int n4) {
    int i = blockIdx.x * blockDim.x + threadIdx.x;
    if (i < n4) ((float4*)g_agg)[i] = make_float4(0.f, 0.f, 0.f, 0.f);
}

// split pair of fp32 into packed bf16x2 hi + bf16x2 lo (lo16 = even-k, hi16 = odd-k)
__device__ __forceinline__ void split2(float a, float b, unsigned& h, unsigned& l) {
    unsigned hp;
    asm("cvt.rn.satfinite.bf16x2.f32 %0, %1, %2;" : "=r"(hp) : "f"(b), "f"(a));
    float fa = __uint_as_float(hp << 16);
    float fb = __uint_as_float(hp & 0xffff0000u);
    float la = a - fa, lb = b - fb;
    unsigned lp;
    asm("cvt.rn.satfinite.bf16x2.f32 %0, %1, %2;" : "=r"(lp) : "f"(lb), "f"(la));
    h = hp; l = lp;
}

__global__ void prepack_kernel(const float* __restrict__ mW1, const float* __restrict__ mW2,
                               const float* __restrict__ uW1, const float* __restrict__ uW2) {
    int i = blockIdx.x * 256 + threadIdx.x;
    const float* W; unsigned *H, *L; int off;
    if (i < 24576)      { W = mW1; H = w1h; L = w1l; off = i; }
    else if (i < 32768) { W = mW2; H = w2h; L = w2l; off = i - 24576; }
    else if (i < 49152) { W = uW1; H = u1h; L = u1l; off = i - 32768; }
    else if (i < 57344) { W = uW2; H = u2h; L = u2l; off = i - 49152; }
    else return;
    int k2 = off >> 7, n = off & 127;
    float v0 = W[(size_t)(2*k2) * 128 + n];
    float v1 = W[(size_t)(2*k2+1) * 128 + n];
    unsigned h, l; split2(v0, v1, h, l);
    H[off] = h; L[off] = l;
}

__device__ __forceinline__ void mma16(float d[4], const unsigned a[4], const unsigned b[2]) {
    asm volatile(
        "mma.sync.aligned.m16n8k16.row.col.f32.bf16.bf16.f32 "
        "{%0,%1,%2,%3}, {%4,%5,%6,%7}, {%8,%9}, {%0,%1,%2,%3};\n"
        : "+f"(d[0]), "+f"(d[1]), "+f"(d[2]), "+f"(d[3])
        : "r"(a[0]), "r"(a[1]), "r"(a[2]), "r"(a[3]), "r"(b[0]), "r"(b[1]));
}

__device__ __forceinline__ void red2(float* p, float a, float b) {
    asm volatile("red.global.add.v2.f32 [%0], {%1, %2};" :: "l"(p), "f"(a), "f"(b) : "memory");
}

// one KT=32 chunk: acc += A(128xKT) * B(KTx128), 3-term bf16 split
__device__ __forceinline__ void frag_compute(
    const unsigned* __restrict__ Ah, const unsigned* __restrict__ Al, int astr,
    const unsigned* __restrict__ Bh, const unsigned* __restrict__ Bl,
    int g, int t, int wm, int wn, float acc[4][4][4])
{
    #pragma unroll
    for (int ks = 0; ks < 2; ks++) {
        unsigned ah[4][4], al[4][4];
        #pragma unroll
        for (int i = 0; i < 4; i++) {
            const unsigned* p = Ah + (wm*64 + i*16 + g) * astr + ks*8 + t;
            ah[i][0] = p[0]; ah[i][1] = p[8*astr]; ah[i][2] = p[4]; ah[i][3] = p[8*astr + 4];
            const unsigned* q = Al + (wm*64 + i*16 + g) * astr + ks*8 + t;
            al[i][0] = q[0]; al[i][1] = q[8*astr]; al[i][2] = q[4]; al[i][3] = q[8*astr + 4];
        }
        unsigned bh[4][2], bl[4][2];
        #pragma unroll
        for (int j = 0; j < 4; j++) {
            const unsigned* p = Bh + (ks*8 + t) * SB_STR + wn*32 + j*8 + g;
            bh[j][0] = p[0]; bh[j][1] = p[4*SB_STR];
            const unsigned* q = Bl + (ks*8 + t) * SB_STR + wn*32 + j*8 + g;
            bl[j][0] = q[0]; bl[j][1] = q[4*SB_STR];
        }
        #pragma unroll
        for (int i = 0; i < 4; i++)
            #pragma unroll
            for (int j = 0; j < 4; j++) {
                mma16(acc[i][j], ah[i], bh[j]);
                mma16(acc[i][j], al[i], bh[j]);
                mma16(acc[i][j], ah[i], bl[j]);
            }
    }
}

__device__ __forceinline__ void stage_w(unsigned* dst, const unsigned* src, int c, int tid) {
    #pragma unroll
    for (int i = tid; i < 512; i += 256) {
        int r = i >> 5, q = (i & 31) * 4;
        __pipeline_memcpy_async(dst + r * SB_STR + q, src + (size_t)(c*16 + r) * 128 + q, 16);
    }
}

__device__ __forceinline__ void stA(unsigned* sAh, unsigned* sAl, int tid, const float4 v[4]) {
    int row = tid >> 1, k2 = (tid & 1) * 8;
    unsigned* dh = sAh + row * SA_STR + k2;
    unsigned* dl = sAl + row * SA_STR + k2;
    #pragma unroll
    for (int q = 0; q < 4; q++) {
        unsigned h0, l0, h1, l1;
        split2(v[q].x, v[q].y, h0, l0);
        split2(v[q].z, v[q].w, h1, l1);
        dh[2*q] = h0; dh[2*q+1] = h1;
        dl[2*q] = l0; dl[2*q+1] = l1;
    }
}

__device__ __forceinline__ void zero_acc(float acc[4][4][4]) {
    #pragma unroll
    for (int i = 0; i < 4; i++)
        #pragma unroll
        for (int j = 0; j < 4; j++)
            #pragma unroll
            for (int r = 0; r < 4; r++) acc[i][j][r] = 0.f;
}

// write layer-1 acc (+bias, relu) as split bf16 pairs into sH
__device__ __forceinline__ void write_H(unsigned* sHh, unsigned* sHl, const float* b1,
                                        int g, int t, int wm, int wn, float acc[4][4][4]) {
    #pragma unroll
    for (int i = 0; i < 4; i++) {
        int r = wm*64 + i*16 + g;
        #pragma unroll
        for (int j = 0; j < 4; j++) {
            int c0 = wn*32 + j*8 + 2*t;
            float2 bb = *(const float2*)(b1 + c0);
            int ci = wn*16 + j*4 + t;
            float a0 = fmaxf(acc[i][j][0] + bb.x, 0.f);
            float a1 = fmaxf(acc[i][j][1] + bb.y, 0.f);
            float a2 = fmaxf(acc[i][j][2] + bb.x, 0.f);
            float a3 = fmaxf(acc[i][j][3] + bb.y, 0.f);
            unsigned h, l;
            split2(a0, a1, h, l);
            sHh[r * SH_STR + ci] = h; sHl[r * SH_STR + ci] = l;
            split2(a2, a3, h, l);
            sHh[(r+8) * SH_STR + ci] = h; sHl[(r+8) * SH_STR + ci] = l;
        }
    }
}

// ---------------------------------------------------------------------------
// Edge kernel: 128 edges/block
// ---------------------------------------------------------------------------
__global__ __launch_bounds__(256)
void edge_kernel(const float* __restrict__ x, const void* __restrict__ eidx,
                 const float* __restrict__ eattr,
                 const float* __restrict__ b1, const float* __restrict__ b2, int E)
{
    extern __shared__ unsigned smu[];
    unsigned* sAhB = smu + OFF_AH;
    unsigned* sAlB = smu + OFF_AL;
    unsigned* sBhB = smu + OFF_BH;
    unsigned* sBlB = smu + OFF_BL;
    unsigned* sHh  = smu + OFF_HH;
    unsigned* sHl  = smu + OFF_HL;
    int* s_src = (int*)(smu + OFF_IX);
    int* s_dst = s_src + BM;

    const int tid  = threadIdx.x;
    const int e0   = blockIdx.x * BM;
    const int lane = tid & 31;
    const int wid  = tid >> 5;
    const int wm   = wid >> 2;
    const int wn   = wid & 3;
    const int g    = lane >> 2;
    const int t    = lane & 3;

    if (tid < BM) {
        int e = e0 + tid;
        int s, d;
        if (g_idx64) {
            s = (int)((const long long*)eidx)[e];
            d = (int)((const long long*)eidx)[(size_t)E + e];
        } else {
            s = ((const int*)eidx)[e];
            d = ((const int*)eidx)[(size_t)E + e];
        }
        s_src[tid] = s; s_dst[tid] = d;
    }
    __syncthreads();

    const int arow = tid >> 1, akh = (tid & 1) * 16;
    auto ldA = [&](int c, float4 v[4]) {
        int k = c * KT + akh;
        const float* src;
        if (k < 128)       src = x + (size_t)s_src[arow] * HID + k;
        else if (k < 256)  src = x + (size_t)s_dst[arow] * HID + (k - 128);
        else               src = eattr + (size_t)(e0 + arow) * HID + (k - 256);
        const float4* s4 = (const float4*)src;
        v[0] = s4[0]; v[1] = s4[1]; v[2] = s4[2]; v[3] = s4[3];
    };

    float acc[4][4][4];
    zero_acc(acc);

    // ---- Layer 1: K=384, 12 chunks ----
    float4 av[4];
    ldA(0, av);
    stage_w(sBhB, w1h, 0, tid); stage_w(sBlB, w1l, 0, tid); __pipeline_commit();
    stA(sAhB, sAlB, tid, av);
    ldA(1, av);
    __pipeline_wait_prior(0);
    __syncthreads();
    stage_w(sBhB + 16*SB_STR, w1h, 1, tid); stage_w(sBlB + 16*SB_STR, w1l, 1, tid);
    __pipeline_commit();

    int b = 0;
    #pragma unroll 1
    for (int c = 0; c < 12; c++) {
        frag_compute(sAhB + b*(BM*SA_STR), sAlB + b*(BM*SA_STR), SA_STR,
                     sBhB + b*(16*SB_STR), sBlB + b*(16*SB_STR),
                     g, t, wm, wn, acc);
        if (c == 11) break;
        stA(sAhB + (b^1)*(BM*SA_STR), sAlB + (b^1)*(BM*SA_STR), tid, av);
        if (c + 2 < 12) ldA(c + 2, av);
        __pipeline_wait_prior(0);
        __syncthreads();
        if (c + 2 < 12) {
            stage_w(sBhB + b*(16*SB_STR), w1h, c + 2, tid);
            stage_w(sBlB + b*(16*SB_STR), w1l, c + 2, tid);
            __pipeline_commit();
        }
        b ^= 1;
    }

    write_H(sHh, sHl, b1, g, t, wm, wn, acc);
    __syncthreads();

    // ---- Layer 2: K=128, 4 chunks, A = sH ----
    zero_acc(acc);
    stage_w(sBhB, w2h, 0, tid); stage_w(sBlB, w2l, 0, tid); __pipeline_commit();
    __pipeline_wait_prior(0);
    __syncthreads();
    stage_w(sBhB + 16*SB_STR, w2h, 1, tid); stage_w(sBlB + 16*SB_STR, w2l, 1, tid);
    __pipeline_commit();

    b = 0;
    #pragma unroll 1
    for (int c = 0; c < 4; c++) {
        frag_compute(sHh + c*16, sHl + c*16, SH_STR,
                     sBhB + b*(16*SB_STR), sBlB + b*(16*SB_STR),
                     g, t, wm, wn, acc);
        if (c == 3) break;
        __pipeline_wait_prior(0);
        __syncthreads();
        if (c + 2 < 4) {
            stage_w(sBhB + b*(16*SB_STR), w2h, c + 2, tid);
            stage_w(sBlB + b*(16*SB_STR), w2l, c + 2, tid);
            __pipeline_commit();
        }
        b ^= 1;
    }

    // bias + scatter-add
    #pragma unroll
    for (int i = 0; i < 4; i++) {
        int ra = wm*64 + i*16 + g;
        #pragma unroll
        for (int j = 0; j < 4; j++) {
            int c0 = wn*32 + j*8 + 2*t;
            float2 bb = *(const float2*)(b2 + c0);
            red2(g_agg + (size_t)s_dst[ra] * HID + c0,
                 acc[i][j][0] + bb.x, acc[i][j][1] + bb.y);
            red2(g_agg + (size_t)s_dst[ra+8] * HID + c0,
                 acc[i][j][2] + bb.x, acc[i][j][3] + bb.y);
        }
    }
}

// ---------------------------------------------------------------------------
// Node kernel: 128 nodes/block
// ---------------------------------------------------------------------------
__global__ __launch_bounds__(256)
void node_kernel(const float* __restrict__ x,
                 const float* __restrict__ b1, const float* __restrict__ b2,
                 const float* __restrict__ gamma, const float* __restrict__ beta,
                 float* __restrict__ out, int N)
{
    extern __shared__ unsigned smu[];
    unsigned* sAhB = smu + OFF_AH;
    unsigned* sAlB = smu + OFF_AL;
    unsigned* sBhB = smu + OFF_BH;
    unsigned* sBlB = smu + OFF_BL;
    unsigned* sHh  = smu + OFF_HH;
    unsigned* sHl  = smu + OFF_HL;
    float* s_mu = (float*)(smu + OFF_IX);
    float* s_rs = s_mu + BM;

    const int tid  = threadIdx.x;
    const int n0   = blockIdx.x * BM;
    const int lane = tid & 31;
    const int wid  = tid >> 5;
    const int wm   = wid >> 2;
    const int wn   = wid & 3;
    const int g    = lane >> 2;
    const int t    = lane & 3;

    const int arow = tid >> 1, akh = (tid & 1) * 16;
    int an = n0 + arow; if (an >= N) an = N - 1;
    auto ldA = [&](int c, float4 v[4]) {
        int k = c * KT + akh;
        const float* src = (k < 128) ? (x + (size_t)an * HID + k)
                                     : (g_agg + (size_t)an * HID + (k - 128));
        const float4* s4 = (const float4*)src;
        v[0] = s4[0]; v[1] = s4[1]; v[2] = s4[2]; v[3] = s4[3];
    };

    float acc[4][4][4];
    zero_acc(acc);

    // ---- Layer 1: K=256, 8 chunks ----
    float4 av[4];
    ldA(0, av);
    stage_w(sBhB, u1h, 0, tid); stage_w(sBlB, u1l, 0, tid); __pipeline_commit();
    stA(sAhB, sAlB, tid, av);
    ldA(1, av);
    __pipeline_wait_prior(0);
    __syncthreads();
    stage_w(sBhB + 16*SB_STR, u1h, 1, tid); stage_w(sBlB + 16*SB_STR, u1l, 1, tid);
    __pipeline_commit();

    int b = 0;
    #pragma unroll 1
    for (int c = 0; c < 8; c++) {
        frag_compute(sAhB + b*(BM*SA_STR), sAlB + b*(BM*SA_STR), SA_STR,
                     sBhB + b*(16*SB_STR), sBlB + b*(16*SB_STR),
                     g, t, wm, wn, acc);
        if (c == 7) break;
        stA(sAhB + (b^1)*(BM*SA_STR), sAlB + (b^1)*(BM*SA_STR), tid, av);
        if (c + 2 < 8) ldA(c + 2, av);
        __pipeline_wait_prior(0);
        __syncthreads();
        if (c + 2 < 8) {
            stage_w(sBhB + b*(16*SB_STR), u1h, c + 2, tid);
            stage_w(sBlB + b*(16*SB_STR), u1l, c + 2, tid);
            __pipeline_commit();
        }
        b ^= 1;
    }

    write_H(sHh, sHl, b1, g, t, wm, wn, acc);
    __syncthreads();

    // ---- Layer 2: K=128, 4 chunks ----
    zero_acc(acc);
    stage_w(sBhB, u2h, 0, tid); stage_w(sBlB, u2l, 0, tid); __pipeline_commit();
    __pipeline_wait_prior(0);
    __syncthreads();
    stage_w(sBhB + 16*SB_STR, u2h, 1, tid); stage_w(sBlB + 16*SB_STR, u2l, 1, tid);
    __pipeline_commit();

    b = 0;
    #pragma unroll 1
    for (int c = 0; c < 4; c++) {
        frag_compute(sHh + c*16, sHl + c*16, SH_STR,
                     sBhB + b*(16*SB_STR), sBlB + b*(16*SB_STR),
                     g, t, wm, wn, acc);
        if (c == 3) break;
        __pipeline_wait_prior(0);
        __syncthreads();
        if (c + 2 < 4) {
            stage_w(sBhB + b*(16*SB_STR), u2h, c + 2, tid);
            stage_w(sBlB + b*(16*SB_STR), u2l, c + 2, tid);
            __pipeline_commit();
        }
        b ^= 1;
    }

    __syncthreads();   // sH reads done; reuse region as fp32 sY
    float* sY = (float*)sHh;   // [128][132] floats

    #pragma unroll
    for (int i = 0; i < 4; i++) {
        int ra = wm*64 + i*16 + g;
        #pragma unroll
        for (int j = 0; j < 4; j++) {
            int c0 = wn*32 + j*8 + 2*t;
            float2 bb = *(const float2*)(b2 + c0);
            int na = n0 + ra;     if (na >= N) na = N - 1;
            int nb = n0 + ra + 8; if (nb >= N) nb = N - 1;
            float2 xa = *(const float2*)(x + (size_t)na * HID + c0);
            float2 xb = *(const float2*)(x + (size_t)nb * HID + c0);
            sY[ra * 132 + c0]         = acc[i][j][0] + bb.x + xa.x;
            sY[ra * 132 + c0 + 1]     = acc[i][j][1] + bb.y + xa.y;
            sY[(ra+8) * 132 + c0]     = acc[i][j][2] + bb.x + xb.x;
            sY[(ra+8) * 132 + c0 + 1] = acc[i][j][3] + bb.y + xb.y;
        }
    }
    __syncthreads();

    // LN stats: 2 threads per row
    {
        int r = tid >> 1, hf = tid & 1;
        const float* row = sY + r * 132 + hf * 64;
        float s = 0.f;
        #pragma unroll
        for (int c = 0; c < 64; c++) s += row[c];
        s += __shfl_xor_sync(0xffffffffu, s, 1);
        float mu = s * (1.f / 128.f);
        float ss = 0.f;
        #pragma unroll
        for (int c = 0; c < 64; c++) { float d = row[c] - mu; ss = fmaf(d, d, ss); }
        ss += __shfl_xor_sync(0xffffffffu, ss, 1);
        float rs = rsqrtf(ss * (1.f / 128.f) + LN_EPS);
        if (hf == 0) { s_mu[r] = mu; s_rs[r] = rs; }
    }
    __syncthreads();

    {
        float4* out4 = (float4*)out;
        const float4* gm4 = (const float4*)gamma;
        const float4* bt4 = (const float4*)beta;
        for (int i = tid; i < BM * 32; i += 256) {
            int r = i >> 5, c4 = i & 31;
            if (n0 + r < N) {
                float4 v = ((const float4*)(sY + r * 132))[c4];
                float mu = s_mu[r], rs = s_rs[r];
                float4 gv = gm4[c4], bv = bt4[c4];
                v.x = fmaf((v.x - mu) * rs, gv.x, bv.x);
                v.y = fmaf((v.y - mu) * rs, gv.y, bv.y);
                v.z = fmaf((v.z - mu) * rs, gv.z, bv.z);
                v.w = fmaf((v.w - mu) * rs, gv.w, bv.w);
                out4[(size_t)(n0 + r) * 32 + c4] = v;
            }
        }
    }
}

extern "C" void kernel_launch(void* const* d_in, const int* in_sizes, int n_in,
                              void* d_out, int out_size) {
    const float* x     = (const float*)d_in[0];
    const void*  eidx  = d_in[1];
    const float* eattr = (const float*)d_in[2];
    const float* mW1 = (const float*)d_in[3];
    const float* mb1 = (const float*)d_in[4];
    const float* mW2 = (const float*)d_in[5];
    const float* mb2 = (const float*)d_in[6];
    const float* uW1 = (const float*)d_in[7];
    const float* ub1 = (const float*)d_in[8];
    const float* uW2 = (const float*)d_in[9];
    const float* ub2 = (const float*)d_in[10];
    const float* gamma = (const float*)d_in[11];
    const float* beta  = (const float*)d_in[12];
    float* out = (float*)d_out;

    const int N = in_sizes[0] / HID;   // 50000
    const int E = in_sizes[2] / HID;   // 640000

    cudaFuncSetAttribute(edge_kernel, cudaFuncAttributeMaxDynamicSharedMemorySize, SMEM_BYTES);
    cudaFuncSetAttribute(node_kernel, cudaFuncAttributeMaxDynamicSharedMemorySize, SMEM_BYTES);

    detect_kernel<<<1, 1>>>((const int*)eidx);
    prepack_kernel<<<224, 256>>>(mW1, mW2, uW1, uW2);

    int zcnt = (N * HID) / 4;
    zero_kernel<<<(zcnt + 255) / 256, 256>>>(zcnt);

    edge_kernel<<<(E + BM - 1) / BM, 256, SMEM_BYTES>>>(x, eidx, eattr, mb1, mb2, E);

    node_kernel<<<(N + BM - 1) / BM, 256, SMEM_BYTES>>>(x, ub1, ub2, gamma, beta, out, N);
}

// round 7
// speedup vs baseline: 4.6641x; 1.0399x over previous
#include <cuda_runtime.h>
#include <cuda_pipeline.h>

#define HID 128
#define MAXN 50048
#define LN_EPS 1e-5f

#define BM 64
#define KT 32
#define SA_STR 20      // uint32 stride per A row (16 + 4 pad)
#define SB_STR 132     // uint32 stride per B k2-row (128 + 4 pad)
#define SH_STR 68      // uint32 stride per H row (64 + 4 pad)

// smem layout (uint32 units)
#define OFF_AH 0
#define OFF_AL (OFF_AH + 2*BM*SA_STR)   // 2560
#define OFF_BH (OFF_AL + 2*BM*SA_STR)   // 5120
#define OFF_BL (OFF_BH + 2*16*SB_STR)   // 9344
#define OFF_HH (OFF_BL + 2*16*SB_STR)   // 13568
#define OFF_HL (OFF_HH + BM*SH_STR)     // 17920
#define OFF_IX (OFF_HL + BM*SH_STR)     // 22272
#define SMEM_U (OFF_IX + 2*BM)          // 22400
#define SMEM_BYTES (SMEM_U * 4)         // 89600  -> 2 CTAs/SM

__device__ __align__(256) float g_agg[(size_t)MAXN * HID];
__device__ int g_idx64;

// pre-packed bf16x2 (hi,lo) weights, k-pair packed: [k2][n]
__device__ unsigned w1h[192*128], w1l[192*128];
__device__ unsigned w2h[ 64*128], w2l[ 64*128];
__device__ unsigned u1h[128*128], u1l[128*128];
__device__ unsigned u2h[ 64*128], u2l[ 64*128];

__global__ void detect_kernel(const int* __restrict__ ei) {
    g_idx64 = (ei[1] == 0 && ei[3] == 0 && ei[5] == 0 && ei[7] == 0) ? 1 : 0;
}

__global__ void zero_kernel(int n4) {
    int i = blockIdx.x * blockDim.x + threadIdx.x;
    if (i < n4) ((float4*)g_agg)[i] = make_float4(0.f, 0.f, 0.f, 0.f);
}

// split pair of fp32 into packed bf16x2 hi + bf16x2 lo (lo16 = even-k, hi16 = odd-k)
__device__ __forceinline__ void split2(float a, float b, unsigned& h, unsigned& l) {
    unsigned hp;
    asm("cvt.rn.satfinite.bf16x2.f32 %0, %1, %2;" : "=r"(hp) : "f"(b), "f"(a));
    float fa = __uint_as_float(hp << 16);
    float fb = __uint_as_float(hp & 0xffff0000u);
    float la = a - fa, lb = b - fb;
    unsigned lp;
    asm("cvt.rn.satfinite.bf16x2.f32 %0, %1, %2;" : "=r"(lp) : "f"(lb), "f"(la));
    h = hp; l = lp;
}

__global__ void prepack_kernel(const float* __restrict__ mW1, const float* __restrict__ mW2,
                               const float* __restrict__ uW1, const float* __restrict__ uW2) {
    int i = blockIdx.x * 256 + threadIdx.x;
    const float* W; unsigned *H, *L; int off;
    if (i < 24576)      { W = mW1; H = w1h; L = w1l; off = i; }
    else if (i < 32768) { W = mW2; H = w2h; L = w2l; off = i - 24576; }
    else if (i < 49152) { W = uW1; H = u1h; L = u1l; off = i - 32768; }
    else if (i < 57344) { W = uW2; H = u2h; L = u2l; off = i - 49152; }
    else return;
    int k2 = off >> 7, n = off & 127;
    float v0 = W[(size_t)(2*k2) * 128 + n];
    float v1 = W[(size_t)(2*k2+1) * 128 + n];
    unsigned h, l; split2(v0, v1, h, l);
    H[off] = h; L[off] = l;
}

__device__ __forceinline__ void mma16(float d[4], const unsigned a[4], const unsigned b[2]) {
    asm volatile(
        "mma.sync.aligned.m16n8k16.row.col.f32.bf16.bf16.f32 "
        "{%0,%1,%2,%3}, {%4,%5,%6,%7}, {%8,%9}, {%0,%1,%2,%3};\n"
        : "+f"(d[0]), "+f"(d[1]), "+f"(d[2]), "+f"(d[3])
        : "r"(a[0]), "r"(a[1]), "r"(a[2]), "r"(a[3]), "r"(b[0]), "r"(b[1]));
}

__device__ __forceinline__ void red2(float* p, float a, float b) {
    asm volatile("red.global.add.v2.f32 [%0], {%1, %2};" :: "l"(p), "f"(a), "f"(b) : "memory");
}

// one KT=32 chunk: acc += A(64xKT) * B(KTx128), 3-term bf16 split
__device__ __forceinline__ void frag_compute(
    const unsigned* __restrict__ Ah, const unsigned* __restrict__ Al, int astr,
    const unsigned* __restrict__ Bh, const unsigned* __restrict__ Bl,
    int g, int t, int wm, int wn, float acc[2][4][4])
{
    #pragma unroll
    for (int ks = 0; ks < 2; ks++) {
        unsigned ah[2][4], al[2][4];
        #pragma unroll
        for (int i = 0; i < 2; i++) {
            const unsigned* p = Ah + (wm*32 + i*16 + g) * astr + ks*8 + t;
            ah[i][0] = p[0]; ah[i][1] = p[8*astr]; ah[i][2] = p[4]; ah[i][3] = p[8*astr + 4];
            const unsigned* q = Al + (wm*32 + i*16 + g) * astr + ks*8 + t;
            al[i][0] = q[0]; al[i][1] = q[8*astr]; al[i][2] = q[4]; al[i][3] = q[8*astr + 4];
        }
        unsigned bh[4][2], bl[4][2];
        #pragma unroll
        for (int j = 0; j < 4; j++) {
            const unsigned* p = Bh + (ks*8 + t) * SB_STR + wn*32 + j*8 + g;
            bh[j][0] = p[0]; bh[j][1] = p[4*SB_STR];
            const unsigned* q = Bl + (ks*8 + t) * SB_STR + wn*32 + j*8 + g;
            bl[j][0] = q[0]; bl[j][1] = q[4*SB_STR];
        }
        #pragma unroll
        for (int i = 0; i < 2; i++)
            #pragma unroll
            for (int j = 0; j < 4; j++) {
                mma16(acc[i][j], ah[i], bh[j]);
                mma16(acc[i][j], al[i], bh[j]);
                mma16(acc[i][j], ah[i], bl[j]);
            }
    }
}

__device__ __forceinline__ void stage_w(unsigned* dst, const unsigned* src, int c, int tid) {
    #pragma unroll
    for (int i = tid; i < 512; i += 256) {
        int r = i >> 5, q = (i & 31) * 4;
        __pipeline_memcpy_async(dst + r * SB_STR + q, src + (size_t)(c*16 + r) * 128 + q, 16);
    }
}

// 256 threads stage 64 rows x 32 k: row = tid>>2, quad = tid&3 (8 fp32 each)
__device__ __forceinline__ void stA(unsigned* sAh, unsigned* sAl, int tid, const float4 v[2]) {
    int row = tid >> 2, quad = tid & 3;
    unsigned* dh = sAh + row * SA_STR + quad * 4;
    unsigned* dl = sAl + row * SA_STR + quad * 4;
    #pragma unroll
    for (int q = 0; q < 2; q++) {
        unsigned h0, l0, h1, l1;
        split2(v[q].x, v[q].y, h0, l0);
        split2(v[q].z, v[q].w, h1, l1);
        dh[2*q] = h0; dh[2*q+1] = h1;
        dl[2*q] = l0; dl[2*q+1] = l1;
    }
}

__device__ __forceinline__ void zero_acc(float acc[2][4][4]) {
    #pragma unroll
    for (int i = 0; i < 2; i++)
        #pragma unroll
        for (int j = 0; j < 4; j++)
            #pragma unroll
            for (int r = 0; r < 4; r++) acc[i][j][r] = 0.f;
}

// write layer-1 acc (+bias, relu) as split bf16 pairs into sH
__device__ __forceinline__ void write_H(unsigned* sHh, unsigned* sHl, const float* b1,
                                        int g, int t, int wm, int wn, float acc[2][4][4]) {
    #pragma unroll
    for (int i = 0; i < 2; i++) {
        int r = wm*32 + i*16 + g;
        #pragma unroll
        for (int j = 0; j < 4; j++) {
            int c0 = wn*32 + j*8 + 2*t;
            float2 bb = *(const float2*)(b1 + c0);
            int ci = wn*16 + j*4 + t;
            float a0 = fmaxf(acc[i][j][0] + bb.x, 0.f);
            float a1 = fmaxf(acc[i][j][1] + bb.y, 0.f);
            float a2 = fmaxf(acc[i][j][2] + bb.x, 0.f);
            float a3 = fmaxf(acc[i][j][3] + bb.y, 0.f);
            unsigned h, l;
            split2(a0, a1, h, l);
            sHh[r * SH_STR + ci] = h; sHl[r * SH_STR + ci] = l;
            split2(a2, a3, h, l);
            sHh[(r+8) * SH_STR + ci] = h; sHl[(r+8) * SH_STR + ci] = l;
        }
    }
}

// ---------------------------------------------------------------------------
// Edge kernel: 64 edges/block, 2 CTAs/SM
// ---------------------------------------------------------------------------
__global__ __launch_bounds__(256, 2)
void edge_kernel(const float* __restrict__ x, const void* __restrict__ eidx,
                 const float* __restrict__ eattr,
                 const float* __restrict__ b1, const float* __restrict__ b2, int E)
{
    extern __shared__ unsigned smu[];
    unsigned* sAhB = smu + OFF_AH;
    unsigned* sAlB = smu + OFF_AL;
    unsigned* sBhB = smu + OFF_BH;
    unsigned* sBlB = smu + OFF_BL;
    unsigned* sHh  = smu + OFF_HH;
    unsigned* sHl  = smu + OFF_HL;
    int* s_src = (int*)(smu + OFF_IX);
    int* s_dst = s_src + BM;

    const int tid  = threadIdx.x;
    const int e0   = blockIdx.x * BM;
    const int lane = tid & 31;
    const int wid  = tid >> 5;
    const int wm   = wid >> 2;
    const int wn   = wid & 3;
    const int g    = lane >> 2;
    const int t    = lane & 3;

    if (tid < BM) {
        int e = e0 + tid;
        int s, d;
        if (g_idx64) {
            s = (int)((const long long*)eidx)[e];
            d = (int)((const long long*)eidx)[(size_t)E + e];
        } else {
            s = ((const int*)eidx)[e];
            d = ((const int*)eidx)[(size_t)E + e];
        }
        s_src[tid] = s; s_dst[tid] = d;
    }
    __syncthreads();

    const int arow = tid >> 2, akh = (tid & 3) * 8;
    auto ldA = [&](int c, float4 v[2]) {
        int k = c * KT + akh;
        const float* src;
        if (k < 128)       src = x + (size_t)s_src[arow] * HID + k;
        else if (k < 256)  src = x + (size_t)s_dst[arow] * HID + (k - 128);
        else               src = eattr + (size_t)(e0 + arow) * HID + (k - 256);
        const float4* s4 = (const float4*)src;
        v[0] = s4[0]; v[1] = s4[1];
    };

    float acc[2][4][4];
    zero_acc(acc);

    // ---- Layer 1: K=384, 12 chunks ----
    float4 av[2];
    ldA(0, av);
    stage_w(sBhB, w1h, 0, tid); stage_w(sBlB, w1l, 0, tid); __pipeline_commit();
    stA(sAhB, sAlB, tid, av);
    ldA(1, av);
    __pipeline_wait_prior(0);
    __syncthreads();
    stage_w(sBhB + 16*SB_STR, w1h, 1, tid); stage_w(sBlB + 16*SB_STR, w1l, 1, tid);
    __pipeline_commit();

    int b = 0;
    #pragma unroll 1
    for (int c = 0; c < 12; c++) {
        frag_compute(sAhB + b*(BM*SA_STR), sAlB + b*(BM*SA_STR), SA_STR,
                     sBhB + b*(16*SB_STR), sBlB + b*(16*SB_STR),
                     g, t, wm, wn, acc);
        if (c == 11) break;
        stA(sAhB + (b^1)*(BM*SA_STR), sAlB + (b^1)*(BM*SA_STR), tid, av);
        if (c + 2 < 12) ldA(c + 2, av);
        __pipeline_wait_prior(0);
        __syncthreads();
        if (c + 2 < 12) {
            stage_w(sBhB + b*(16*SB_STR), w1h, c + 2, tid);
            stage_w(sBlB + b*(16*SB_STR), w1l, c + 2, tid);
            __pipeline_commit();
        }
        b ^= 1;
    }

    write_H(sHh, sHl, b1, g, t, wm, wn, acc);
    __syncthreads();

    // ---- Layer 2: K=128, 4 chunks, A = sH ----
    zero_acc(acc);
    stage_w(sBhB, w2h, 0, tid); stage_w(sBlB, w2l, 0, tid); __pipeline_commit();
    __pipeline_wait_prior(0);
    __syncthreads();
    stage_w(sBhB + 16*SB_STR, w2h, 1, tid); stage_w(sBlB + 16*SB_STR, w2l, 1, tid);
    __pipeline_commit();

    b = 0;
    #pragma unroll 1
    for (int c = 0; c < 4; c++) {
        frag_compute(sHh + c*16, sHl + c*16, SH_STR,
                     sBhB + b*(16*SB_STR), sBlB + b*(16*SB_STR),
                     g, t, wm, wn, acc);
        if (c == 3) break;
        __pipeline_wait_prior(0);
        __syncthreads();
        if (c + 2 < 4) {
            stage_w(sBhB + b*(16*SB_STR), w2h, c + 2, tid);
            stage_w(sBlB + b*(16*SB_STR), w2l, c + 2, tid);
            __pipeline_commit();
        }
        b ^= 1;
    }

    // bias + scatter-add
    #pragma unroll
    for (int i = 0; i < 2; i++) {
        int ra = wm*32 + i*16 + g;
        #pragma unroll
        for (int j = 0; j < 4; j++) {
            int c0 = wn*32 + j*8 + 2*t;
            float2 bb = *(const float2*)(b2 + c0);
            red2(g_agg + (size_t)s_dst[ra] * HID + c0,
                 acc[i][j][0] + bb.x, acc[i][j][1] + bb.y);
            red2(g_agg + (size_t)s_dst[ra+8] * HID + c0,
                 acc[i][j][2] + bb.x, acc[i][j][3] + bb.y);
        }
    }
}

// ---------------------------------------------------------------------------
// Node kernel: 64 nodes/block, 2 CTAs/SM
// ---------------------------------------------------------------------------
__global__ __launch_bounds__(256, 2)
void node_kernel(const float* __restrict__ x,
                 const float* __restrict__ b1, const float* __restrict__ b2,
                 const float* __restrict__ gamma, const float* __restrict__ beta,
                 float* __restrict__ out, int N)
{
    extern __shared__ unsigned smu[];
    unsigned* sAhB = smu + OFF_AH;
    unsigned* sAlB = smu + OFF_AL;
    unsigned* sBhB = smu + OFF_BH;
    unsigned* sBlB = smu + OFF_BL;
    unsigned* sHh  = smu + OFF_HH;
    unsigned* sHl  = smu + OFF_HL;
    float* s_mu = (float*)(smu + OFF_IX);
    float* s_rs = s_mu + BM;

    const int tid  = threadIdx.x;
    const int n0   = blockIdx.x * BM;
    const int lane = tid & 31;
    const int wid  = tid >> 5;
    const int wm   = wid >> 2;
    const int wn   = wid & 3;
    const int g    = lane >> 2;
    const int t    = lane & 3;

    const int arow = tid >> 2, akh = (tid & 3) * 8;
    int an = n0 + arow; if (an >= N) an = N - 1;
    auto ldA = [&](int c, float4 v[2]) {
        int k = c * KT + akh;
        const float* src = (k < 128) ? (x + (size_t)an * HID + k)
                                     : (g_agg + (size_t)an * HID + (k - 128));
        const float4* s4 = (const float4*)src;
        v[0] = s4[0]; v[1] = s4[1];
    };

    float acc[2][4][4];
    zero_acc(acc);

    // ---- Layer 1: K=256, 8 chunks ----
    float4 av[2];
    ldA(0, av);
    stage_w(sBhB, u1h, 0, tid); stage_w(sBlB, u1l, 0, tid); __pipeline_commit();
    stA(sAhB, sAlB, tid, av);
    ldA(1, av);
    __pipeline_wait_prior(0);
    __syncthreads();
    stage_w(sBhB + 16*SB_STR, u1h, 1, tid); stage_w(sBlB + 16*SB_STR, u1l, 1, tid);
    __pipeline_commit();

    int b = 0;
    #pragma unroll 1
    for (int c = 0; c < 8; c++) {
        frag_compute(sAhB + b*(BM*SA_STR), sAlB + b*(BM*SA_STR), SA_STR,
                     sBhB + b*(16*SB_STR), sBlB + b*(16*SB_STR),
                     g, t, wm, wn, acc);
        if (c == 7) break;
        stA(sAhB + (b^1)*(BM*SA_STR), sAlB + (b^1)*(BM*SA_STR), tid, av);
        if (c + 2 < 8) ldA(c + 2, av);
        __pipeline_wait_prior(0);
        __syncthreads();
        if (c + 2 < 8) {
            stage_w(sBhB + b*(16*SB_STR), u1h, c + 2, tid);
            stage_w(sBlB + b*(16*SB_STR), u1l, c + 2, tid);
            __pipeline_commit();
        }
        b ^= 1;
    }

    write_H(sHh, sHl, b1, g, t, wm, wn, acc);
    __syncthreads();

    // ---- Layer 2: K=128, 4 chunks ----
    zero_acc(acc);
    stage_w(sBhB, u2h, 0, tid); stage_w(sBlB, u2l, 0, tid); __pipeline_commit();
    __pipeline_wait_prior(0);
    __syncthreads();
    stage_w(sBhB + 16*SB_STR, u2h, 1, tid); stage_w(sBlB + 16*SB_STR, u2l, 1, tid);
    __pipeline_commit();

    b = 0;
    #pragma unroll 1
    for (int c = 0; c < 4; c++) {
        frag_compute(sHh + c*16, sHl + c*16, SH_STR,
                     sBhB + b*(16*SB_STR), sBlB + b*(16*SB_STR),
                     g, t, wm, wn, acc);
        if (c == 3) break;
        __pipeline_wait_prior(0);
        __syncthreads();
        if (c + 2 < 4) {
            stage_w(sBhB + b*(16*SB_STR), u2h, c + 2, tid);
            stage_w(sBlB + b*(16*SB_STR), u2l, c + 2, tid);
            __pipeline_commit();
        }
        b ^= 1;
    }

    __syncthreads();   // sH reads done; reuse region as fp32 sY
    float* sY = (float*)sHh;   // [64][132] floats (fits in HH+HL region)

    #pragma unroll
    for (int i = 0; i < 2; i++) {
        int ra = wm*32 + i*16 + g;
        #pragma unroll
        for (int j = 0; j < 4; j++) {
            int c0 = wn*32 + j*8 + 2*t;
            float2 bb = *(const float2*)(b2 + c0);
            int na = n0 + ra;     if (na >= N) na = N - 1;
            int nb = n0 + ra + 8; if (nb >= N) nb = N - 1;
            float2 xa = *(const float2*)(x + (size_t)na * HID + c0);
            float2 xb = *(const float2*)(x + (size_t)nb * HID + c0);
            sY[ra * 132 + c0]         = acc[i][j][0] + bb.x + xa.x;
            sY[ra * 132 + c0 + 1]     = acc[i][j][1] + bb.y + xa.y;
            sY[(ra+8) * 132 + c0]     = acc[i][j][2] + bb.x + xb.x;
            sY[(ra+8) * 132 + c0 + 1] = acc[i][j][3] + bb.y + xb.y;
        }
    }
    __syncthreads();

    // LN stats: 4 threads per row
    {
        int r = tid >> 2, l4 = tid & 3;
        const float* row = sY + r * 132 + l4 * 32;
        float s = 0.f;
        #pragma unroll
        for (int c = 0; c < 32; c++) s += row[c];
        s += __shfl_xor_sync(0xffffffffu, s, 2);
        s += __shfl_xor_sync(0xffffffffu, s, 1);
        float mu = s * (1.f / 128.f);
        float ss = 0.f;
        #pragma unroll
        for (int c = 0; c < 32; c++) { float d = row[c] - mu; ss = fmaf(d, d, ss); }
        ss += __shfl_xor_sync(0xffffffffu, ss, 2);
        ss += __shfl_xor_sync(0xffffffffu, ss, 1);
        float rs = rsqrtf(ss * (1.f / 128.f) + LN_EPS);
        if (l4 == 0) { s_mu[r] = mu; s_rs[r] = rs; }
    }
    __syncthreads();

    {
        float4* out4 = (float4*)out;
        const float4* gm4 = (const float4*)gamma;
        const float4* bt4 = (const float4*)beta;
        for (int i = tid; i < BM * 32; i += 256) {
            int r = i >> 5, c4 = i & 31;
            if (n0 + r < N) {
                float4 v = ((const float4*)(sY + r * 132))[c4];
                float mu = s_mu[r], rs = s_rs[r];
                float4 gv = gm4[c4], bv = bt4[c4];
                v.x = fmaf((v.x - mu) * rs, gv.x, bv.x);
                v.y = fmaf((v.y - mu) * rs, gv.y, bv.y);
                v.z = fmaf((v.z - mu) * rs, gv.z, bv.z);
                v.w = fmaf((v.w - mu) * rs, gv.w, bv.w);
                out4[(size_t)(n0 + r) * 32 + c4] = v;
            }
        }
    }
}

extern "C" void kernel_launch(void* const* d_in, const int* in_sizes, int n_in,
                              void* d_out, int out_size) {
    const float* x     = (const float*)d_in[0];
    const void*  eidx  = d_in[1];
    const float* eattr = (const float*)d_in[2];
    const float* mW1 = (const float*)d_in[3];
    const float* mb1 = (const float*)d_in[4];
    const float* mW2 = (const float*)d_in[5];
    const float* mb2 = (const float*)d_in[6];
    const float* uW1 = (const float*)d_in[7];
    const float* ub1 = (const float*)d_in[8];
    const float* uW2 = (const float*)d_in[9];
    const float* ub2 = (const float*)d_in[10];
    const float* gamma = (const float*)d_in[11];
    const float* beta  = (const float*)d_in[12];
    float* out = (float*)d_out;

    const int N = in_sizes[0] / HID;   // 50000
    const int E = in_sizes[2] / HID;   // 640000

    cudaFuncSetAttribute(edge_kernel, cudaFuncAttributeMaxDynamicSharedMemorySize, SMEM_BYTES);
    cudaFuncSetAttribute(node_kernel, cudaFuncAttributeMaxDynamicSharedMemorySize, SMEM_BYTES);

    detect_kernel<<<1, 1>>>((const int*)eidx);
    prepack_kernel<<<224, 256>>>(mW1, mW2, uW1, uW2);

    int zcnt = (N * HID) / 4;
    zero_kernel<<<(zcnt + 255) / 256, 256>>>(zcnt);

    edge_kernel<<<(E + BM - 1) / BM, 256, SMEM_BYTES>>>(x, eidx, eattr, mb1, mb2, E);

    node_kernel<<<(N + BM - 1) / BM, 256, SMEM_BYTES>>>(x, ub1, ub2, gamma, beta, out, N);
}

// round 9
// speedup vs baseline: 5.6249x; 1.2060x over previous
#include <cuda_runtime.h>
#include <cuda_pipeline.h>

#define HID 128
#define MAXN 50048
#define MAXE 640000
#define LN_EPS 1e-5f

#define BM 64
#define SA_STR 20      // uint32 stride per A row (16 + 4 pad)
#define SB_STR 132     // uint32 stride per B k2-row (128 + 4 pad)
#define SH_STR 68      // uint32 stride per H/T row (64 + 4 pad)

// smem layout (uint32 units)
#define OFF_AH 0
#define OFF_AL (OFF_AH + 2*BM*SA_STR)   // 2560
#define OFF_BH (OFF_AL + 2*BM*SA_STR)   // 5120
#define OFF_BL (OFF_BH + 2*16*SB_STR)   // 9344
#define OFF_HH (OFF_BL + 2*16*SB_STR)   // 13568
#define OFF_HL (OFF_HH + BM*SH_STR)     // 17920
#define OFF_IX (OFF_HL + BM*SH_STR)     // 22272
#define SMEM_U (OFF_IX + 2*BM)          // 22400
#define NODE_SMEM (SMEM_U * 4)          // 89600
#define GEMM_SMEM (OFF_HH * 4)          // 54272

// scratch (static device memory; no runtime allocs)
__device__ __align__(256) float g_P[(size_t)MAXN * HID];
__device__ __align__(256) float g_Q[(size_t)MAXN * HID];
__device__ __align__(256) float g_R[(size_t)MAXE * HID];
__device__ __align__(256) float g_aggH[(size_t)MAXN * HID];
__device__ __align__(256) float g_deg[MAXN];
__device__ int g_idx64;

// prepacked bf16x2 (hi,lo) weights, k-pair packed [k2][n]
__device__ __align__(16) unsigned m1a_h[64*128], m1a_l[64*128];
__device__ __align__(16) unsigned m1b_h[64*128], m1b_l[64*128];
__device__ __align__(16) unsigned m1c_h[64*128], m1c_l[64*128];
__device__ __align__(16) unsigned m2h [64*128], m2l [64*128];
__device__ __align__(16) unsigned u1h[128*128], u1l[128*128];
__device__ __align__(16) unsigned u2h [64*128], u2l [64*128];

__global__ void detect_kernel(const int* __restrict__ ei) {
    g_idx64 = (ei[1] == 0 && ei[3] == 0 && ei[5] == 0 && ei[7] == 0) ? 1 : 0;
}

__global__ void zero_kernel(float* __restrict__ p, int n4) {
    int i = blockIdx.x * blockDim.x + threadIdx.x;
    if (i < n4) ((float4*)p)[i] = make_float4(0.f, 0.f, 0.f, 0.f);
}

// split pair of fp32 -> packed bf16x2 hi + lo (low16 = first arg)
__device__ __forceinline__ void split2(float a, float b, unsigned& h, unsigned& l) {
    unsigned hp;
    asm("cvt.rn.satfinite.bf16x2.f32 %0, %1, %2;" : "=r"(hp) : "f"(b), "f"(a));
    float fa = __uint_as_float(hp << 16);
    float fb = __uint_as_float(hp & 0xffff0000u);
    float la = a - fa, lb = b - fb;
    unsigned lp;
    asm("cvt.rn.satfinite.bf16x2.f32 %0, %1, %2;" : "=r"(lp) : "f"(lb), "f"(la));
    h = hp; l = lp;
}

__global__ void prepack_kernel(const float* __restrict__ mW1, const float* __restrict__ mW2,
                               const float* __restrict__ uW1, const float* __restrict__ uW2) {
    int i = blockIdx.x * 256 + threadIdx.x;
    const float* W; unsigned *H, *L; int off, koff = 0;
    if (i < 8192)       { W = mW1; H = m1a_h; L = m1a_l; off = i; }
    else if (i < 16384) { W = mW1; H = m1b_h; L = m1b_l; off = i - 8192;  koff = 128; }
    else if (i < 24576) { W = mW1; H = m1c_h; L = m1c_l; off = i - 16384; koff = 256; }
    else if (i < 32768) { W = mW2; H = m2h;   L = m2l;   off = i - 24576; }
    else if (i < 49152) { W = uW1; H = u1h;   L = u1l;   off = i - 32768; }
    else if (i < 57344) { W = uW2; H = u2h;   L = u2l;   off = i - 49152; }
    else return;
    int k2 = off >> 7, n = off & 127;
    float v0 = W[(size_t)(koff + 2*k2) * 128 + n];
    float v1 = W[(size_t)(koff + 2*k2 + 1) * 128 + n];
    unsigned h, l; split2(v0, v1, h, l);
    H[off] = h; L[off] = l;
}

__device__ __forceinline__ void mma16(float d[4], const unsigned a[4], const unsigned b[2]) {
    asm volatile(
        "mma.sync.aligned.m16n8k16.row.col.f32.bf16.bf16.f32 "
        "{%0,%1,%2,%3}, {%4,%5,%6,%7}, {%8,%9}, {%0,%1,%2,%3};\n"
        : "+f"(d[0]), "+f"(d[1]), "+f"(d[2]), "+f"(d[3])
        : "r"(a[0]), "r"(a[1]), "r"(a[2]), "r"(a[3]), "r"(b[0]), "r"(b[1]));
}

__device__ __forceinline__ void red2(float* p, float a, float b) {
    asm volatile("red.global.add.v2.f32 [%0], {%1, %2};" :: "l"(p), "f"(a), "f"(b) : "memory");
}

// one K=32 chunk: acc += A(64x32) * B(32x128), 3-term bf16 split
__device__ __forceinline__ void frag_compute(
    const unsigned* __restrict__ Ah, const unsigned* __restrict__ Al, int astr,
    const unsigned* __restrict__ Bh, const unsigned* __restrict__ Bl,
    int g, int t, int wm, int wn, float acc[2][4][4])
{
    #pragma unroll
    for (int ks = 0; ks < 2; ks++) {
        unsigned ah[2][4], al[2][4];
        #pragma unroll
        for (int i = 0; i < 2; i++) {
            const unsigned* p = Ah + (wm*32 + i*16 + g) * astr + ks*8 + t;
            ah[i][0] = p[0]; ah[i][1] = p[8*astr]; ah[i][2] = p[4]; ah[i][3] = p[8*astr + 4];
            const unsigned* q = Al + (wm*32 + i*16 + g) * astr + ks*8 + t;
            al[i][0] = q[0]; al[i][1] = q[8*astr]; al[i][2] = q[4]; al[i][3] = q[8*astr + 4];
        }
        unsigned bh[4][2], bl[4][2];
        #pragma unroll
        for (int j = 0; j < 4; j++) {
            const unsigned* p = Bh + (ks*8 + t) * SB_STR + wn*32 + j*8 + g;
            bh[j][0] = p[0]; bh[j][1] = p[4*SB_STR];
            const unsigned* q = Bl + (ks*8 + t) * SB_STR + wn*32 + j*8 + g;
            bl[j][0] = q[0]; bl[j][1] = q[4*SB_STR];
        }
        #pragma unroll
        for (int i = 0; i < 2; i++)
            #pragma unroll
            for (int j = 0; j < 4; j++) {
                mma16(acc[i][j], ah[i], bh[j]);
                mma16(acc[i][j], al[i], bh[j]);
                mma16(acc[i][j], ah[i], bl[j]);
            }
    }
}

__device__ __forceinline__ void stage_w(unsigned* dst, const unsigned* src, int c, int tid) {
    #pragma unroll
    for (int i = tid; i < 512; i += 256) {
        int r = i >> 5, q = (i & 31) * 4;
        __pipeline_memcpy_async(dst + r * SB_STR + q, src + (size_t)(c*16 + r) * 128 + q, 16);
    }
}

__device__ __forceinline__ void stA(unsigned* sAh, unsigned* sAl, int tid, const float4 v[2]) {
    int row = tid >> 2, quad = tid & 3;
    unsigned* dh = sAh + row * SA_STR + quad * 4;
    unsigned* dl = sAl + row * SA_STR + quad * 4;
    #pragma unroll
    for (int q = 0; q < 2; q++) {
        unsigned h0, l0, h1, l1;
        split2(v[q].x, v[q].y, h0, l0);
        split2(v[q].z, v[q].w, h1, l1);
        dh[2*q] = h0; dh[2*q+1] = h1;
        dl[2*q] = l0; dl[2*q+1] = l1;
    }
}

__device__ __forceinline__ void zero_acc(float acc[2][4][4]) {
    #pragma unroll
    for (int i = 0; i < 2; i++)
        #pragma unroll
        for (int j = 0; j < 4; j++)
            #pragma unroll
            for (int r = 0; r < 4; r++) acc[i][j][r] = 0.f;
}

// ---------------------------------------------------------------------------
// Dense GEMM: C[rows x 128] = A[rows x 128] @ W, no bias. 64 rows/CTA.
// ---------------------------------------------------------------------------
__global__ __launch_bounds__(256, 2)
void gemm128_kernel(const float* __restrict__ A,
                    const unsigned* __restrict__ Wh, const unsigned* __restrict__ Wl,
                    float* __restrict__ C, int rows)
{
    extern __shared__ unsigned smu[];
    unsigned* sAhB = smu + OFF_AH;
    unsigned* sAlB = smu + OFF_AL;
    unsigned* sBhB = smu + OFF_BH;
    unsigned* sBlB = smu + OFF_BL;

    const int tid = threadIdx.x;
    const int n0 = blockIdx.x * BM;
    const int lane = tid & 31, wid = tid >> 5;
    const int wm = wid >> 2, wn = wid & 3, g = lane >> 2, t = lane & 3;

    const int arow = tid >> 2, akh = (tid & 3) * 8;
    int ar = n0 + arow; if (ar >= rows) ar = rows - 1;
    const float* Ab = A + (size_t)ar * HID;
    auto ldA = [&](int c, float4 v[2]) {
        const float4* s4 = (const float4*)(Ab + c * 32 + akh);
        v[0] = s4[0]; v[1] = s4[1];
    };

    float acc[2][4][4];
    zero_acc(acc);
    float4 av[2];
    ldA(0, av);
    stage_w(sBhB, Wh, 0, tid); stage_w(sBlB, Wl, 0, tid); __pipeline_commit();
    stA(sAhB, sAlB, tid, av);
    ldA(1, av);
    __pipeline_wait_prior(0);
    __syncthreads();
    stage_w(sBhB + 16*SB_STR, Wh, 1, tid); stage_w(sBlB + 16*SB_STR, Wl, 1, tid);
    __pipeline_commit();

    int b = 0;
    #pragma unroll 1
    for (int c = 0; c < 4; c++) {
        frag_compute(sAhB + b*(BM*SA_STR), sAlB + b*(BM*SA_STR), SA_STR,
                     sBhB + b*(16*SB_STR), sBlB + b*(16*SB_STR), g, t, wm, wn, acc);
        if (c == 3) break;
        stA(sAhB + (b^1)*(BM*SA_STR), sAlB + (b^1)*(BM*SA_STR), tid, av);
        if (c + 2 < 4) ldA(c + 2, av);
        __pipeline_wait_prior(0);
        __syncthreads();
        if (c + 2 < 4) {
            stage_w(sBhB + b*(16*SB_STR), Wh, c + 2, tid);
            stage_w(sBlB + b*(16*SB_STR), Wl, c + 2, tid);
            __pipeline_commit();
        }
        b ^= 1;
    }

    #pragma unroll
    for (int i = 0; i < 2; i++) {
        int ra = wm*32 + i*16 + g;
        #pragma unroll
        for (int j = 0; j < 4; j++) {
            int c0 = wn*32 + j*8 + 2*t;
            int na = n0 + ra, nb = na + 8;
            if (na < rows)
                *(float2*)(C + (size_t)na * HID + c0) = make_float2(acc[i][j][0], acc[i][j][1]);
            if (nb < rows)
                *(float2*)(C + (size_t)nb * HID + c0) = make_float2(acc[i][j][2], acc[i][j][3]);
        }
    }
}

// ---------------------------------------------------------------------------
// Edge pass: h = relu(P[src] + Q[dst] + R[e] + b1); aggH[dst] += h; deg[dst]++
// one warp per edge
// ---------------------------------------------------------------------------
__global__ __launch_bounds__(256)
void edge_pass(const void* __restrict__ eidx, const float* __restrict__ b1, int E)
{
    int gw = (blockIdx.x * 256 + threadIdx.x) >> 5;
    int lane = threadIdx.x & 31;
    if (gw >= E) return;
    int s, d;
    if (g_idx64) {
        s = (int)((const long long*)eidx)[gw];
        d = (int)((const long long*)eidx)[(size_t)E + gw];
    } else {
        s = ((const int*)eidx)[gw];
        d = ((const int*)eidx)[(size_t)E + gw];
    }
    float4 p = ((const float4*)(g_P + (size_t)s * HID))[lane];
    float4 q = ((const float4*)(g_Q + (size_t)d * HID))[lane];
    float4 r = ((const float4*)(g_R + (size_t)gw * HID))[lane];
    float4 bv = __ldg(((const float4*)b1) + lane);
    float h0 = fmaxf(p.x + q.x + r.x + bv.x, 0.f);
    float h1 = fmaxf(p.y + q.y + r.y + bv.y, 0.f);
    float h2 = fmaxf(p.z + q.z + r.z + bv.z, 0.f);
    float h3 = fmaxf(p.w + q.w + r.w + bv.w, 0.f);
    float* dstp = g_aggH + (size_t)d * HID + lane * 4;
    red2(dstp, h0, h1);
    red2(dstp + 2, h2, h3);
    if (lane == 0)
        asm volatile("red.global.add.f32 [%0], %1;" :: "l"(g_deg + d), "f"(1.0f) : "memory");
}

// ---------------------------------------------------------------------------
// Node kernel: T = aggH@W2 + deg*b2; u = relu([x|T]@U1+ub1); upd = u@U2+ub2;
// out = LN(x + upd)
// ---------------------------------------------------------------------------
__device__ __forceinline__ void write_T(unsigned* sTh, unsigned* sTl, const float* b2,
                                        int n0, int N, int g, int t, int wm, int wn,
                                        float acc[2][4][4]) {
    #pragma unroll
    for (int i = 0; i < 2; i++) {
        int r = wm*32 + i*16 + g;
        #pragma unroll
        for (int j = 0; j < 4; j++) {
            int c0 = wn*32 + j*8 + 2*t;
            float2 bb = *(const float2*)(b2 + c0);
            int ci = wn*16 + j*4 + t;
            int na = n0 + r;     if (na >= N) na = N - 1;
            int nb = n0 + r + 8; if (nb >= N) nb = N - 1;
            float da = g_deg[na], db = g_deg[nb];
            unsigned h, l;
            split2(acc[i][j][0] + da*bb.x, acc[i][j][1] + da*bb.y, h, l);
            sTh[r * SH_STR + ci] = h; sTl[r * SH_STR + ci] = l;
            split2(acc[i][j][2] + db*bb.x, acc[i][j][3] + db*bb.y, h, l);
            sTh[(r+8) * SH_STR + ci] = h; sTl[(r+8) * SH_STR + ci] = l;
        }
    }
}

__device__ __forceinline__ void write_H(unsigned* sHh, unsigned* sHl, const float* b1,
                                        int g, int t, int wm, int wn, float acc[2][4][4]) {
    #pragma unroll
    for (int i = 0; i < 2; i++) {
        int r = wm*32 + i*16 + g;
        #pragma unroll
        for (int j = 0; j < 4; j++) {
            int c0 = wn*32 + j*8 + 2*t;
            float2 bb = *(const float2*)(b1 + c0);
            int ci = wn*16 + j*4 + t;
            float a0 = fmaxf(acc[i][j][0] + bb.x, 0.f);
            float a1 = fmaxf(acc[i][j][1] + bb.y, 0.f);
            float a2 = fmaxf(acc[i][j][2] + bb.x, 0.f);
            float a3 = fmaxf(acc[i][j][3] + bb.y, 0.f);
            unsigned h, l;
            split2(a0, a1, h, l);
            sHh[r * SH_STR + ci] = h; sHl[r * SH_STR + ci] = l;
            split2(a2, a3, h, l);
            sHh[(r+8) * SH_STR + ci] = h; sHl[(r+8) * SH_STR + ci] = l;
        }
    }
}

__global__ __launch_bounds__(256, 2)
void node_kernel(const float* __restrict__ x, const float* __restrict__ mb2,
                 const float* __restrict__ ub1, const float* __restrict__ ub2,
                 const float* __restrict__ gamma, const float* __restrict__ beta,
                 float* __restrict__ out, int N)
{
    extern __shared__ unsigned smu[];
    unsigned* sAhB = smu + OFF_AH;
    unsigned* sAlB = smu + OFF_AL;
    unsigned* sBhB = smu + OFF_BH;
    unsigned* sBlB = smu + OFF_BL;
    unsigned* sTh  = smu + OFF_HH;
    unsigned* sTl  = smu + OFF_HL;
    float* s_mu = (float*)(smu + OFF_IX);
    float* s_rs = s_mu + BM;

    const int tid = threadIdx.x;
    const int n0 = blockIdx.x * BM;
    const int lane = tid & 31, wid = tid >> 5;
    const int wm = wid >> 2, wn = wid & 3, g = lane >> 2, t = lane & 3;

    const int arow = tid >> 2, akh = (tid & 3) * 8;
    int an = n0 + arow; if (an >= N) an = N - 1;
    const float* base_agg = g_aggH + (size_t)an * HID;
    const float* base_x   = x      + (size_t)an * HID;
    auto ldAp = [&](const float* base, int c, float4 v[2]) {
        const float4* s4 = (const float4*)(base + c * 32 + akh);
        v[0] = s4[0]; v[1] = s4[1];
    };

    float acc[2][4][4];
    float4 av[2];
    int b;

    // ---- Stage 0: T = aggH @ W2 (+deg*b2), K=128 ----
    zero_acc(acc);
    ldAp(base_agg, 0, av);
    stage_w(sBhB, m2h, 0, tid); stage_w(sBlB, m2l, 0, tid); __pipeline_commit();
    stA(sAhB, sAlB, tid, av);
    ldAp(base_agg, 1, av);
    __pipeline_wait_prior(0);
    __syncthreads();
    stage_w(sBhB + 16*SB_STR, m2h, 1, tid); stage_w(sBlB + 16*SB_STR, m2l, 1, tid);
    __pipeline_commit();
    b = 0;
    #pragma unroll 1
    for (int c = 0; c < 4; c++) {
        frag_compute(sAhB + b*(BM*SA_STR), sAlB + b*(BM*SA_STR), SA_STR,
                     sBhB + b*(16*SB_STR), sBlB + b*(16*SB_STR), g, t, wm, wn, acc);
        if (c == 3) break;
        stA(sAhB + (b^1)*(BM*SA_STR), sAlB + (b^1)*(BM*SA_STR), tid, av);
        if (c + 2 < 4) ldAp(base_agg, c + 2, av);
        __pipeline_wait_prior(0);
        __syncthreads();
        if (c + 2 < 4) {
            stage_w(sBhB + b*(16*SB_STR), m2h, c + 2, tid);
            stage_w(sBlB + b*(16*SB_STR), m2l, c + 2, tid);
            __pipeline_commit();
        }
        b ^= 1;
    }
    write_T(sTh, sTl, mb2, n0, N, g, t, wm, wn, acc);
    __syncthreads();

    // ---- Layer 1: K=256 (chunks 0-3 A=x staged, 4-7 A=T tiles) ----
    zero_acc(acc);
    ldAp(base_x, 0, av);
    stage_w(sBhB, u1h, 0, tid); stage_w(sBlB, u1l, 0, tid); __pipeline_commit();
    stA(sAhB, sAlB, tid, av);
    ldAp(base_x, 1, av);
    __pipeline_wait_prior(0);
    __syncthreads();
    stage_w(sBhB + 16*SB_STR, u1h, 1, tid); stage_w(sBlB + 16*SB_STR, u1l, 1, tid);
    __pipeline_commit();
    b = 0;
    #pragma unroll 1
    for (int c = 0; c < 8; c++) {
        const unsigned *Ah, *Al; int astr;
        if (c < 4) { Ah = sAhB + b*(BM*SA_STR); Al = sAlB + b*(BM*SA_STR); astr = SA_STR; }
        else       { Ah = sTh + (c - 4) * 16;   Al = sTl + (c - 4) * 16;   astr = SH_STR; }
        frag_compute(Ah, Al, astr,
                     sBhB + b*(16*SB_STR), sBlB + b*(16*SB_STR), g, t, wm, wn, acc);
        if (c == 7) break;
        if (c + 1 < 4) stA(sAhB + (b^1)*(BM*SA_STR), sAlB + (b^1)*(BM*SA_STR), tid, av);
        if (c + 2 < 4) ldAp(base_x, c + 2, av);
        __pipeline_wait_prior(0);
        __syncthreads();
        if (c + 2 < 8) {
            stage_w(sBhB + b*(16*SB_STR), u1h, c + 2, tid);
            stage_w(sBlB + b*(16*SB_STR), u1l, c + 2, tid);
            __pipeline_commit();
        }
        b ^= 1;
    }
    __syncthreads();            // all T reads done before overwrite
    write_H(sTh, sTl, ub1, g, t, wm, wn, acc);
    __syncthreads();

    // ---- Layer 2: K=128, A = H tiles ----
    zero_acc(acc);
    stage_w(sBhB, u2h, 0, tid); stage_w(sBlB, u2l, 0, tid); __pipeline_commit();
    __pipeline_wait_prior(0);
    __syncthreads();
    stage_w(sBhB + 16*SB_STR, u2h, 1, tid); stage_w(sBlB + 16*SB_STR, u2l, 1, tid);
    __pipeline_commit();
    b = 0;
    #pragma unroll 1
    for (int c = 0; c < 4; c++) {
        frag_compute(sTh + c*16, sTl + c*16, SH_STR,
                     sBhB + b*(16*SB_STR), sBlB + b*(16*SB_STR), g, t, wm, wn, acc);
        if (c == 3) break;
        __pipeline_wait_prior(0);
        __syncthreads();
        if (c + 2 < 4) {
            stage_w(sBhB + b*(16*SB_STR), u2h, c + 2, tid);
            stage_w(sBlB + b*(16*SB_STR), u2l, c + 2, tid);
            __pipeline_commit();
        }
        b ^= 1;
    }

    __syncthreads();
    float* sY = (float*)sTh;   // [64][132] floats

    #pragma unroll
    for (int i = 0; i < 2; i++) {
        int ra = wm*32 + i*16 + g;
        #pragma unroll
        for (int j = 0; j < 4; j++) {
            int c0 = wn*32 + j*8 + 2*t;
            float2 bb = *(const float2*)(ub2 + c0);
            int na = n0 + ra;     if (na >= N) na = N - 1;
            int nb = n0 + ra + 8; if (nb >= N) nb = N - 1;
            float2 xa = *(const float2*)(x + (size_t)na * HID + c0);
            float2 xb = *(const float2*)(x + (size_t)nb * HID + c0);
            sY[ra * 132 + c0]         = acc[i][j][0] + bb.x + xa.x;
            sY[ra * 132 + c0 + 1]     = acc[i][j][1] + bb.y + xa.y;
            sY[(ra+8) * 132 + c0]     = acc[i][j][2] + bb.x + xb.x;
            sY[(ra+8) * 132 + c0 + 1] = acc[i][j][3] + bb.y + xb.y;
        }
    }
    __syncthreads();

    {
        int r = tid >> 2, l4 = tid & 3;
        const float* row = sY + r * 132 + l4 * 32;
        float s = 0.f;
        #pragma unroll
        for (int c = 0; c < 32; c++) s += row[c];
        s += __shfl_xor_sync(0xffffffffu, s, 2);
        s += __shfl_xor_sync(0xffffffffu, s, 1);
        float mu = s * (1.f / 128.f);
        float ss = 0.f;
        #pragma unroll
        for (int c = 0; c < 32; c++) { float d = row[c] - mu; ss = fmaf(d, d, ss); }
        ss += __shfl_xor_sync(0xffffffffu, ss, 2);
        ss += __shfl_xor_sync(0xffffffffu, ss, 1);
        float rs = rsqrtf(ss * (1.f / 128.f) + LN_EPS);
        if (l4 == 0) { s_mu[r] = mu; s_rs[r] = rs; }
    }
    __syncthreads();

    {
        float4* out4 = (float4*)out;
        const float4* gm4 = (const float4*)gamma;
        const float4* bt4 = (const float4*)beta;
        for (int i = tid; i < BM * 32; i += 256) {
            int r = i >> 5, c4 = i & 31;
            if (n0 + r < N) {
                float4 v = ((const float4*)(sY + r * 132))[c4];
                float mu = s_mu[r], rs = s_rs[r];
                float4 gv = gm4[c4], bv = bt4[c4];
                v.x = fmaf((v.x - mu) * rs, gv.x, bv.x);
                v.y = fmaf((v.y - mu) * rs, gv.y, bv.y);
                v.z = fmaf((v.z - mu) * rs, gv.z, bv.z);
                v.w = fmaf((v.w - mu) * rs, gv.w, bv.w);
                out4[(size_t)(n0 + r) * 32 + c4] = v;
            }
        }
    }
}

extern "C" void kernel_launch(void* const* d_in, const int* in_sizes, int n_in,
                              void* d_out, int out_size) {
    const float* x     = (const float*)d_in[0];
    const void*  eidx  = d_in[1];
    const float* eattr = (const float*)d_in[2];
    const float* mW1 = (const float*)d_in[3];
    const float* mb1 = (const float*)d_in[4];
    const float* mW2 = (const float*)d_in[5];
    const float* mb2 = (const float*)d_in[6];
    const float* uW1 = (const float*)d_in[7];
    const float* ub1 = (const float*)d_in[8];
    const float* uW2 = (const float*)d_in[9];
    const float* ub2 = (const float*)d_in[10];
    const float* gamma = (const float*)d_in[11];
    const float* beta  = (const float*)d_in[12];
    float* out = (float*)d_out;

    const int N = in_sizes[0] / HID;   // 50000
    const int E = in_sizes[2] / HID;   // 640000

    cudaFuncSetAttribute(gemm128_kernel, cudaFuncAttributeMaxDynamicSharedMemorySize, GEMM_SMEM);
    cudaFuncSetAttribute(node_kernel,    cudaFuncAttributeMaxDynamicSharedMemorySize, NODE_SMEM);

    detect_kernel<<<1, 1>>>((const int*)eidx);
    prepack_kernel<<<224, 256>>>(mW1, mW2, uW1, uW2);

    // zero aggregation buffers
    {
        float* aggp; cudaGetSymbolAddress((void**)&aggp, g_aggH);
        float* degp; cudaGetSymbolAddress((void**)&degp, g_deg);
        int a4 = MAXN * 32;
        zero_kernel<<<(a4 + 255) / 256, 256>>>(aggp, a4);
        int d4 = MAXN / 4;
        zero_kernel<<<(d4 + 255) / 256, 256>>>(degp, d4);
    }

    // dense precompute GEMMs
    {
        float *Pp, *Qp, *Rp;
        cudaGetSymbolAddress((void**)&Pp, g_P);
        cudaGetSymbolAddress((void**)&Qp, g_Q);
        cudaGetSymbolAddress((void**)&Rp, g_R);
        unsigned *a_h, *a_l, *b_h, *b_l, *c_h, *c_l;
        cudaGetSymbolAddress((void**)&a_h, m1a_h); cudaGetSymbolAddress((void**)&a_l, m1a_l);
        cudaGetSymbolAddress((void**)&b_h, m1b_h); cudaGetSymbolAddress((void**)&b_l, m1b_l);
        cudaGetSymbolAddress((void**)&c_h, m1c_h); cudaGetSymbolAddress((void**)&c_l, m1c_l);
        gemm128_kernel<<<(N + BM - 1) / BM, 256, GEMM_SMEM>>>(x, a_h, a_l, Pp, N);
        gemm128_kernel<<<(N + BM - 1) / BM, 256, GEMM_SMEM>>>(x, b_h, b_l, Qp, N);
        gemm128_kernel<<<(E + BM - 1) / BM, 256, GEMM_SMEM>>>(eattr, c_h, c_l, Rp, E);
    }

    edge_pass<<<(E + 7) / 8, 256>>>(eidx, mb1, E);

    node_kernel<<<(N + BM - 1) / BM, 256, NODE_SMEM>>>(x, mb2, ub1, ub2,
                                                       gamma, beta, out, N);
}

// round 11
// speedup vs baseline: 7.3879x; 1.3134x over previous
#include <cuda_runtime.h>
#include <cuda_pipeline.h>

#define HID 128
#define MAXN 50048
#define LN_EPS 1e-5f

#define BM 64
#define SA_STR 20      // uint32 stride per A row (16 + 4 pad)
#define SB_STR 132     // uint32 stride per B k2-row (128 + 4 pad)
#define SH_STR 68      // uint32 stride per H row (64 + 4 pad)

// smem layout (uint32 units)
#define OFF_AH 0
#define OFF_AL (OFF_AH + 2*BM*SA_STR)   // 2560
#define OFF_BH (OFF_AL + 2*BM*SA_STR)   // 5120
#define OFF_BL (OFF_BH + 2*16*SB_STR)   // 9344
#define OFF_HH (OFF_BL + 2*16*SB_STR)   // 13568
#define OFF_HL (OFF_HH + BM*SH_STR)     // 17920
#define OFF_IX (OFF_HL + BM*SH_STR)     // 22272
#define SMEM_U (OFF_IX + 2*BM)          // 22400
#define NODE_SMEM (SMEM_U * 4)          // 89600
#define GEMM_SMEM (OFF_HH * 4)          // 54272
#define EDGE_SMEM ((OFF_HH + 128) * 4)  // 54784

// scratch (static device memory)
__device__ __align__(256) float g_P[(size_t)MAXN * HID];
__device__ __align__(256) float g_Q[(size_t)MAXN * HID];
__device__ __align__(256) float g_S[(size_t)MAXN * HID];
__device__ __align__(256) float g_aggH[(size_t)MAXN * HID];
__device__ __align__(256) float g_deg[MAXN];
__device__ __align__(256) float g_V[128*128];
__device__ __align__(256) float g_vb[128];
__device__ int g_idx64;

// prepacked bf16x2 (hi,lo) weights, k-pair packed [k2][n]
__device__ __align__(16) unsigned m1a_h[64*128], m1a_l[64*128];
__device__ __align__(16) unsigned m1b_h[64*128], m1b_l[64*128];
__device__ __align__(16) unsigned m1c_h[64*128], m1c_l[64*128];
__device__ __align__(16) unsigned u1a_h[64*128], u1a_l[64*128];
__device__ __align__(16) unsigned vvh [64*128], vvl [64*128];
__device__ __align__(16) unsigned u2h [64*128], u2l [64*128];

__global__ void detect_kernel(const int* __restrict__ ei) {
    g_idx64 = (ei[1] == 0 && ei[3] == 0 && ei[5] == 0 && ei[7] == 0) ? 1 : 0;
}

__global__ void zero_kernel(float* __restrict__ p, int n4) {
    int i = blockIdx.x * blockDim.x + threadIdx.x;
    if (i < n4) ((float4*)p)[i] = make_float4(0.f, 0.f, 0.f, 0.f);
}

// V = W2 @ U1b  (U1b = rows 128..255 of uW1); vb = b2 @ U1b
__global__ void compose_V(const float* __restrict__ mW2, const float* __restrict__ uW1,
                          const float* __restrict__ b2) {
    int i = blockIdx.x * 256 + threadIdx.x;
    if (i >= 16384) return;
    int r = i >> 7, j = i & 127;
    float s = 0.f;
    #pragma unroll 4
    for (int k = 0; k < 128; k++)
        s = fmaf(mW2[r * 128 + k], uW1[(size_t)(128 + k) * 128 + j], s);
    g_V[i] = s;
    if (i < 128) {
        float vb = 0.f;
        #pragma unroll 4
        for (int k = 0; k < 128; k++)
            vb = fmaf(b2[k], uW1[(size_t)(128 + k) * 128 + i], vb);
        g_vb[i] = vb;
    }
}

// split pair of fp32 -> packed bf16x2 hi + lo (low16 = first arg)
__device__ __forceinline__ void split2(float a, float b, unsigned& h, unsigned& l) {
    unsigned hp;
    asm("cvt.rn.satfinite.bf16x2.f32 %0, %1, %2;" : "=r"(hp) : "f"(b), "f"(a));
    float fa = __uint_as_float(hp << 16);
    float fb = __uint_as_float(hp & 0xffff0000u);
    float la = a - fa, lb = b - fb;
    unsigned lp;
    asm("cvt.rn.satfinite.bf16x2.f32 %0, %1, %2;" : "=r"(lp) : "f"(lb), "f"(la));
    h = hp; l = lp;
}

__global__ void prepack_kernel(const float* __restrict__ mW1,
                               const float* __restrict__ uW1,
                               const float* __restrict__ uW2) {
    int i = blockIdx.x * 256 + threadIdx.x;
    const float* W; unsigned *H, *L; int off, koff = 0;
    if (i < 8192)       { W = mW1; H = m1a_h; L = m1a_l; off = i; }
    else if (i < 16384) { W = mW1; H = m1b_h; L = m1b_l; off = i - 8192;  koff = 128; }
    else if (i < 24576) { W = mW1; H = m1c_h; L = m1c_l; off = i - 16384; koff = 256; }
    else if (i < 32768) { W = uW1; H = u1a_h; L = u1a_l; off = i - 24576; }
    else if (i < 40960) { W = g_V; H = vvh;   L = vvl;   off = i - 32768; }
    else if (i < 49152) { W = uW2; H = u2h;   L = u2l;   off = i - 40960; }
    else return;
    int k2 = off >> 7, n = off & 127;
    float v0 = W[(size_t)(koff + 2*k2) * 128 + n];
    float v1 = W[(size_t)(koff + 2*k2 + 1) * 128 + n];
    unsigned h, l; split2(v0, v1, h, l);
    H[off] = h; L[off] = l;
}

__device__ __forceinline__ void mma16(float d[4], const unsigned a[4], const unsigned b[2]) {
    asm volatile(
        "mma.sync.aligned.m16n8k16.row.col.f32.bf16.bf16.f32 "
        "{%0,%1,%2,%3}, {%4,%5,%6,%7}, {%8,%9}, {%0,%1,%2,%3};\n"
        : "+f"(d[0]), "+f"(d[1]), "+f"(d[2]), "+f"(d[3])
        : "r"(a[0]), "r"(a[1]), "r"(a[2]), "r"(a[3]), "r"(b[0]), "r"(b[1]));
}

__device__ __forceinline__ void red2(float* p, float a, float b) {
    asm volatile("red.global.add.v2.f32 [%0], {%1, %2};" :: "l"(p), "f"(a), "f"(b) : "memory");
}

// one K=32 chunk: acc += A(64x32) * B(32x128), 3-term bf16 split
__device__ __forceinline__ void frag_compute(
    const unsigned* __restrict__ Ah, const unsigned* __restrict__ Al, int astr,
    const unsigned* __restrict__ Bh, const unsigned* __restrict__ Bl,
    int g, int t, int wm, int wn, float acc[2][4][4])
{
    #pragma unroll
    for (int ks = 0; ks < 2; ks++) {
        unsigned ah[2][4], al[2][4];
        #pragma unroll
        for (int i = 0; i < 2; i++) {
            const unsigned* p = Ah + (wm*32 + i*16 + g) * astr + ks*8 + t;
            ah[i][0] = p[0]; ah[i][1] = p[8*astr]; ah[i][2] = p[4]; ah[i][3] = p[8*astr + 4];
            const unsigned* q = Al + (wm*32 + i*16 + g) * astr + ks*8 + t;
            al[i][0] = q[0]; al[i][1] = q[8*astr]; al[i][2] = q[4]; al[i][3] = q[8*astr + 4];
        }
        unsigned bh[4][2], bl[4][2];
        #pragma unroll
        for (int j = 0; j < 4; j++) {
            const unsigned* p = Bh + (ks*8 + t) * SB_STR + wn*32 + j*8 + g;
            bh[j][0] = p[0]; bh[j][1] = p[4*SB_STR];
            const unsigned* q = Bl + (ks*8 + t) * SB_STR + wn*32 + j*8 + g;
            bl[j][0] = q[0]; bl[j][1] = q[4*SB_STR];
        }
        #pragma unroll
        for (int i = 0; i < 2; i++)
            #pragma unroll
            for (int j = 0; j < 4; j++) {
                mma16(acc[i][j], ah[i], bh[j]);
                mma16(acc[i][j], al[i], bh[j]);
                mma16(acc[i][j], ah[i], bl[j]);
            }
    }
}

__device__ __forceinline__ void stage_w(unsigned* dst, const unsigned* src, int c, int tid) {
    #pragma unroll
    for (int i = tid; i < 512; i += 256) {
        int r = i >> 5, q = (i & 31) * 4;
        __pipeline_memcpy_async(dst + r * SB_STR + q, src + (size_t)(c*16 + r) * 128 + q, 16);
    }
}

__device__ __forceinline__ void stA(unsigned* sAh, unsigned* sAl, int tid, const float4 v[2]) {
    int row = tid >> 2, quad = tid & 3;
    unsigned* dh = sAh + row * SA_STR + quad * 4;
    unsigned* dl = sAl + row * SA_STR + quad * 4;
    #pragma unroll
    for (int q = 0; q < 2; q++) {
        unsigned h0, l0, h1, l1;
        split2(v[q].x, v[q].y, h0, l0);
        split2(v[q].z, v[q].w, h1, l1);
        dh[2*q] = h0; dh[2*q+1] = h1;
        dl[2*q] = l0; dl[2*q+1] = l1;
    }
}

__device__ __forceinline__ void zero_acc(float acc[2][4][4]) {
    #pragma unroll
    for (int i = 0; i < 2; i++)
        #pragma unroll
        for (int j = 0; j < 4; j++)
            #pragma unroll
            for (int r = 0; r < 4; r++) acc[i][j][r] = 0.f;
}

// K=128 GEMM mainloop over A staged from gmem (4 chunks, double-buffered)
#define GEMM_MAIN(ldA_expr, Wh, Wl) do { \
    float4 av[2]; \
    ldA_expr(0, av); \
    stage_w(sBhB, Wh, 0, tid); stage_w(sBlB, Wl, 0, tid); __pipeline_commit(); \
    stA(sAhB, sAlB, tid, av); \
    ldA_expr(1, av); \
    __pipeline_wait_prior(0); \
    __syncthreads(); \
    stage_w(sBhB + 16*SB_STR, Wh, 1, tid); stage_w(sBlB + 16*SB_STR, Wl, 1, tid); \
    __pipeline_commit(); \
    int b = 0; \
    _Pragma("unroll 1") \
    for (int c = 0; c < 4; c++) { \
        frag_compute(sAhB + b*(BM*SA_STR), sAlB + b*(BM*SA_STR), SA_STR, \
                     sBhB + b*(16*SB_STR), sBlB + b*(16*SB_STR), g, t, wm, wn, acc); \
        if (c == 3) break; \
        stA(sAhB + (b^1)*(BM*SA_STR), sAlB + (b^1)*(BM*SA_STR), tid, av); \
        if (c + 2 < 4) ldA_expr(c + 2, av); \
        __pipeline_wait_prior(0); \
        __syncthreads(); \
        if (c + 2 < 4) { \
            stage_w(sBhB + b*(16*SB_STR), Wh, c + 2, tid); \
            stage_w(sBlB + b*(16*SB_STR), Wl, c + 2, tid); \
            __pipeline_commit(); \
        } \
        b ^= 1; \
    } \
} while (0)

// ---------------------------------------------------------------------------
// Dense GEMM: C[rows x 128] = A[rows x 128] @ W. 64 rows/CTA.
// ---------------------------------------------------------------------------
__global__ __launch_bounds__(256, 2)
void gemm128_kernel(const float* __restrict__ A,
                    const unsigned* __restrict__ Wh, const unsigned* __restrict__ Wl,
                    float* __restrict__ C, int rows)
{
    extern __shared__ unsigned smu[];
    unsigned* sAhB = smu + OFF_AH;
    unsigned* sAlB = smu + OFF_AL;
    unsigned* sBhB = smu + OFF_BH;
    unsigned* sBlB = smu + OFF_BL;

    const int tid = threadIdx.x;
    const int n0 = blockIdx.x * BM;
    const int lane = tid & 31, wid = tid >> 5;
    const int wm = wid >> 2, wn = wid & 3, g = lane >> 2, t = lane & 3;

    const int arow = tid >> 2, akh = (tid & 3) * 8;
    int ar = n0 + arow; if (ar >= rows) ar = rows - 1;
    const float* Ab = A + (size_t)ar * HID;
    auto ldA = [&](int c, float4 v[2]) {
        const float4* s4 = (const float4*)(Ab + c * 32 + akh);
        v[0] = s4[0]; v[1] = s4[1];
    };

    float acc[2][4][4];
    zero_acc(acc);
    GEMM_MAIN(ldA, Wh, Wl);

    #pragma unroll
    for (int i = 0; i < 2; i++) {
        int ra = wm*32 + i*16 + g;
        #pragma unroll
        for (int j = 0; j < 4; j++) {
            int c0 = wn*32 + j*8 + 2*t;
            int na = n0 + ra, nb = na + 8;
            if (na < rows)
                *(float2*)(C + (size_t)na * HID + c0) = make_float2(acc[i][j][0], acc[i][j][1]);
            if (nb < rows)
                *(float2*)(C + (size_t)nb * HID + c0) = make_float2(acc[i][j][2], acc[i][j][3]);
        }
    }
}

// ---------------------------------------------------------------------------
// Fused edge kernel: R = eattr@W1c (in-register), then
// h = relu(P[src] + Q[dst] + R + b1); aggH[dst] += h; deg[dst] += 1
// ---------------------------------------------------------------------------
__global__ __launch_bounds__(256, 2)
void edge_fused(const float* __restrict__ eattr, const void* __restrict__ eidx,
                const float* __restrict__ b1, int E)
{
    extern __shared__ unsigned smu[];
    unsigned* sAhB = smu + OFF_AH;
    unsigned* sAlB = smu + OFF_AL;
    unsigned* sBhB = smu + OFF_BH;
    unsigned* sBlB = smu + OFF_BL;
    int* s_src = (int*)(smu + OFF_HH);
    int* s_dst = s_src + BM;

    const int tid = threadIdx.x;
    const int e0 = blockIdx.x * BM;
    const int lane = tid & 31, wid = tid >> 5;
    const int wm = wid >> 2, wn = wid & 3, g = lane >> 2, t = lane & 3;

    if (tid < BM) {
        int e = e0 + tid; if (e >= E) e = E - 1;
        int s, d;
        if (g_idx64) {
            s = (int)((const long long*)eidx)[e];
            d = (int)((const long long*)eidx)[(size_t)E + e];
        } else {
            s = ((const int*)eidx)[e];
            d = ((const int*)eidx)[(size_t)E + e];
        }
        s_src[tid] = s; s_dst[tid] = d;
    }
    __syncthreads();

    const int arow = tid >> 2, akh = (tid & 3) * 8;
    int ar = e0 + arow; if (ar >= E) ar = E - 1;
    const float* Ab = eattr + (size_t)ar * HID;
    auto ldA = [&](int c, float4 v[2]) {
        const float4* s4 = (const float4*)(Ab + c * 32 + akh);
        v[0] = s4[0]; v[1] = s4[1];
    };

    float acc[2][4][4];
    zero_acc(acc);
    GEMM_MAIN(ldA, m1c_h, m1c_l);

    // epilogue: add P[src], Q[dst], b1; relu; scatter-add
    #pragma unroll
    for (int i = 0; i < 2; i++) {
        int ra = wm*32 + i*16 + g;
        int rb = ra + 8;
        #pragma unroll
        for (int j = 0; j < 4; j++) {
            int c0 = wn*32 + j*8 + 2*t;
            float2 bb = *(const float2*)(b1 + c0);
            if (e0 + ra < E) {
                int s = s_src[ra], d = s_dst[ra];
                float2 p = *(const float2*)(g_P + (size_t)s * HID + c0);
                float2 q = *(const float2*)(g_Q + (size_t)d * HID + c0);
                float h0 = fmaxf(acc[i][j][0] + p.x + q.x + bb.x, 0.f);
                float h1 = fmaxf(acc[i][j][1] + p.y + q.y + bb.y, 0.f);
                red2(g_aggH + (size_t)d * HID + c0, h0, h1);
            }
            if (e0 + rb < E) {
                int s = s_src[rb], d = s_dst[rb];
                float2 p = *(const float2*)(g_P + (size_t)s * HID + c0);
                float2 q = *(const float2*)(g_Q + (size_t)d * HID + c0);
                float h0 = fmaxf(acc[i][j][2] + p.x + q.x + bb.x, 0.f);
                float h1 = fmaxf(acc[i][j][3] + p.y + q.y + bb.y, 0.f);
                red2(g_aggH + (size_t)d * HID + c0, h0, h1);
            }
        }
    }
    if (tid < BM && e0 + tid < E)
        asm volatile("red.global.add.f32 [%0], %1;" :: "l"(g_deg + s_dst[tid]), "f"(1.0f) : "memory");
}

// ---------------------------------------------------------------------------
// Node kernel: u = relu(aggH@V + S + deg*vb + ub1); upd = u@U2 + ub2;
// out = LN(x + upd)
// ---------------------------------------------------------------------------
__global__ __launch_bounds__(256, 2)
void node_kernel(const float* __restrict__ x,
                 const float* __restrict__ ub1, const float* __restrict__ ub2,
                 const float* __restrict__ gamma, const float* __restrict__ beta,
                 float* __restrict__ out, int N)
{
    extern __shared__ unsigned smu[];
    unsigned* sAhB = smu + OFF_AH;
    unsigned* sAlB = smu + OFF_AL;
    unsigned* sBhB = smu + OFF_BH;
    unsigned* sBlB = smu + OFF_BL;
    unsigned* sTh  = smu + OFF_HH;
    unsigned* sTl  = smu + OFF_HL;
    float* s_mu = (float*)(smu + OFF_IX);
    float* s_rs = s_mu + BM;

    const int tid = threadIdx.x;
    const int n0 = blockIdx.x * BM;
    const int lane = tid & 31, wid = tid >> 5;
    const int wm = wid >> 2, wn = wid & 3, g = lane >> 2, t = lane & 3;

    const int arow = tid >> 2, akh = (tid & 3) * 8;
    int an = n0 + arow; if (an >= N) an = N - 1;
    const float* Ab = g_aggH + (size_t)an * HID;
    auto ldA = [&](int c, float4 v[2]) {
        const float4* s4 = (const float4*)(Ab + c * 32 + akh);
        v[0] = s4[0]; v[1] = s4[1];
    };

    float acc[2][4][4];
    zero_acc(acc);
    // ---- u-layer GEMM: aggH @ V, K=128 ----
    GEMM_MAIN(ldA, vvh, vvl);

    // epilogue: + S + deg*vb + ub1, relu, split -> H tiles
    #pragma unroll
    for (int i = 0; i < 2; i++) {
        int r = wm*32 + i*16 + g;
        #pragma unroll
        for (int j = 0; j < 4; j++) {
            int c0 = wn*32 + j*8 + 2*t;
            int ci = wn*16 + j*4 + t;
            float2 bb = *(const float2*)(ub1 + c0);
            float2 vb = *(const float2*)(g_vb + c0);
            int na = n0 + r;     if (na >= N) na = N - 1;
            int nb = n0 + r + 8; if (nb >= N) nb = N - 1;
            float2 sa = *(const float2*)(g_S + (size_t)na * HID + c0);
            float2 sb = *(const float2*)(g_S + (size_t)nb * HID + c0);
            float da = g_deg[na], db = g_deg[nb];
            float a0 = fmaxf(acc[i][j][0] + sa.x + da*vb.x + bb.x, 0.f);
            float a1 = fmaxf(acc[i][j][1] + sa.y + da*vb.y + bb.y, 0.f);
            float a2 = fmaxf(acc[i][j][2] + sb.x + db*vb.x + bb.x, 0.f);
            float a3 = fmaxf(acc[i][j][3] + sb.y + db*vb.y + bb.y, 0.f);
            unsigned h, l;
            split2(a0, a1, h, l);
            sTh[r * SH_STR + ci] = h; sTl[r * SH_STR + ci] = l;
            split2(a2, a3, h, l);
            sTh[(r+8) * SH_STR + ci] = h; sTl[(r+8) * SH_STR + ci] = l;
        }
    }
    __syncthreads();

    // ---- upd GEMM: u @ U2, K=128, A = H tiles ----
    zero_acc(acc);
    stage_w(sBhB, u2h, 0, tid); stage_w(sBlB, u2l, 0, tid); __pipeline_commit();
    __pipeline_wait_prior(0);
    __syncthreads();
    stage_w(sBhB + 16*SB_STR, u2h, 1, tid); stage_w(sBlB + 16*SB_STR, u2l, 1, tid);
    __pipeline_commit();
    int b = 0;
    #pragma unroll 1
    for (int c = 0; c < 4; c++) {
        frag_compute(sTh + c*16, sTl + c*16, SH_STR,
                     sBhB + b*(16*SB_STR), sBlB + b*(16*SB_STR), g, t, wm, wn, acc);
        if (c == 3) break;
        __pipeline_wait_prior(0);
        __syncthreads();
        if (c + 2 < 4) {
            stage_w(sBhB + b*(16*SB_STR), u2h, c + 2, tid);
            stage_w(sBlB + b*(16*SB_STR), u2l, c + 2, tid);
            __pipeline_commit();
        }
        b ^= 1;
    }

    __syncthreads();
    float* sY = (float*)sTh;   // [64][132] floats

    #pragma unroll
    for (int i = 0; i < 2; i++) {
        int ra = wm*32 + i*16 + g;
        #pragma unroll
        for (int j = 0; j < 4; j++) {
            int c0 = wn*32 + j*8 + 2*t;
            float2 bb = *(const float2*)(ub2 + c0);
            int na = n0 + ra;     if (na >= N) na = N - 1;
            int nb = n0 + ra + 8; if (nb >= N) nb = N - 1;
            float2 xa = *(const float2*)(x + (size_t)na * HID + c0);
            float2 xb = *(const float2*)(x + (size_t)nb * HID + c0);
            sY[ra * 132 + c0]         = acc[i][j][0] + bb.x + xa.x;
            sY[ra * 132 + c0 + 1]     = acc[i][j][1] + bb.y + xa.y;
            sY[(ra+8) * 132 + c0]     = acc[i][j][2] + bb.x + xb.x;
            sY[(ra+8) * 132 + c0 + 1] = acc[i][j][3] + bb.y + xb.y;
        }
    }
    __syncthreads();

    {
        int r = tid >> 2, l4 = tid & 3;
        const float* row = sY + r * 132 + l4 * 32;
        float s = 0.f;
        #pragma unroll
        for (int c = 0; c < 32; c++) s += row[c];
        s += __shfl_xor_sync(0xffffffffu, s, 2);
        s += __shfl_xor_sync(0xffffffffu, s, 1);
        float mu = s * (1.f / 128.f);
        float ss = 0.f;
        #pragma unroll
        for (int c = 0; c < 32; c++) { float d = row[c] - mu; ss = fmaf(d, d, ss); }
        ss += __shfl_xor_sync(0xffffffffu, ss, 2);
        ss += __shfl_xor_sync(0xffffffffu, ss, 1);
        float rs = rsqrtf(ss * (1.f / 128.f) + LN_EPS);
        if (l4 == 0) { s_mu[r] = mu; s_rs[r] = rs; }
    }
    __syncthreads();

    {
        float4* out4 = (float4*)out;
        const float4* gm4 = (const float4*)gamma;
        const float4* bt4 = (const float4*)beta;
        for (int i = tid; i < BM * 32; i += 256) {
            int r = i >> 5, c4 = i & 31;
            if (n0 + r < N) {
                float4 v = ((const float4*)(sY + r * 132))[c4];
                float mu = s_mu[r], rs = s_rs[r];
                float4 gv = gm4[c4], bv = bt4[c4];
                v.x = fmaf((v.x - mu) * rs, gv.x, bv.x);
                v.y = fmaf((v.y - mu) * rs, gv.y, bv.y);
                v.z = fmaf((v.z - mu) * rs, gv.z, bv.z);
                v.w = fmaf((v.w - mu) * rs, gv.w, bv.w);
                out4[(size_t)(n0 + r) * 32 + c4] = v;
            }
        }
    }
}

extern "C" void kernel_launch(void* const* d_in, const int* in_sizes, int n_in,
                              void* d_out, int out_size) {
    const float* x     = (const float*)d_in[0];
    const void*  eidx  = d_in[1];
    const float* eattr = (const float*)d_in[2];
    const float* mW1 = (const float*)d_in[3];
    const float* mb1 = (const float*)d_in[4];
    const float* mW2 = (const float*)d_in[5];
    const float* mb2 = (const float*)d_in[6];
    const float* uW1 = (const float*)d_in[7];
    const float* ub1 = (const float*)d_in[8];
    const float* uW2 = (const float*)d_in[9];
    const float* ub2 = (const float*)d_in[10];
    const float* gamma = (const float*)d_in[11];
    const float* beta  = (const float*)d_in[12];
    float* out = (float*)d_out;

    const int N = in_sizes[0] / HID;   // 50000
    const int E = in_sizes[2] / HID;   // 640000

    cudaFuncSetAttribute(gemm128_kernel, cudaFuncAttributeMaxDynamicSharedMemorySize, GEMM_SMEM);
    cudaFuncSetAttribute(edge_fused,     cudaFuncAttributeMaxDynamicSharedMemorySize, EDGE_SMEM);
    cudaFuncSetAttribute(node_kernel,    cudaFuncAttributeMaxDynamicSharedMemorySize, NODE_SMEM);

    detect_kernel<<<1, 1>>>((const int*)eidx);
    compose_V<<<64, 256>>>(mW2, uW1, mb2);
    prepack_kernel<<<192, 256>>>(mW1, uW1, uW2);

    {
        float* aggp; cudaGetSymbolAddress((void**)&aggp, g_aggH);
        float* degp; cudaGetSymbolAddress((void**)&degp, g_deg);
        int a4 = MAXN * 32;
        zero_kernel<<<(a4 + 255) / 256, 256>>>(aggp, a4);
        int d4 = MAXN / 4;
        zero_kernel<<<(d4 + 255) / 256, 256>>>(degp, d4);
    }

    {
        float *Pp, *Qp, *Sp;
        cudaGetSymbolAddress((void**)&Pp, g_P);
        cudaGetSymbolAddress((void**)&Qp, g_Q);
        cudaGetSymbolAddress((void**)&Sp, g_S);
        unsigned *a_h, *a_l, *b_h, *b_l, *s_h, *s_l;
        cudaGetSymbolAddress((void**)&a_h, m1a_h); cudaGetSymbolAddress((void**)&a_l, m1a_l);
        cudaGetSymbolAddress((void**)&b_h, m1b_h); cudaGetSymbolAddress((void**)&b_l, m1b_l);
        cudaGetSymbolAddress((void**)&s_h, u1a_h); cudaGetSymbolAddress((void**)&s_l, u1a_l);
        gemm128_kernel<<<(N + BM - 1) / BM, 256, GEMM_SMEM>>>(x, a_h, a_l, Pp, N);
        gemm128_kernel<<<(N + BM - 1) / BM, 256, GEMM_SMEM>>>(x, b_h, b_l, Qp, N);
        gemm128_kernel<<<(N + BM - 1) / BM, 256, GEMM_SMEM>>>(x, s_h, s_l, Sp, N);
    }

    edge_fused<<<(E + BM - 1) / BM, 256, EDGE_SMEM>>>(eattr, eidx, mb1, E);

    node_kernel<<<(N + BM - 1) / BM, 256, NODE_SMEM>>>(x, ub1, ub2,
                                                       gamma, beta, out, N);
}

// round 13
// speedup vs baseline: 8.3073x; 1.1244x over previous
#include <cuda_runtime.h>
#include <cuda_pipeline.h>

#define HID 128
#define MAXN 50048
#define LN_EPS 1e-5f

#define BM 64
#define SA_STR 20      // uint32 stride per A row (16 + 4 pad)
#define SB_STR 132     // uint32 stride per B k2-row (128 + 4 pad)
#define SH_STR 68      // uint32 stride per H row (64 + 4 pad)

// smem layout (uint32 units)
#define OFF_AH 0
#define OFF_AL (OFF_AH + 2*BM*SA_STR)   // 2560
#define OFF_BH (OFF_AL + 2*BM*SA_STR)   // 5120
#define OFF_BL (OFF_BH + 2*16*SB_STR)   // 9344
#define OFF_HH (OFF_BL + 2*16*SB_STR)   // 13568
#define OFF_HL (OFF_HH + BM*SH_STR)     // 17920
#define OFF_IX (OFF_HL + BM*SH_STR)     // 22272
#define SMEM_U (OFF_IX + 2*BM)          // 22400
#define NODE_SMEM (SMEM_U * 4)          // 89600
#define GEMM_SMEM (OFF_HH * 4)          // 54272
// edge kernel: GEMM region + fp32 sY[64][132] + idx
#define E_OFF_Y  OFF_HH                  // 13568
#define E_OFF_IX (E_OFF_Y + BM*132)      // 22016
#define EDGE_SMEM ((E_OFF_IX + 2*BM) * 4) // 88576

// scratch (static device memory)
__device__ __align__(256) float g_P[(size_t)MAXN * HID];
__device__ __align__(256) float g_Q[(size_t)MAXN * HID];
__device__ __align__(256) float g_aggH[(size_t)MAXN * HID];
__device__ __align__(256) float g_deg[MAXN];
__device__ __align__(256) float g_V[128*128];
__device__ __align__(256) float g_vb[128];
__device__ int g_idx64;

// prepacked bf16x2 (hi,lo) weights, k-pair packed [k2][n]
__device__ __align__(16) unsigned m1a_h[64*128], m1a_l[64*128];
__device__ __align__(16) unsigned m1b_h[64*128], m1b_l[64*128];
__device__ __align__(16) unsigned m1c_h[64*128], m1c_l[64*128];
__device__ __align__(16) unsigned u1a_h[64*128], u1a_l[64*128];
__device__ __align__(16) unsigned vvh [64*128], vvl [64*128];
__device__ __align__(16) unsigned u2h [64*128], u2l [64*128];

__global__ void detect_kernel(const int* __restrict__ ei) {
    g_idx64 = (ei[1] == 0 && ei[3] == 0 && ei[5] == 0 && ei[7] == 0) ? 1 : 0;
}

__global__ void zero_kernel(float* __restrict__ p, int n4) {
    int i = blockIdx.x * blockDim.x + threadIdx.x;
    if (i < n4) ((float4*)p)[i] = make_float4(0.f, 0.f, 0.f, 0.f);
}

// V = W2 @ U1b  (U1b = rows 128..255 of uW1); vb = b2 @ U1b
__global__ void compose_V(const float* __restrict__ mW2, const float* __restrict__ uW1,
                          const float* __restrict__ b2) {
    int i = blockIdx.x * 256 + threadIdx.x;
    if (i >= 16384) return;
    int r = i >> 7, j = i & 127;
    float s = 0.f;
    #pragma unroll 4
    for (int k = 0; k < 128; k++)
        s = fmaf(mW2[r * 128 + k], uW1[(size_t)(128 + k) * 128 + j], s);
    g_V[i] = s;
    if (i < 128) {
        float vb = 0.f;
        #pragma unroll 4
        for (int k = 0; k < 128; k++)
            vb = fmaf(b2[k], uW1[(size_t)(128 + k) * 128 + i], vb);
        g_vb[i] = vb;
    }
}

// split pair of fp32 -> packed bf16x2 hi + lo (low16 = first arg)
__device__ __forceinline__ void split2(float a, float b, unsigned& h, unsigned& l) {
    unsigned hp;
    asm("cvt.rn.satfinite.bf16x2.f32 %0, %1, %2;" : "=r"(hp) : "f"(b), "f"(a));
    float fa = __uint_as_float(hp << 16);
    float fb = __uint_as_float(hp & 0xffff0000u);
    float la = a - fa, lb = b - fb;
    unsigned lp;
    asm("cvt.rn.satfinite.bf16x2.f32 %0, %1, %2;" : "=r"(lp) : "f"(lb), "f"(la));
    h = hp; l = lp;
}

__global__ void prepack_kernel(const float* __restrict__ mW1,
                               const float* __restrict__ uW1,
                               const float* __restrict__ uW2) {
    int i = blockIdx.x * 256 + threadIdx.x;
    const float* W; unsigned *H, *L; int off, koff = 0;
    if (i < 8192)       { W = mW1; H = m1a_h; L = m1a_l; off = i; }
    else if (i < 16384) { W = mW1; H = m1b_h; L = m1b_l; off = i - 8192;  koff = 128; }
    else if (i < 24576) { W = mW1; H = m1c_h; L = m1c_l; off = i - 16384; koff = 256; }
    else if (i < 32768) { W = uW1; H = u1a_h; L = u1a_l; off = i - 24576; }
    else if (i < 40960) { W = g_V; H = vvh;   L = vvl;   off = i - 32768; }
    else if (i < 49152) { W = uW2; H = u2h;   L = u2l;   off = i - 40960; }
    else return;
    int k2 = off >> 7, n = off & 127;
    float v0 = W[(size_t)(koff + 2*k2) * 128 + n];
    float v1 = W[(size_t)(koff + 2*k2 + 1) * 128 + n];
    unsigned h, l; split2(v0, v1, h, l);
    H[off] = h; L[off] = l;
}

__device__ __forceinline__ void mma16(float d[4], const unsigned a[4], const unsigned b[2]) {
    asm volatile(
        "mma.sync.aligned.m16n8k16.row.col.f32.bf16.bf16.f32 "
        "{%0,%1,%2,%3}, {%4,%5,%6,%7}, {%8,%9}, {%0,%1,%2,%3};\n"
        : "+f"(d[0]), "+f"(d[1]), "+f"(d[2]), "+f"(d[3])
        : "r"(a[0]), "r"(a[1]), "r"(a[2]), "r"(a[3]), "r"(b[0]), "r"(b[1]));
}

__device__ __forceinline__ void red4(float* p, float4 v) {
    asm volatile("red.global.add.v4.f32 [%0], {%1, %2, %3, %4};"
                 :: "l"(p), "f"(v.x), "f"(v.y), "f"(v.z), "f"(v.w) : "memory");
}

// one K=32 chunk: acc += A(64x32) * B(32x128), 3-term bf16 split
__device__ __forceinline__ void frag_compute(
    const unsigned* __restrict__ Ah, const unsigned* __restrict__ Al, int astr,
    const unsigned* __restrict__ Bh, const unsigned* __restrict__ Bl,
    int g, int t, int wm, int wn, float acc[2][4][4])
{
    #pragma unroll
    for (int ks = 0; ks < 2; ks++) {
        unsigned ah[2][4], al[2][4];
        #pragma unroll
        for (int i = 0; i < 2; i++) {
            const unsigned* p = Ah + (wm*32 + i*16 + g) * astr + ks*8 + t;
            ah[i][0] = p[0]; ah[i][1] = p[8*astr]; ah[i][2] = p[4]; ah[i][3] = p[8*astr + 4];
            const unsigned* q = Al + (wm*32 + i*16 + g) * astr + ks*8 + t;
            al[i][0] = q[0]; al[i][1] = q[8*astr]; al[i][2] = q[4]; al[i][3] = q[8*astr + 4];
        }
        unsigned bh[4][2], bl[4][2];
        #pragma unroll
        for (int j = 0; j < 4; j++) {
            const unsigned* p = Bh + (ks*8 + t) * SB_STR + wn*32 + j*8 + g;
            bh[j][0] = p[0]; bh[j][1] = p[4*SB_STR];
            const unsigned* q = Bl + (ks*8 + t) * SB_STR + wn*32 + j*8 + g;
            bl[j][0] = q[0]; bl[j][1] = q[4*SB_STR];
        }
        #pragma unroll
        for (int i = 0; i < 2; i++)
            #pragma unroll
            for (int j = 0; j < 4; j++) {
                mma16(acc[i][j], ah[i], bh[j]);
                mma16(acc[i][j], al[i], bh[j]);
                mma16(acc[i][j], ah[i], bl[j]);
            }
    }
}

__device__ __forceinline__ void stage_w(unsigned* dst, const unsigned* src, int c, int tid) {
    #pragma unroll
    for (int i = tid; i < 512; i += 256) {
        int r = i >> 5, q = (i & 31) * 4;
        __pipeline_memcpy_async(dst + r * SB_STR + q, src + (size_t)(c*16 + r) * 128 + q, 16);
    }
}

__device__ __forceinline__ void stA(unsigned* sAh, unsigned* sAl, int tid, const float4 v[2]) {
    int row = tid >> 2, quad = tid & 3;
    unsigned* dh = sAh + row * SA_STR + quad * 4;
    unsigned* dl = sAl + row * SA_STR + quad * 4;
    #pragma unroll
    for (int q = 0; q < 2; q++) {
        unsigned h0, l0, h1, l1;
        split2(v[q].x, v[q].y, h0, l0);
        split2(v[q].z, v[q].w, h1, l1);
        dh[2*q] = h0; dh[2*q+1] = h1;
        dl[2*q] = l0; dl[2*q+1] = l1;
    }
}

__device__ __forceinline__ void zero_acc(float acc[2][4][4]) {
    #pragma unroll
    for (int i = 0; i < 2; i++)
        #pragma unroll
        for (int j = 0; j < 4; j++)
            #pragma unroll
            for (int r = 0; r < 4; r++) acc[i][j][r] = 0.f;
}

// K=128 GEMM mainloop over A staged from gmem (4 chunks, double-buffered).
// Accumulates into existing acc.
#define GEMM_MAIN(ldA_expr, Wh, Wl) do { \
    float4 av[2]; \
    ldA_expr(0, av); \
    stage_w(sBhB, Wh, 0, tid); stage_w(sBlB, Wl, 0, tid); __pipeline_commit(); \
    stA(sAhB, sAlB, tid, av); \
    ldA_expr(1, av); \
    __pipeline_wait_prior(0); \
    __syncthreads(); \
    stage_w(sBhB + 16*SB_STR, Wh, 1, tid); stage_w(sBlB + 16*SB_STR, Wl, 1, tid); \
    __pipeline_commit(); \
    int b = 0; \
    _Pragma("unroll 1") \
    for (int c = 0; c < 4; c++) { \
        frag_compute(sAhB + b*(BM*SA_STR), sAlB + b*(BM*SA_STR), SA_STR, \
                     sBhB + b*(16*SB_STR), sBlB + b*(16*SB_STR), g, t, wm, wn, acc); \
        if (c == 3) break; \
        stA(sAhB + (b^1)*(BM*SA_STR), sAlB + (b^1)*(BM*SA_STR), tid, av); \
        if (c + 2 < 4) ldA_expr(c + 2, av); \
        __pipeline_wait_prior(0); \
        __syncthreads(); \
        if (c + 2 < 4) { \
            stage_w(sBhB + b*(16*SB_STR), Wh, c + 2, tid); \
            stage_w(sBlB + b*(16*SB_STR), Wl, c + 2, tid); \
            __pipeline_commit(); \
        } \
        b ^= 1; \
    } \
    __syncthreads(); \
} while (0)

// ---------------------------------------------------------------------------
// Dense GEMM: C[rows x 128] = A[rows x 128] @ W. 64 rows/CTA.
// ---------------------------------------------------------------------------
__global__ __launch_bounds__(256, 2)
void gemm128_kernel(const float* __restrict__ A,
                    const unsigned* __restrict__ Wh, const unsigned* __restrict__ Wl,
                    float* __restrict__ C, int rows)
{
    extern __shared__ unsigned smu[];
    unsigned* sAhB = smu + OFF_AH;
    unsigned* sAlB = smu + OFF_AL;
    unsigned* sBhB = smu + OFF_BH;
    unsigned* sBlB = smu + OFF_BL;

    const int tid = threadIdx.x;
    const int n0 = blockIdx.x * BM;
    const int lane = tid & 31, wid = tid >> 5;
    const int wm = wid >> 2, wn = wid & 3, g = lane >> 2, t = lane & 3;

    const int arow = tid >> 2, akh = (tid & 3) * 8;
    int ar = n0 + arow; if (ar >= rows) ar = rows - 1;
    const float* Ab = A + (size_t)ar * HID;
    auto ldA = [&](int c, float4 v[2]) {
        const float4* s4 = (const float4*)(Ab + c * 32 + akh);
        v[0] = s4[0]; v[1] = s4[1];
    };

    float acc[2][4][4];
    zero_acc(acc);
    GEMM_MAIN(ldA, Wh, Wl);

    #pragma unroll
    for (int i = 0; i < 2; i++) {
        int ra = wm*32 + i*16 + g;
        #pragma unroll
        for (int j = 0; j < 4; j++) {
            int c0 = wn*32 + j*8 + 2*t;
            int na = n0 + ra, nb = na + 8;
            if (na < rows)
                *(float2*)(C + (size_t)na * HID + c0) = make_float2(acc[i][j][0], acc[i][j][1]);
            if (nb < rows)
                *(float2*)(C + (size_t)nb * HID + c0) = make_float2(acc[i][j][2], acc[i][j][3]);
        }
    }
}

// ---------------------------------------------------------------------------
// Fused edge kernel: R = eattr@W1c (in-register), then per-row coalesced:
// h = relu(R + P[src] + Q[dst] + b1); aggH[dst] += h (red.v4); deg[dst] += 1
// ---------------------------------------------------------------------------
__global__ __launch_bounds__(256, 2)
void edge_fused(const float* __restrict__ eattr, const void* __restrict__ eidx,
                const float* __restrict__ b1, int E)
{
    extern __shared__ unsigned smu[];
    unsigned* sAhB = smu + OFF_AH;
    unsigned* sAlB = smu + OFF_AL;
    unsigned* sBhB = smu + OFF_BH;
    unsigned* sBlB = smu + OFF_BL;
    float* sY = (float*)(smu + E_OFF_Y);        // [64][132]
    int* s_src = (int*)(smu + E_OFF_IX);
    int* s_dst = s_src + BM;

    const int tid = threadIdx.x;
    const int e0 = blockIdx.x * BM;
    const int lane = tid & 31, wid = tid >> 5;
    const int wm = wid >> 2, wn = wid & 3, g = lane >> 2, t = lane & 3;

    if (tid < BM) {
        int e = e0 + tid; if (e >= E) e = E - 1;
        int s, d;
        if (g_idx64) {
            s = (int)((const long long*)eidx)[e];
            d = (int)((const long long*)eidx)[(size_t)E + e];
        } else {
            s = ((const int*)eidx)[e];
            d = ((const int*)eidx)[(size_t)E + e];
        }
        s_src[tid] = s; s_dst[tid] = d;
    }
    __syncthreads();

    const int arow = tid >> 2, akh = (tid & 3) * 8;
    int ar = e0 + arow; if (ar >= E) ar = E - 1;
    const float* Ab = eattr + (size_t)ar * HID;
    auto ldA = [&](int c, float4 v[2]) {
        const float4* s4 = (const float4*)(Ab + c * 32 + akh);
        v[0] = s4[0]; v[1] = s4[1];
    };

    float acc[2][4][4];
    zero_acc(acc);
    GEMM_MAIN(ldA, m1c_h, m1c_l);

    // acc -> sY (fp32)
    #pragma unroll
    for (int i = 0; i < 2; i++) {
        int ra = wm*32 + i*16 + g;
        #pragma unroll
        for (int j = 0; j < 4; j++) {
            int c0 = wn*32 + j*8 + 2*t;
            *(float2*)(sY + ra * 132 + c0)     = make_float2(acc[i][j][0], acc[i][j][1]);
            *(float2*)(sY + (ra+8) * 132 + c0) = make_float2(acc[i][j][2], acc[i][j][3]);
        }
    }
    __syncthreads();

    // coalesced epilogue: one warp per row, 8 rows per warp
    float4 bb = __ldg(((const float4*)b1) + lane);
    #pragma unroll 1
    for (int rr = 0; rr < 8; rr++) {
        int r = wid * 8 + rr;
        if (e0 + r >= E) break;
        int s = s_src[r], d = s_dst[r];
        float4 pv = ((const float4*)(g_P + (size_t)s * HID))[lane];
        float4 qv = ((const float4*)(g_Q + (size_t)d * HID))[lane];
        float4 yv = ((const float4*)(sY + r * 132))[lane];
        float4 h;
        h.x = fmaxf(yv.x + pv.x + qv.x + bb.x, 0.f);
        h.y = fmaxf(yv.y + pv.y + qv.y + bb.y, 0.f);
        h.z = fmaxf(yv.z + pv.z + qv.z + bb.z, 0.f);
        h.w = fmaxf(yv.w + pv.w + qv.w + bb.w, 0.f);
        red4(g_aggH + (size_t)d * HID + lane * 4, h);
        if (lane == 0)
            asm volatile("red.global.add.f32 [%0], %1;" :: "l"(g_deg + d), "f"(1.0f) : "memory");
    }
}

// ---------------------------------------------------------------------------
// Node kernel: u = relu(aggH@V + x@U1a + deg*vb + ub1); upd = u@U2 + ub2;
// out = LN(x + upd)
// ---------------------------------------------------------------------------
__global__ __launch_bounds__(256, 2)
void node_kernel(const float* __restrict__ x,
                 const float* __restrict__ ub1, const float* __restrict__ ub2,
                 const float* __restrict__ gamma, const float* __restrict__ beta,
                 float* __restrict__ out, int N)
{
    extern __shared__ unsigned smu[];
    unsigned* sAhB = smu + OFF_AH;
    unsigned* sAlB = smu + OFF_AL;
    unsigned* sBhB = smu + OFF_BH;
    unsigned* sBlB = smu + OFF_BL;
    unsigned* sTh  = smu + OFF_HH;
    unsigned* sTl  = smu + OFF_HL;
    float* s_mu = (float*)(smu + OFF_IX);
    float* s_rs = s_mu + BM;

    const int tid = threadIdx.x;
    const int n0 = blockIdx.x * BM;
    const int lane = tid & 31, wid = tid >> 5;
    const int wm = wid >> 2, wn = wid & 3, g = lane >> 2, t = lane & 3;

    const int arow = tid >> 2, akh = (tid & 3) * 8;
    int an = n0 + arow; if (an >= N) an = N - 1;
    const float* Ab_agg = g_aggH + (size_t)an * HID;
    const float* Ab_x   = x      + (size_t)an * HID;
    auto ldAagg = [&](int c, float4 v[2]) {
        const float4* s4 = (const float4*)(Ab_agg + c * 32 + akh);
        v[0] = s4[0]; v[1] = s4[1];
    };
    auto ldAx = [&](int c, float4 v[2]) {
        const float4* s4 = (const float4*)(Ab_x + c * 32 + akh);
        v[0] = s4[0]; v[1] = s4[1];
    };

    float acc[2][4][4];
    zero_acc(acc);
    GEMM_MAIN(ldAagg, vvh, vvl);     // acc  = aggH @ V
    GEMM_MAIN(ldAx,   u1a_h, u1a_l); // acc += x @ U1a

    // epilogue: + deg*vb + ub1, relu, split -> H tiles
    #pragma unroll
    for (int i = 0; i < 2; i++) {
        int r = wm*32 + i*16 + g;
        #pragma unroll
        for (int j = 0; j < 4; j++) {
            int c0 = wn*32 + j*8 + 2*t;
            int ci = wn*16 + j*4 + t;
            float2 bb = *(const float2*)(ub1 + c0);
            float2 vb = *(const float2*)(g_vb + c0);
            int na = n0 + r;     if (na >= N) na = N - 1;
            int nb = n0 + r + 8; if (nb >= N) nb = N - 1;
            float da = g_deg[na], db = g_deg[nb];
            float a0 = fmaxf(acc[i][j][0] + da*vb.x + bb.x, 0.f);
            float a1 = fmaxf(acc[i][j][1] + da*vb.y + bb.y, 0.f);
            float a2 = fmaxf(acc[i][j][2] + db*vb.x + bb.x, 0.f);
            float a3 = fmaxf(acc[i][j][3] + db*vb.y + bb.y, 0.f);
            unsigned h, l;
            split2(a0, a1, h, l);
            sTh[r * SH_STR + ci] = h; sTl[r * SH_STR + ci] = l;
            split2(a2, a3, h, l);
            sTh[(r+8) * SH_STR + ci] = h; sTl[(r+8) * SH_STR + ci] = l;
        }
    }
    __syncthreads();

    // ---- upd GEMM: u @ U2, K=128, A = H tiles ----
    zero_acc(acc);
    stage_w(sBhB, u2h, 0, tid); stage_w(sBlB, u2l, 0, tid); __pipeline_commit();
    __pipeline_wait_prior(0);
    __syncthreads();
    stage_w(sBhB + 16*SB_STR, u2h, 1, tid); stage_w(sBlB + 16*SB_STR, u2l, 1, tid);
    __pipeline_commit();
    int b = 0;
    #pragma unroll 1
    for (int c = 0; c < 4; c++) {
        frag_compute(sTh + c*16, sTl + c*16, SH_STR,
                     sBhB + b*(16*SB_STR), sBlB + b*(16*SB_STR), g, t, wm, wn, acc);
        if (c == 3) break;
        __pipeline_wait_prior(0);
        __syncthreads();
        if (c + 2 < 4) {
            stage_w(sBhB + b*(16*SB_STR), u2h, c + 2, tid);
            stage_w(sBlB + b*(16*SB_STR), u2l, c + 2, tid);
            __pipeline_commit();
        }
        b ^= 1;
    }

    __syncthreads();
    float* sY = (float*)sTh;   // [64][132] floats

    #pragma unroll
    for (int i = 0; i < 2; i++) {
        int ra = wm*32 + i*16 + g;
        #pragma unroll
        for (int j = 0; j < 4; j++) {
            int c0 = wn*32 + j*8 + 2*t;
            float2 bb = *(const float2*)(ub2 + c0);
            int na = n0 + ra;     if (na >= N) na = N - 1;
            int nb = n0 + ra + 8; if (nb >= N) nb = N - 1;
            float2 xa = *(const float2*)(x + (size_t)na * HID + c0);
            float2 xb = *(const float2*)(x + (size_t)nb * HID + c0);
            sY[ra * 132 + c0]         = acc[i][j][0] + bb.x + xa.x;
            sY[ra * 132 + c0 + 1]     = acc[i][j][1] + bb.y + xa.y;
            sY[(ra+8) * 132 + c0]     = acc[i][j][2] + bb.x + xb.x;
            sY[(ra+8) * 132 + c0 + 1] = acc[i][j][3] + bb.y + xb.y;
        }
    }
    __syncthreads();

    {
        int r = tid >> 2, l4 = tid & 3;
        const float* row = sY + r * 132 + l4 * 32;
        float s = 0.f;
        #pragma unroll
        for (int c = 0; c < 32; c++) s += row[c];
        s += __shfl_xor_sync(0xffffffffu, s, 2);
        s += __shfl_xor_sync(0xffffffffu, s, 1);
        float mu = s * (1.f / 128.f);
        float ss = 0.f;
        #pragma unroll
        for (int c = 0; c < 32; c++) { float d = row[c] - mu; ss = fmaf(d, d, ss); }
        ss += __shfl_xor_sync(0xffffffffu, ss, 2);
        ss += __shfl_xor_sync(0xffffffffu, ss, 1);
        float rs = rsqrtf(ss * (1.f / 128.f) + LN_EPS);
        if (l4 == 0) { s_mu[r] = mu; s_rs[r] = rs; }
    }
    __syncthreads();

    {
        float4* out4 = (float4*)out;
        const float4* gm4 = (const float4*)gamma;
        const float4* bt4 = (const float4*)beta;
        for (int i = tid; i < BM * 32; i += 256) {
            int r = i >> 5, c4 = i & 31;
            if (n0 + r < N) {
                float4 v = ((const float4*)(sY + r * 132))[c4];
                float mu = s_mu[r], rs = s_rs[r];
                float4 gv = gm4[c4], bv = bt4[c4];
                v.x = fmaf((v.x - mu) * rs, gv.x, bv.x);
                v.y = fmaf((v.y - mu) * rs, gv.y, bv.y);
                v.z = fmaf((v.z - mu) * rs, gv.z, bv.z);
                v.w = fmaf((v.w - mu) * rs, gv.w, bv.w);
                out4[(size_t)(n0 + r) * 32 + c4] = v;
            }
        }
    }
}

extern "C" void kernel_launch(void* const* d_in, const int* in_sizes, int n_in,
                              void* d_out, int out_size) {
    const float* x     = (const float*)d_in[0];
    const void*  eidx  = d_in[1];
    const float* eattr = (const float*)d_in[2];
    const float* mW1 = (const float*)d_in[3];
    const float* mb1 = (const float*)d_in[4];
    const float* mW2 = (const float*)d_in[5];
    const float* mb2 = (const float*)d_in[6];
    const float* uW1 = (const float*)d_in[7];
    const float* ub1 = (const float*)d_in[8];
    const float* uW2 = (const float*)d_in[9];
    const float* ub2 = (const float*)d_in[10];
    const float* gamma = (const float*)d_in[11];
    const float* beta  = (const float*)d_in[12];
    float* out = (float*)d_out;

    const int N = in_sizes[0] / HID;   // 50000
    const int E = in_sizes[2] / HID;   // 640000

    cudaFuncSetAttribute(gemm128_kernel, cudaFuncAttributeMaxDynamicSharedMemorySize, GEMM_SMEM);
    cudaFuncSetAttribute(edge_fused,     cudaFuncAttributeMaxDynamicSharedMemorySize, EDGE_SMEM);
    cudaFuncSetAttribute(node_kernel,    cudaFuncAttributeMaxDynamicSharedMemorySize, NODE_SMEM);

    detect_kernel<<<1, 1>>>((const int*)eidx);
    compose_V<<<64, 256>>>(mW2, uW1, mb2);
    prepack_kernel<<<192, 256>>>(mW1, uW1, uW2);

    {
        float* aggp; cudaGetSymbolAddress((void**)&aggp, g_aggH);
        float* degp; cudaGetSymbolAddress((void**)&degp, g_deg);
        int a4 = MAXN * 32;
        zero_kernel<<<(a4 + 255) / 256, 256>>>(aggp, a4);
        int d4 = MAXN / 4;
        zero_kernel<<<(d4 + 255) / 256, 256>>>(degp, d4);
    }

    {
        float *Pp, *Qp;
        cudaGetSymbolAddress((void**)&Pp, g_P);
        cudaGetSymbolAddress((void**)&Qp, g_Q);
        unsigned *a_h, *a_l, *b_h, *b_l;
        cudaGetSymbolAddress((void**)&a_h, m1a_h); cudaGetSymbolAddress((void**)&a_l, m1a_l);
        cudaGetSymbolAddress((void**)&b_h, m1b_h); cudaGetSymbolAddress((void**)&b_l, m1b_l);
        gemm128_kernel<<<(N + BM - 1) / BM, 256, GEMM_SMEM>>>(x, a_h, a_l, Pp, N);
        gemm128_kernel<<<(N + BM - 1) / BM, 256, GEMM_SMEM>>>(x, b_h, b_l, Qp, N);
    }

    edge_fused<<<(E + BM - 1) / BM, 256, EDGE_SMEM>>>(eattr, eidx, mb1, E);

    node_kernel<<<(N + BM - 1) / BM, 256, NODE_SMEM>>>(x, ub1, ub2,
                                                       gamma, beta, out, N);
}

// round 14
// speedup vs baseline: 8.3467x; 1.0047x over previous
#include <cuda_runtime.h>
#include <cuda_pipeline.h>

#define HID 128
#define MAXN 50048
#define LN_EPS 1e-5f

#define BM 64
#define SA_STR 20      // uint32 stride per A row (16 + 4 pad)  [node/gemm kernels]
#define SB_STR 132     // uint32 stride per B k2-row (128 + 4 pad)
#define SH_STR 68      // uint32 stride per H row (64 + 4 pad)

// node/gemm smem layout (uint32 units)
#define OFF_AH 0
#define OFF_AL (OFF_AH + 2*BM*SA_STR)   // 2560
#define OFF_BH (OFF_AL + 2*BM*SA_STR)   // 5120
#define OFF_BL (OFF_BH + 2*16*SB_STR)   // 9344
#define OFF_HH (OFF_BL + 2*16*SB_STR)   // 13568
#define OFF_HL (OFF_HH + BM*SH_STR)     // 17920
#define OFF_IX (OFF_HL + BM*SH_STR)     // 22272
#define SMEM_U (OFF_IX + 2*BM)          // 22400
#define NODE_SMEM (SMEM_U * 4)          // 89600
#define GEMM_SMEM (OFF_HH * 4)          // 54272

// persistent edge kernel smem layout (uint32 units)
//   B resident: hi 64xSB_STR, lo 64xSB_STR
//   A tile: hi 64xSH_STR, lo 64xSH_STR  (sY fp32 [64][132] overlays A)
//   idx: 2 buffers x 128
#define E_BH 0
#define E_BL (E_BH + 64*SB_STR)          // 8448
#define E_A  (E_BL + 64*SB_STR)          // 16896
#define E_AL (E_A + 64*SH_STR)           // 21248
#define E_IX (E_AL + 64*SH_STR)          // 25600
#define E_U  (E_IX + 256)                // 25856
#define EDGE_SMEM (E_U * 4)              // 103424

// scratch (static device memory)
__device__ __align__(256) float g_P[(size_t)MAXN * HID];
__device__ __align__(256) float g_Q[(size_t)MAXN * HID];
__device__ __align__(256) float g_aggH[(size_t)MAXN * HID];
__device__ __align__(256) float g_deg[MAXN];
__device__ __align__(256) float g_V[128*128];
__device__ __align__(256) float g_vb[128];
__device__ int g_idx64;

// prepacked bf16x2 (hi,lo) weights, k-pair packed [k2][n]
__device__ __align__(16) unsigned m1a_h[64*128], m1a_l[64*128];
__device__ __align__(16) unsigned m1b_h[64*128], m1b_l[64*128];
__device__ __align__(16) unsigned m1c_h[64*128], m1c_l[64*128];
__device__ __align__(16) unsigned u1a_h[64*128], u1a_l[64*128];
__device__ __align__(16) unsigned vvh [64*128], vvl [64*128];
__device__ __align__(16) unsigned u2h [64*128], u2l [64*128];

__global__ void detect_kernel(const int* __restrict__ ei) {
    g_idx64 = (ei[1] == 0 && ei[3] == 0 && ei[5] == 0 && ei[7] == 0) ? 1 : 0;
}

__global__ void zero_kernel(float* __restrict__ p, int n4) {
    int i = blockIdx.x * blockDim.x + threadIdx.x;
    if (i < n4) ((float4*)p)[i] = make_float4(0.f, 0.f, 0.f, 0.f);
}

// V = W2 @ U1b  (U1b = rows 128..255 of uW1); vb = b2 @ U1b
__global__ void compose_V(const float* __restrict__ mW2, const float* __restrict__ uW1,
                          const float* __restrict__ b2) {
    int i = blockIdx.x * 256 + threadIdx.x;
    if (i >= 16384) return;
    int r = i >> 7, j = i & 127;
    float s = 0.f;
    #pragma unroll 4
    for (int k = 0; k < 128; k++)
        s = fmaf(mW2[r * 128 + k], uW1[(size_t)(128 + k) * 128 + j], s);
    g_V[i] = s;
    if (i < 128) {
        float vb = 0.f;
        #pragma unroll 4
        for (int k = 0; k < 128; k++)
            vb = fmaf(b2[k], uW1[(size_t)(128 + k) * 128 + i], vb);
        g_vb[i] = vb;
    }
}

// split pair of fp32 -> packed bf16x2 hi + lo (low16 = first arg)
__device__ __forceinline__ void split2(float a, float b, unsigned& h, unsigned& l) {
    unsigned hp;
    asm("cvt.rn.satfinite.bf16x2.f32 %0, %1, %2;" : "=r"(hp) : "f"(b), "f"(a));
    float fa = __uint_as_float(hp << 16);
    float fb = __uint_as_float(hp & 0xffff0000u);
    float la = a - fa, lb = b - fb;
    unsigned lp;
    asm("cvt.rn.satfinite.bf16x2.f32 %0, %1, %2;" : "=r"(lp) : "f"(lb), "f"(la));
    h = hp; l = lp;
}

__global__ void prepack_kernel(const float* __restrict__ mW1,
                               const float* __restrict__ uW1,
                               const float* __restrict__ uW2) {
    int i = blockIdx.x * 256 + threadIdx.x;
    const float* W; unsigned *H, *L; int off, koff = 0;
    if (i < 8192)       { W = mW1; H = m1a_h; L = m1a_l; off = i; }
    else if (i < 16384) { W = mW1; H = m1b_h; L = m1b_l; off = i - 8192;  koff = 128; }
    else if (i < 24576) { W = mW1; H = m1c_h; L = m1c_l; off = i - 16384; koff = 256; }
    else if (i < 32768) { W = uW1; H = u1a_h; L = u1a_l; off = i - 24576; }
    else if (i < 40960) { W = g_V; H = vvh;   L = vvl;   off = i - 32768; }
    else if (i < 49152) { W = uW2; H = u2h;   L = u2l;   off = i - 40960; }
    else return;
    int k2 = off >> 7, n = off & 127;
    float v0 = W[(size_t)(koff + 2*k2) * 128 + n];
    float v1 = W[(size_t)(koff + 2*k2 + 1) * 128 + n];
    unsigned h, l; split2(v0, v1, h, l);
    H[off] = h; L[off] = l;
}

__device__ __forceinline__ void mma16(float d[4], const unsigned a[4], const unsigned b[2]) {
    asm volatile(
        "mma.sync.aligned.m16n8k16.row.col.f32.bf16.bf16.f32 "
        "{%0,%1,%2,%3}, {%4,%5,%6,%7}, {%8,%9}, {%0,%1,%2,%3};\n"
        : "+f"(d[0]), "+f"(d[1]), "+f"(d[2]), "+f"(d[3])
        : "r"(a[0]), "r"(a[1]), "r"(a[2]), "r"(a[3]), "r"(b[0]), "r"(b[1]));
}

__device__ __forceinline__ void red4(float* p, float4 v) {
    asm volatile("red.global.add.v4.f32 [%0], {%1, %2, %3, %4};"
                 :: "l"(p), "f"(v.x), "f"(v.y), "f"(v.z), "f"(v.w) : "memory");
}

// one K=32 chunk: acc += A(64x32) * B(32x128), 3-term bf16 split
__device__ __forceinline__ void frag_compute(
    const unsigned* __restrict__ Ah, const unsigned* __restrict__ Al, int astr,
    const unsigned* __restrict__ Bh, const unsigned* __restrict__ Bl,
    int g, int t, int wm, int wn, float acc[2][4][4])
{
    #pragma unroll
    for (int ks = 0; ks < 2; ks++) {
        unsigned ah[2][4], al[2][4];
        #pragma unroll
        for (int i = 0; i < 2; i++) {
            const unsigned* p = Ah + (wm*32 + i*16 + g) * astr + ks*8 + t;
            ah[i][0] = p[0]; ah[i][1] = p[8*astr]; ah[i][2] = p[4]; ah[i][3] = p[8*astr + 4];
            const unsigned* q = Al + (wm*32 + i*16 + g) * astr + ks*8 + t;
            al[i][0] = q[0]; al[i][1] = q[8*astr]; al[i][2] = q[4]; al[i][3] = q[8*astr + 4];
        }
        unsigned bh[4][2], bl[4][2];
        #pragma unroll
        for (int j = 0; j < 4; j++) {
            const unsigned* p = Bh + (ks*8 + t) * SB_STR + wn*32 + j*8 + g;
            bh[j][0] = p[0]; bh[j][1] = p[4*SB_STR];
            const unsigned* q = Bl + (ks*8 + t) * SB_STR + wn*32 + j*8 + g;
            bl[j][0] = q[0]; bl[j][1] = q[4*SB_STR];
        }
        #pragma unroll
        for (int i = 0; i < 2; i++)
            #pragma unroll
            for (int j = 0; j < 4; j++) {
                mma16(acc[i][j], ah[i], bh[j]);
                mma16(acc[i][j], al[i], bh[j]);
                mma16(acc[i][j], ah[i], bl[j]);
            }
    }
}

__device__ __forceinline__ void stage_w(unsigned* dst, const unsigned* src, int c, int tid) {
    #pragma unroll
    for (int i = tid; i < 512; i += 256) {
        int r = i >> 5, q = (i & 31) * 4;
        __pipeline_memcpy_async(dst + r * SB_STR + q, src + (size_t)(c*16 + r) * 128 + q, 16);
    }
}

__device__ __forceinline__ void stA(unsigned* sAh, unsigned* sAl, int tid, const float4 v[2]) {
    int row = tid >> 2, quad = tid & 3;
    unsigned* dh = sAh + row * SA_STR + quad * 4;
    unsigned* dl = sAl + row * SA_STR + quad * 4;
    #pragma unroll
    for (int q = 0; q < 2; q++) {
        unsigned h0, l0, h1, l1;
        split2(v[q].x, v[q].y, h0, l0);
        split2(v[q].z, v[q].w, h1, l1);
        dh[2*q] = h0; dh[2*q+1] = h1;
        dl[2*q] = l0; dl[2*q+1] = l1;
    }
}

__device__ __forceinline__ void zero_acc(float acc[2][4][4]) {
    #pragma unroll
    for (int i = 0; i < 2; i++)
        #pragma unroll
        for (int j = 0; j < 4; j++)
            #pragma unroll
            for (int r = 0; r < 4; r++) acc[i][j][r] = 0.f;
}

// K=128 GEMM mainloop over A staged from gmem (4 chunks, double-buffered).
#define GEMM_MAIN(ldA_expr, Wh, Wl) do { \
    float4 av[2]; \
    ldA_expr(0, av); \
    stage_w(sBhB, Wh, 0, tid); stage_w(sBlB, Wl, 0, tid); __pipeline_commit(); \
    stA(sAhB, sAlB, tid, av); \
    ldA_expr(1, av); \
    __pipeline_wait_prior(0); \
    __syncthreads(); \
    stage_w(sBhB + 16*SB_STR, Wh, 1, tid); stage_w(sBlB + 16*SB_STR, Wl, 1, tid); \
    __pipeline_commit(); \
    int b = 0; \
    _Pragma("unroll 1") \
    for (int c = 0; c < 4; c++) { \
        frag_compute(sAhB + b*(BM*SA_STR), sAlB + b*(BM*SA_STR), SA_STR, \
                     sBhB + b*(16*SB_STR), sBlB + b*(16*SB_STR), g, t, wm, wn, acc); \
        if (c == 3) break; \
        stA(sAhB + (b^1)*(BM*SA_STR), sAlB + (b^1)*(BM*SA_STR), tid, av); \
        if (c + 2 < 4) ldA_expr(c + 2, av); \
        __pipeline_wait_prior(0); \
        __syncthreads(); \
        if (c + 2 < 4) { \
            stage_w(sBhB + b*(16*SB_STR), Wh, c + 2, tid); \
            stage_w(sBlB + b*(16*SB_STR), Wl, c + 2, tid); \
            __pipeline_commit(); \
        } \
        b ^= 1; \
    } \
    __syncthreads(); \
} while (0)

// ---------------------------------------------------------------------------
// Dense GEMM: C[rows x 128] = A[rows x 128] @ W. 64 rows/CTA.
// ---------------------------------------------------------------------------
__global__ __launch_bounds__(256, 2)
void gemm128_kernel(const float* __restrict__ A,
                    const unsigned* __restrict__ Wh, const unsigned* __restrict__ Wl,
                    float* __restrict__ C, int rows)
{
    extern __shared__ unsigned smu[];
    unsigned* sAhB = smu + OFF_AH;
    unsigned* sAlB = smu + OFF_AL;
    unsigned* sBhB = smu + OFF_BH;
    unsigned* sBlB = smu + OFF_BL;

    const int tid = threadIdx.x;
    const int n0 = blockIdx.x * BM;
    const int lane = tid & 31, wid = tid >> 5;
    const int wm = wid >> 2, wn = wid & 3, g = lane >> 2, t = lane & 3;

    const int arow = tid >> 2, akh = (tid & 3) * 8;
    int ar = n0 + arow; if (ar >= rows) ar = rows - 1;
    const float* Ab = A + (size_t)ar * HID;
    auto ldA = [&](int c, float4 v[2]) {
        const float4* s4 = (const float4*)(Ab + c * 32 + akh);
        v[0] = s4[0]; v[1] = s4[1];
    };

    float acc[2][4][4];
    zero_acc(acc);
    GEMM_MAIN(ldA, Wh, Wl);

    #pragma unroll
    for (int i = 0; i < 2; i++) {
        int ra = wm*32 + i*16 + g;
        #pragma unroll
        for (int j = 0; j < 4; j++) {
            int c0 = wn*32 + j*8 + 2*t;
            int na = n0 + ra, nb = na + 8;
            if (na < rows)
                *(float2*)(C + (size_t)na * HID + c0) = make_float2(acc[i][j][0], acc[i][j][1]);
            if (nb < rows)
                *(float2*)(C + (size_t)nb * HID + c0) = make_float2(acc[i][j][2], acc[i][j][3]);
        }
    }
}

// ---------------------------------------------------------------------------
// Persistent fused edge kernel: W1c resident in smem; per 64-edge tile:
//   R = eattr@W1c; h = relu(R + P[src] + Q[dst] + b1); red4 aggH[dst]; deg++
// ---------------------------------------------------------------------------
__global__ __launch_bounds__(256, 2)
void edge_fused(const float* __restrict__ eattr, const void* __restrict__ eidx,
                const float* __restrict__ b1, int E, int nTiles)
{
    extern __shared__ unsigned smu[];
    unsigned* sBh = smu + E_BH;
    unsigned* sBl = smu + E_BL;
    unsigned* sAh = smu + E_A;
    unsigned* sAl = smu + E_AL;
    float* sY = (float*)(smu + E_A);      // overlays A region after compute
    int* s_idx = (int*)(smu + E_IX);      // 2 buffers x (64 src + 64 dst)

    const int tid = threadIdx.x;
    const int lane = tid & 31, wid = tid >> 5;
    const int wm = wid >> 2, wn = wid & 3, g = lane >> 2, t = lane & 3;
    const int arow = tid >> 2;            // 0..63
    const int kq = tid & 3;               // quarter of K (32 fp32)

    // stage full W1c (hi+lo) once
    #pragma unroll 4
    for (int i = tid; i < 2048; i += 256) {
        int r = i >> 5, q = (i & 31) * 4;
        __pipeline_memcpy_async(sBh + r * SB_STR + q, m1c_h + (size_t)r * 128 + q, 16);
        __pipeline_memcpy_async(sBl + r * SB_STR + q, m1c_l + (size_t)r * 128 + q, 16);
    }
    __pipeline_commit();

    auto ld_idx = [&](int tile, int buf) {
        if (tid < 64) {
            int e = tile * 64 + tid; if (e >= E) e = E - 1;
            int s, d;
            if (g_idx64) {
                s = (int)((const long long*)eidx)[e];
                d = (int)((const long long*)eidx)[(size_t)E + e];
            } else {
                s = ((const int*)eidx)[e];
                d = ((const int*)eidx)[(size_t)E + e];
            }
            s_idx[buf * 128 + tid] = s;
            s_idx[buf * 128 + 64 + tid] = d;
        }
    };
    auto ld_A = [&](int tile, float4 v[8]) {
        int e = tile * 64 + arow; if (e >= E) e = E - 1;
        const float4* s4 = (const float4*)(eattr + (size_t)e * HID + kq * 32);
        #pragma unroll
        for (int i = 0; i < 8; i++) v[i] = s4[i];
    };

    float4 av[8];
    int tile0 = blockIdx.x;
    if (tile0 < nTiles) { ld_idx(tile0, 0); ld_A(tile0, av); }
    __pipeline_wait_prior(0);
    __syncthreads();

    const float4 bb = __ldg(((const float4*)b1) + lane);

    int pb = 0;
    #pragma unroll 1
    for (int tile = tile0; tile < nTiles; tile += gridDim.x) {
        // split + STS A (16 k-pairs per thread at kq*16)
        {
            unsigned* dh = sAh + arow * SH_STR + kq * 16;
            unsigned* dl = sAl + arow * SH_STR + kq * 16;
            #pragma unroll
            for (int q = 0; q < 4; q++) {
                unsigned h0, l0, h1, l1, h2, l2, h3, l3;
                split2(av[2*q].x,   av[2*q].y,   h0, l0);
                split2(av[2*q].z,   av[2*q].w,   h1, l1);
                split2(av[2*q+1].x, av[2*q+1].y, h2, l2);
                split2(av[2*q+1].z, av[2*q+1].w, h3, l3);
                *(uint4*)(dh + 4*q) = make_uint4(h0, h1, h2, h3);
                *(uint4*)(dl + 4*q) = make_uint4(l0, l1, l2, l3);
            }
        }
        __syncthreads();

        // all 4 K-chunks back-to-back, everything resident
        float acc[2][4][4];
        zero_acc(acc);
        #pragma unroll
        for (int c = 0; c < 4; c++)
            frag_compute(sAh + c*16, sAl + c*16, SH_STR,
                         sBh + c*16*SB_STR, sBl + c*16*SB_STR,
                         g, t, wm, wn, acc);
        __syncthreads();   // A dead

        // acc -> sY
        #pragma unroll
        for (int i = 0; i < 2; i++) {
            int ra = wm*32 + i*16 + g;
            #pragma unroll
            for (int j = 0; j < 4; j++) {
                int c0 = wn*32 + j*8 + 2*t;
                *(float2*)(sY + ra * 132 + c0)     = make_float2(acc[i][j][0], acc[i][j][1]);
                *(float2*)(sY + (ra+8) * 132 + c0) = make_float2(acc[i][j][2], acc[i][j][3]);
            }
        }

        // prefetch next tile (regs + other idx buffer)
        int ntile = tile + gridDim.x;
        if (ntile < nTiles) { ld_idx(ntile, pb ^ 1); ld_A(ntile, av); }
        __syncthreads();   // sY complete

        // coalesced epilogue: one warp per row, 8 rows per warp
        const int* sb = s_idx + pb * 128;
        int e0 = tile * 64;
        #pragma unroll 1
        for (int rr = 0; rr < 8; rr++) {
            int r = wid * 8 + rr;
            if (e0 + r >= E) break;
            int s = sb[r], d = sb[64 + r];
            float4 pv = ((const float4*)(g_P + (size_t)s * HID))[lane];
            float4 qv = ((const float4*)(g_Q + (size_t)d * HID))[lane];
            float4 yv = ((const float4*)(sY + r * 132))[lane];
            float4 h;
            h.x = fmaxf(yv.x + pv.x + qv.x + bb.x, 0.f);
            h.y = fmaxf(yv.y + pv.y + qv.y + bb.y, 0.f);
            h.z = fmaxf(yv.z + pv.z + qv.z + bb.z, 0.f);
            h.w = fmaxf(yv.w + pv.w + qv.w + bb.w, 0.f);
            red4(g_aggH + (size_t)d * HID + lane * 4, h);
            if (lane == 0)
                asm volatile("red.global.add.f32 [%0], %1;" :: "l"(g_deg + d), "f"(1.0f) : "memory");
        }
        __syncthreads();   // epilogue reads done before next STS overwrites sY/A
        pb ^= 1;
    }
}

// ---------------------------------------------------------------------------
// Node kernel: u = relu(aggH@V + x@U1a + deg*vb + ub1); upd = u@U2 + ub2;
// out = LN(x + upd)
// ---------------------------------------------------------------------------
__global__ __launch_bounds__(256, 2)
void node_kernel(const float* __restrict__ x,
                 const float* __restrict__ ub1, const float* __restrict__ ub2,
                 const float* __restrict__ gamma, const float* __restrict__ beta,
                 float* __restrict__ out, int N)
{
    extern __shared__ unsigned smu[];
    unsigned* sAhB = smu + OFF_AH;
    unsigned* sAlB = smu + OFF_AL;
    unsigned* sBhB = smu + OFF_BH;
    unsigned* sBlB = smu + OFF_BL;
    unsigned* sTh  = smu + OFF_HH;
    unsigned* sTl  = smu + OFF_HL;
    float* s_mu = (float*)(smu + OFF_IX);
    float* s_rs = s_mu + BM;

    const int tid = threadIdx.x;
    const int n0 = blockIdx.x * BM;
    const int lane = tid & 31, wid = tid >> 5;
    const int wm = wid >> 2, wn = wid & 3, g = lane >> 2, t = lane & 3;

    const int arow = tid >> 2, akh = (tid & 3) * 8;
    int an = n0 + arow; if (an >= N) an = N - 1;
    const float* Ab_agg = g_aggH + (size_t)an * HID;
    const float* Ab_x   = x      + (size_t)an * HID;
    auto ldAagg = [&](int c, float4 v[2]) {
        const float4* s4 = (const float4*)(Ab_agg + c * 32 + akh);
        v[0] = s4[0]; v[1] = s4[1];
    };
    auto ldAx = [&](int c, float4 v[2]) {
        const float4* s4 = (const float4*)(Ab_x + c * 32 + akh);
        v[0] = s4[0]; v[1] = s4[1];
    };

    float acc[2][4][4];
    zero_acc(acc);
    GEMM_MAIN(ldAagg, vvh, vvl);     // acc  = aggH @ V
    GEMM_MAIN(ldAx,   u1a_h, u1a_l); // acc += x @ U1a

    // epilogue: + deg*vb + ub1, relu, split -> H tiles
    #pragma unroll
    for (int i = 0; i < 2; i++) {
        int r = wm*32 + i*16 + g;
        #pragma unroll
        for (int j = 0; j < 4; j++) {
            int c0 = wn*32 + j*8 + 2*t;
            int ci = wn*16 + j*4 + t;
            float2 bb = *(const float2*)(ub1 + c0);
            float2 vb = *(const float2*)(g_vb + c0);
            int na = n0 + r;     if (na >= N) na = N - 1;
            int nb = n0 + r + 8; if (nb >= N) nb = N - 1;
            float da = g_deg[na], db = g_deg[nb];
            float a0 = fmaxf(acc[i][j][0] + da*vb.x + bb.x, 0.f);
            float a1 = fmaxf(acc[i][j][1] + da*vb.y + bb.y, 0.f);
            float a2 = fmaxf(acc[i][j][2] + db*vb.x + bb.x, 0.f);
            float a3 = fmaxf(acc[i][j][3] + db*vb.y + bb.y, 0.f);
            unsigned h, l;
            split2(a0, a1, h, l);
            sTh[r * SH_STR + ci] = h; sTl[r * SH_STR + ci] = l;
            split2(a2, a3, h, l);
            sTh[(r+8) * SH_STR + ci] = h; sTl[(r+8) * SH_STR + ci] = l;
        }
    }
    __syncthreads();

    // ---- upd GEMM: u @ U2, K=128, A = H tiles ----
    zero_acc(acc);
    stage_w(sBhB, u2h, 0, tid); stage_w(sBlB, u2l, 0, tid); __pipeline_commit();
    __pipeline_wait_prior(0);
    __syncthreads();
    stage_w(sBhB + 16*SB_STR, u2h, 1, tid); stage_w(sBlB + 16*SB_STR, u2l, 1, tid);
    __pipeline_commit();
    int b = 0;
    #pragma unroll 1
    for (int c = 0; c < 4; c++) {
        frag_compute(sTh + c*16, sTl + c*16, SH_STR,
                     sBhB + b*(16*SB_STR), sBlB + b*(16*SB_STR), g, t, wm, wn, acc);
        if (c == 3) break;
        __pipeline_wait_prior(0);
        __syncthreads();
        if (c + 2 < 4) {
            stage_w(sBhB + b*(16*SB_STR), u2h, c + 2, tid);
            stage_w(sBlB + b*(16*SB_STR), u2l, c + 2, tid);
            __pipeline_commit();
        }
        b ^= 1;
    }

    __syncthreads();
    float* sY = (float*)sTh;   // [64][132] floats

    #pragma unroll
    for (int i = 0; i < 2; i++) {
        int ra = wm*32 + i*16 + g;
        #pragma unroll
        for (int j = 0; j < 4; j++) {
            int c0 = wn*32 + j*8 + 2*t;
            float2 bb = *(const float2*)(ub2 + c0);
            int na = n0 + ra;     if (na >= N) na = N - 1;
            int nb = n0 + ra + 8; if (nb >= N) nb = N - 1;
            float2 xa = *(const float2*)(x + (size_t)na * HID + c0);
            float2 xb = *(const float2*)(x + (size_t)nb * HID + c0);
            sY[ra * 132 + c0]         = acc[i][j][0] + bb.x + xa.x;
            sY[ra * 132 + c0 + 1]     = acc[i][j][1] + bb.y + xa.y;
            sY[(ra+8) * 132 + c0]     = acc[i][j][2] + bb.x + xb.x;
            sY[(ra+8) * 132 + c0 + 1] = acc[i][j][3] + bb.y + xb.y;
        }
    }
    __syncthreads();

    {
        int r = tid >> 2, l4 = tid & 3;
        const float* row = sY + r * 132 + l4 * 32;
        float s = 0.f;
        #pragma unroll
        for (int c = 0; c < 32; c++) s += row[c];
        s += __shfl_xor_sync(0xffffffffu, s, 2);
        s += __shfl_xor_sync(0xffffffffu, s, 1);
        float mu = s * (1.f / 128.f);
        float ss = 0.f;
        #pragma unroll
        for (int c = 0; c < 32; c++) { float d = row[c] - mu; ss = fmaf(d, d, ss); }
        ss += __shfl_xor_sync(0xffffffffu, ss, 2);
        ss += __shfl_xor_sync(0xffffffffu, ss, 1);
        float rs = rsqrtf(ss * (1.f / 128.f) + LN_EPS);
        if (l4 == 0) { s_mu[r] = mu; s_rs[r] = rs; }
    }
    __syncthreads();

    {
        float4* out4 = (float4*)out;
        const float4* gm4 = (const float4*)gamma;
        const float4* bt4 = (const float4*)beta;
        for (int i = tid; i < BM * 32; i += 256) {
            int r = i >> 5, c4 = i & 31;
            if (n0 + r < N) {
                float4 v = ((const float4*)(sY + r * 132))[c4];
                float mu = s_mu[r], rs = s_rs[r];
                float4 gv = gm4[c4], bv = bt4[c4];
                v.x = fmaf((v.x - mu) * rs, gv.x, bv.x);
                v.y = fmaf((v.y - mu) * rs, gv.y, bv.y);
                v.z = fmaf((v.z - mu) * rs, gv.z, bv.z);
                v.w = fmaf((v.w - mu) * rs, gv.w, bv.w);
                out4[(size_t)(n0 + r) * 32 + c4] = v;
            }
        }
    }
}

extern "C" void kernel_launch(void* const* d_in, const int* in_sizes, int n_in,
                              void* d_out, int out_size) {
    const float* x     = (const float*)d_in[0];
    const void*  eidx  = d_in[1];
    const float* eattr = (const float*)d_in[2];
    const float* mW1 = (const float*)d_in[3];
    const float* mb1 = (const float*)d_in[4];
    const float* mW2 = (const float*)d_in[5];
    const float* mb2 = (const float*)d_in[6];
    const float* uW1 = (const float*)d_in[7];
    const float* ub1 = (const float*)d_in[8];
    const float* uW2 = (const float*)d_in[9];
    const float* ub2 = (const float*)d_in[10];
    const float* gamma = (const float*)d_in[11];
    const float* beta  = (const float*)d_in[12];
    float* out = (float*)d_out;

    const int N = in_sizes[0] / HID;   // 50000
    const int E = in_sizes[2] / HID;   // 640000

    cudaFuncSetAttribute(gemm128_kernel, cudaFuncAttributeMaxDynamicSharedMemorySize, GEMM_SMEM);
    cudaFuncSetAttribute(edge_fused,     cudaFuncAttributeMaxDynamicSharedMemorySize, EDGE_SMEM);
    cudaFuncSetAttribute(node_kernel,    cudaFuncAttributeMaxDynamicSharedMemorySize, NODE_SMEM);

    detect_kernel<<<1, 1>>>((const int*)eidx);
    compose_V<<<64, 256>>>(mW2, uW1, mb2);
    prepack_kernel<<<192, 256>>>(mW1, uW1, uW2);

    {
        float* aggp; cudaGetSymbolAddress((void**)&aggp, g_aggH);
        float* degp; cudaGetSymbolAddress((void**)&degp, g_deg);
        int a4 = MAXN * 32;
        zero_kernel<<<(a4 + 255) / 256, 256>>>(aggp, a4);
        int d4 = MAXN / 4;
        zero_kernel<<<(d4 + 255) / 256, 256>>>(degp, d4);
    }

    {
        float *Pp, *Qp;
        cudaGetSymbolAddress((void**)&Pp, g_P);
        cudaGetSymbolAddress((void**)&Qp, g_Q);
        unsigned *a_h, *a_l, *b_h, *b_l;
        cudaGetSymbolAddress((void**)&a_h, m1a_h); cudaGetSymbolAddress((void**)&a_l, m1a_l);
        cudaGetSymbolAddress((void**)&b_h, m1b_h); cudaGetSymbolAddress((void**)&b_l, m1b_l);
        gemm128_kernel<<<(N + BM - 1) / BM, 256, GEMM_SMEM>>>(x, a_h, a_l, Pp, N);
        gemm128_kernel<<<(N + BM - 1) / BM, 256, GEMM_SMEM>>>(x, b_h, b_l, Qp, N);
    }

    int nTiles = (E + 63) / 64;
    edge_fused<<<296, 256, EDGE_SMEM>>>(eattr, eidx, mb1, E, nTiles);

    node_kernel<<<(N + BM - 1) / BM, 256, NODE_SMEM>>>(x, ub1, ub2,
                                                       gamma, beta, out, N);
}

// round 16
// speedup vs baseline: 8.6170x; 1.0324x over previous
#include <cuda_runtime.h>
#include <cuda_pipeline.h>

#define HID 128
#define MAXN 50048
#define LN_EPS 1e-5f

#define BM 64
#define SA_STR 20      // uint32 stride per A row (16 + 4 pad)
#define SB_STR 132     // uint32 stride per B k2-row (128 + 4 pad)
#define SH_STR 68      // uint32 stride per H row (64 + 4 pad)

// node smem layout (uint32 units)
#define OFF_AH 0
#define OFF_AL (OFF_AH + 2*BM*SA_STR)   // 2560
#define OFF_BH (OFF_AL + 2*BM*SA_STR)   // 5120
#define OFF_BL (OFF_BH + 2*16*SB_STR)   // 9344
#define OFF_HH (OFF_BL + 2*16*SB_STR)   // 13568
#define OFF_HL (OFF_HH + BM*SH_STR)     // 17920
#define OFF_IX (OFF_HL + BM*SH_STR)     // 22272
#define SMEM_U (OFF_IX + 2*BM)          // 22400
#define NODE_SMEM (SMEM_U * 4)          // 89600

// fused P/Q GEMM smem (A double-buffer + 2 weights x hi/lo double-buffer)
#define PQ_B   (OFF_AL + 2*BM*SA_STR)   // 5120
#define PQ_SEG (16*SB_STR)              // 2112
#define PQ_BUF (4*PQ_SEG)               // 8448
#define PQ_SMEM ((PQ_B + 2*PQ_BUF) * 4) // 88064

// persistent edge kernel smem layout (uint32 units)
#define E_BH 0
#define E_BL (E_BH + 64*SB_STR)          // 8448
#define E_A  (E_BL + 64*SB_STR)          // 16896
#define E_AL (E_A + 64*SH_STR)           // 21248
#define E_IX (E_AL + 64*SH_STR)          // 25600
#define E_U  (E_IX + 256)                // 25856
#define EDGE_SMEM (E_U * 4)              // 103424

// scratch (static device memory)
__device__ __align__(256) float g_P[(size_t)MAXN * HID];   // x@W1a + b1
__device__ __align__(256) float g_Q[(size_t)MAXN * HID];   // x@W1b
__device__ __align__(256) float g_aggH[(size_t)MAXN * HID];
__device__ __align__(256) float g_deg[MAXN];
__device__ __align__(256) float g_V[128*128];
__device__ __align__(256) float g_vb[128];
__device__ int g_idx64;

// prepacked bf16x2 (hi,lo) weights, k-pair packed [k2][n]
__device__ __align__(16) unsigned m1a_h[64*128], m1a_l[64*128];
__device__ __align__(16) unsigned m1b_h[64*128], m1b_l[64*128];
__device__ __align__(16) unsigned m1c_h[64*128], m1c_l[64*128];
__device__ __align__(16) unsigned u1a_h[64*128], u1a_l[64*128];
__device__ __align__(16) unsigned vvh [64*128], vvl [64*128];
__device__ __align__(16) unsigned u2h [64*128], u2l [64*128];

// zero aggH + deg, and detect edge_index dtype, in one launch
__global__ void zeroall_kernel(const int* __restrict__ ei,
                               float* __restrict__ agg, float* __restrict__ deg,
                               int n4a, int n4d) {
    int i = blockIdx.x * blockDim.x + threadIdx.x;
    if (i == 0)
        g_idx64 = (ei[1] == 0 && ei[3] == 0 && ei[5] == 0 && ei[7] == 0) ? 1 : 0;
    if (i < n4a)
        ((float4*)agg)[i] = make_float4(0.f, 0.f, 0.f, 0.f);
    else if (i < n4a + n4d)
        ((float4*)deg)[i - n4a] = make_float4(0.f, 0.f, 0.f, 0.f);
}

// V = W2 @ U1b  (U1b = rows 128..255 of uW1); vb = b2 @ U1b
__global__ void compose_V(const float* __restrict__ mW2, const float* __restrict__ uW1,
                          const float* __restrict__ b2) {
    int i = blockIdx.x * 256 + threadIdx.x;
    if (i >= 16384) return;
    int r = i >> 7, j = i & 127;
    float s = 0.f;
    #pragma unroll 4
    for (int k = 0; k < 128; k++)
        s = fmaf(mW2[r * 128 + k], uW1[(size_t)(128 + k) * 128 + j], s);
    g_V[i] = s;
    if (i < 128) {
        float vb = 0.f;
        #pragma unroll 4
        for (int k = 0; k < 128; k++)
            vb = fmaf(b2[k], uW1[(size_t)(128 + k) * 128 + i], vb);
        g_vb[i] = vb;
    }
}

// split pair of fp32 -> packed bf16x2 hi + lo (low16 = first arg)
__device__ __forceinline__ void split2(float a, float b, unsigned& h, unsigned& l) {
    unsigned hp;
    asm("cvt.rn.satfinite.bf16x2.f32 %0, %1, %2;" : "=r"(hp) : "f"(b), "f"(a));
    float fa = __uint_as_float(hp << 16);
    float fb = __uint_as_float(hp & 0xffff0000u);
    float la = a - fa, lb = b - fb;
    unsigned lp;
    asm("cvt.rn.satfinite.bf16x2.f32 %0, %1, %2;" : "=r"(lp) : "f"(lb), "f"(la));
    h = hp; l = lp;
}

__global__ void prepack_kernel(const float* __restrict__ mW1,
                               const float* __restrict__ uW1,
                               const float* __restrict__ uW2) {
    int i = blockIdx.x * 256 + threadIdx.x;
    const float* W; unsigned *H, *L; int off, koff = 0;
    if (i < 8192)       { W = mW1; H = m1a_h; L = m1a_l; off = i; }
    else if (i < 16384) { W = mW1; H = m1b_h; L = m1b_l; off = i - 8192;  koff = 128; }
    else if (i < 24576) { W = mW1; H = m1c_h; L = m1c_l; off = i - 16384; koff = 256; }
    else if (i < 32768) { W = uW1; H = u1a_h; L = u1a_l; off = i - 24576; }
    else if (i < 40960) { W = g_V; H = vvh;   L = vvl;   off = i - 32768; }
    else if (i < 49152) { W = uW2; H = u2h;   L = u2l;   off = i - 40960; }
    else return;
    int k2 = off >> 7, n = off & 127;
    float v0 = W[(size_t)(koff + 2*k2) * 128 + n];
    float v1 = W[(size_t)(koff + 2*k2 + 1) * 128 + n];
    unsigned h, l; split2(v0, v1, h, l);
    H[off] = h; L[off] = l;
}

__device__ __forceinline__ void mma16(float d[4], const unsigned a[4], const unsigned b[2]) {
    asm volatile(
        "mma.sync.aligned.m16n8k16.row.col.f32.bf16.bf16.f32 "
        "{%0,%1,%2,%3}, {%4,%5,%6,%7}, {%8,%9}, {%0,%1,%2,%3};\n"
        : "+f"(d[0]), "+f"(d[1]), "+f"(d[2]), "+f"(d[3])
        : "r"(a[0]), "r"(a[1]), "r"(a[2]), "r"(a[3]), "r"(b[0]), "r"(b[1]));
}

__device__ __forceinline__ void red4(float* p, float4 v) {
    asm volatile("red.global.add.v4.f32 [%0], {%1, %2, %3, %4};"
                 :: "l"(p), "f"(v.x), "f"(v.y), "f"(v.z), "f"(v.w) : "memory");
}

// one K=32 chunk: acc += A(64x32) * B(32x128), 3-term bf16 split
__device__ __forceinline__ void frag_compute(
    const unsigned* __restrict__ Ah, const unsigned* __restrict__ Al, int astr,
    const unsigned* __restrict__ Bh, const unsigned* __restrict__ Bl,
    int g, int t, int wm, int wn, float acc[2][4][4])
{
    #pragma unroll
    for (int ks = 0; ks < 2; ks++) {
        unsigned ah[2][4], al[2][4];
        #pragma unroll
        for (int i = 0; i < 2; i++) {
            const unsigned* p = Ah + (wm*32 + i*16 + g) * astr + ks*8 + t;
            ah[i][0] = p[0]; ah[i][1] = p[8*astr]; ah[i][2] = p[4]; ah[i][3] = p[8*astr + 4];
            const unsigned* q = Al + (wm*32 + i*16 + g) * astr + ks*8 + t;
            al[i][0] = q[0]; al[i][1] = q[8*astr]; al[i][2] = q[4]; al[i][3] = q[8*astr + 4];
        }
        unsigned bh[4][2], bl[4][2];
        #pragma unroll
        for (int j = 0; j < 4; j++) {
            const unsigned* p = Bh + (ks*8 + t) * SB_STR + wn*32 + j*8 + g;
            bh[j][0] = p[0]; bh[j][1] = p[4*SB_STR];
            const unsigned* q = Bl + (ks*8 + t) * SB_STR + wn*32 + j*8 + g;
            bl[j][0] = q[0]; bl[j][1] = q[4*SB_STR];
        }
        #pragma unroll
        for (int i = 0; i < 2; i++)
            #pragma unroll
            for (int j = 0; j < 4; j++) {
                mma16(acc[i][j], ah[i], bh[j]);
                mma16(acc[i][j], al[i], bh[j]);
                mma16(acc[i][j], ah[i], bl[j]);
            }
    }
}

// dual-B chunk: accP += A*Ba, accQ += A*Bb (A fragments loaded once)
__device__ __forceinline__ void frag_dual(
    const unsigned* __restrict__ Ah, const unsigned* __restrict__ Al,
    const unsigned* __restrict__ Bbuf,
    int g, int t, int wm, int wn, float accP[2][4][4], float accQ[2][4][4])
{
    #pragma unroll
    for (int ks = 0; ks < 2; ks++) {
        unsigned ah[2][4], al[2][4];
        #pragma unroll
        for (int i = 0; i < 2; i++) {
            const unsigned* p = Ah + (wm*32 + i*16 + g) * SA_STR + ks*8 + t;
            ah[i][0] = p[0]; ah[i][1] = p[8*SA_STR]; ah[i][2] = p[4]; ah[i][3] = p[8*SA_STR + 4];
            const unsigned* q = Al + (wm*32 + i*16 + g) * SA_STR + ks*8 + t;
            al[i][0] = q[0]; al[i][1] = q[8*SA_STR]; al[i][2] = q[4]; al[i][3] = q[8*SA_STR + 4];
        }
        #pragma unroll
        for (int w = 0; w < 2; w++) {
            const unsigned* Bh = Bbuf + (2*w)     * PQ_SEG;
            const unsigned* Bl = Bbuf + (2*w + 1) * PQ_SEG;
            unsigned bh[4][2], bl[4][2];
            #pragma unroll
            for (int j = 0; j < 4; j++) {
                const unsigned* p = Bh + (ks*8 + t) * SB_STR + wn*32 + j*8 + g;
                bh[j][0] = p[0]; bh[j][1] = p[4*SB_STR];
                const unsigned* q = Bl + (ks*8 + t) * SB_STR + wn*32 + j*8 + g;
                bl[j][0] = q[0]; bl[j][1] = q[4*SB_STR];
            }
            float (*acc)[4][4] = w ? accQ : accP;
            #pragma unroll
            for (int i = 0; i < 2; i++)
                #pragma unroll
                for (int j = 0; j < 4; j++) {
                    mma16(acc[i][j], ah[i], bh[j]);
                    mma16(acc[i][j], al[i], bh[j]);
                    mma16(acc[i][j], ah[i], bl[j]);
                }
        }
    }
}

__device__ __forceinline__ void stage_w(unsigned* dst, const unsigned* src, int c, int tid) {
    #pragma unroll
    for (int i = tid; i < 512; i += 256) {
        int r = i >> 5, q = (i & 31) * 4;
        __pipeline_memcpy_async(dst + r * SB_STR + q, src + (size_t)(c*16 + r) * 128 + q, 16);
    }
}

__device__ __forceinline__ void stA(unsigned* sAh, unsigned* sAl, int tid, const float4 v[2]) {
    int row = tid >> 2, quad = tid & 3;
    unsigned* dh = sAh + row * SA_STR + quad * 4;
    unsigned* dl = sAl + row * SA_STR + quad * 4;
    #pragma unroll
    for (int q = 0; q < 2; q++) {
        unsigned h0, l0, h1, l1;
        split2(v[q].x, v[q].y, h0, l0);
        split2(v[q].z, v[q].w, h1, l1);
        dh[2*q] = h0; dh[2*q+1] = h1;
        dl[2*q] = l0; dl[2*q+1] = l1;
    }
}

__device__ __forceinline__ void zero_acc(float acc[2][4][4]) {
    #pragma unroll
    for (int i = 0; i < 2; i++)
        #pragma unroll
        for (int j = 0; j < 4; j++)
            #pragma unroll
            for (int r = 0; r < 4; r++) acc[i][j][r] = 0.f;
}

// K=128 GEMM mainloop over A staged from gmem (4 chunks, double-buffered).
#define GEMM_MAIN(ldA_expr, Wh, Wl) do { \
    float4 av[2]; \
    ldA_expr(0, av); \
    stage_w(sBhB, Wh, 0, tid); stage_w(sBlB, Wl, 0, tid); __pipeline_commit(); \
    stA(sAhB, sAlB, tid, av); \
    ldA_expr(1, av); \
    __pipeline_wait_prior(0); \
    __syncthreads(); \
    stage_w(sBhB + 16*SB_STR, Wh, 1, tid); stage_w(sBlB + 16*SB_STR, Wl, 1, tid); \
    __pipeline_commit(); \
    int b = 0; \
    _Pragma("unroll 1") \
    for (int c = 0; c < 4; c++) { \
        frag_compute(sAhB + b*(BM*SA_STR), sAlB + b*(BM*SA_STR), SA_STR, \
                     sBhB + b*(16*SB_STR), sBlB + b*(16*SB_STR), g, t, wm, wn, acc); \
        if (c == 3) break; \
        stA(sAhB + (b^1)*(BM*SA_STR), sAlB + (b^1)*(BM*SA_STR), tid, av); \
        if (c + 2 < 4) ldA_expr(c + 2, av); \
        __pipeline_wait_prior(0); \
        __syncthreads(); \
        if (c + 2 < 4) { \
            stage_w(sBhB + b*(16*SB_STR), Wh, c + 2, tid); \
            stage_w(sBlB + b*(16*SB_STR), Wl, c + 2, tid); \
            __pipeline_commit(); \
        } \
        b ^= 1; \
    } \
    __syncthreads(); \
} while (0)

// ---------------------------------------------------------------------------
// Fused dense GEMM: P = x@W1a + b1, Q = x@W1b. x staged once. 64 rows/CTA.
// ---------------------------------------------------------------------------
__global__ __launch_bounds__(256)
void gemmPQ_kernel(const float* __restrict__ x, const float* __restrict__ b1, int N)
{
    extern __shared__ unsigned smu[];
    unsigned* sAhB = smu + OFF_AH;
    unsigned* sAlB = smu + OFF_AL;
    unsigned* sB   = smu + PQ_B;

    const int tid = threadIdx.x;
    const int n0 = blockIdx.x * BM;
    const int lane = tid & 31, wid = tid >> 5;
    const int wm = wid >> 2, wn = wid & 3, g = lane >> 2, t = lane & 3;

    const int arow = tid >> 2, akh = (tid & 3) * 8;
    int ar = n0 + arow; if (ar >= N) ar = N - 1;
    const float* Ab = x + (size_t)ar * HID;
    auto ldA = [&](int c, float4 v[2]) {
        const float4* s4 = (const float4*)(Ab + c * 32 + akh);
        v[0] = s4[0]; v[1] = s4[1];
    };
    auto stageBoth = [&](int c, int buf) {
        unsigned* base = sB + buf * PQ_BUF;
        stage_w(base + 0*PQ_SEG, m1a_h, c, tid);
        stage_w(base + 1*PQ_SEG, m1a_l, c, tid);
        stage_w(base + 2*PQ_SEG, m1b_h, c, tid);
        stage_w(base + 3*PQ_SEG, m1b_l, c, tid);
    };

    float accP[2][4][4], accQ[2][4][4];
    zero_acc(accP); zero_acc(accQ);

    float4 av[2];
    ldA(0, av);
    stageBoth(0, 0); __pipeline_commit();
    stA(sAhB, sAlB, tid, av);
    ldA(1, av);
    __pipeline_wait_prior(0);
    __syncthreads();
    stageBoth(1, 1); __pipeline_commit();

    int b = 0;
    #pragma unroll 1
    for (int c = 0; c < 4; c++) {
        frag_dual(sAhB + b*(BM*SA_STR), sAlB + b*(BM*SA_STR), sB + b*PQ_BUF,
                  g, t, wm, wn, accP, accQ);
        if (c == 3) break;
        stA(sAhB + (b^1)*(BM*SA_STR), sAlB + (b^1)*(BM*SA_STR), tid, av);
        if (c + 2 < 4) ldA(c + 2, av);
        __pipeline_wait_prior(0);
        __syncthreads();
        if (c + 2 < 4) { stageBoth(c + 2, b); __pipeline_commit(); }
        b ^= 1;
    }

    #pragma unroll
    for (int i = 0; i < 2; i++) {
        int ra = wm*32 + i*16 + g;
        #pragma unroll
        for (int j = 0; j < 4; j++) {
            int c0 = wn*32 + j*8 + 2*t;
            float2 bb = *(const float2*)(b1 + c0);
            int na = n0 + ra, nb = na + 8;
            if (na < N) {
                *(float2*)(g_P + (size_t)na * HID + c0) =
                    make_float2(accP[i][j][0] + bb.x, accP[i][j][1] + bb.y);
                *(float2*)(g_Q + (size_t)na * HID + c0) =
                    make_float2(accQ[i][j][0], accQ[i][j][1]);
            }
            if (nb < N) {
                *(float2*)(g_P + (size_t)nb * HID + c0) =
                    make_float2(accP[i][j][2] + bb.x, accP[i][j][3] + bb.y);
                *(float2*)(g_Q + (size_t)nb * HID + c0) =
                    make_float2(accQ[i][j][2], accQ[i][j][3]);
            }
        }
    }
}

// ---------------------------------------------------------------------------
// Persistent fused edge kernel: W1c resident; per 64-edge tile:
//   R = eattr@W1c; h = relu(R + P[src] + Q[dst]); red4 aggH[dst]; deg++
// Epilogue software-pipelined (prefetch next row's P/Q).
// ---------------------------------------------------------------------------
__global__ __launch_bounds__(256, 2)
void edge_fused(const float* __restrict__ eattr, const void* __restrict__ eidx,
                int E, int nTiles)
{
    extern __shared__ unsigned smu[];
    unsigned* sBh = smu + E_BH;
    unsigned* sBl = smu + E_BL;
    unsigned* sAh = smu + E_A;
    unsigned* sAl = smu + E_AL;
    float* sY = (float*)(smu + E_A);      // overlays A region after compute
    int* s_idx = (int*)(smu + E_IX);      // 2 buffers x (64 src + 64 dst)

    const int tid = threadIdx.x;
    const int lane = tid & 31, wid = tid >> 5;
    const int wm = wid >> 2, wn = wid & 3, g = lane >> 2, t = lane & 3;
    const int arow = tid >> 2;            // 0..63
    const int kq = tid & 3;               // quarter of K (32 fp32)

    // stage full W1c (hi+lo) once
    #pragma unroll 4
    for (int i = tid; i < 2048; i += 256) {
        int r = i >> 5, q = (i & 31) * 4;
        __pipeline_memcpy_async(sBh + r * SB_STR + q, m1c_h + (size_t)r * 128 + q, 16);
        __pipeline_memcpy_async(sBl + r * SB_STR + q, m1c_l + (size_t)r * 128 + q, 16);
    }
    __pipeline_commit();

    auto ld_idx = [&](int tile, int buf) {
        if (tid < 64) {
            int e = tile * 64 + tid; if (e >= E) e = E - 1;
            int s, d;
            if (g_idx64) {
                s = (int)((const long long*)eidx)[e];
                d = (int)((const long long*)eidx)[(size_t)E + e];
            } else {
                s = ((const int*)eidx)[e];
                d = ((const int*)eidx)[(size_t)E + e];
            }
            s_idx[buf * 128 + tid] = s;
            s_idx[buf * 128 + 64 + tid] = d;
        }
    };
    auto ld_A = [&](int tile, float4 v[8]) {
        int e = tile * 64 + arow; if (e >= E) e = E - 1;
        const float4* s4 = (const float4*)(eattr + (size_t)e * HID + kq * 32);
        #pragma unroll
        for (int i = 0; i < 8; i++) v[i] = s4[i];
    };

    float4 av[8];
    int tile0 = blockIdx.x;
    if (tile0 < nTiles) { ld_idx(tile0, 0); ld_A(tile0, av); }
    __pipeline_wait_prior(0);
    __syncthreads();

    int pb = 0;
    #pragma unroll 1
    for (int tile = tile0; tile < nTiles; tile += gridDim.x) {
        // split + STS A
        {
            unsigned* dh = sAh + arow * SH_STR + kq * 16;
            unsigned* dl = sAl + arow * SH_STR + kq * 16;
            #pragma unroll
            for (int q = 0; q < 4; q++) {
                unsigned h0, l0, h1, l1, h2, l2, h3, l3;
                split2(av[2*q].x,   av[2*q].y,   h0, l0);
                split2(av[2*q].z,   av[2*q].w,   h1, l1);
                split2(av[2*q+1].x, av[2*q+1].y, h2, l2);
                split2(av[2*q+1].z, av[2*q+1].w, h3, l3);
                *(uint4*)(dh + 4*q) = make_uint4(h0, h1, h2, h3);
                *(uint4*)(dl + 4*q) = make_uint4(l0, l1, l2, l3);
            }
        }
        __syncthreads();

        float acc[2][4][4];
        zero_acc(acc);
        #pragma unroll
        for (int c = 0; c < 4; c++)
            frag_compute(sAh + c*16, sAl + c*16, SH_STR,
                         sBh + c*16*SB_STR, sBl + c*16*SB_STR,
                         g, t, wm, wn, acc);
        __syncthreads();   // A dead

        // acc -> sY
        #pragma unroll
        for (int i = 0; i < 2; i++) {
            int ra = wm*32 + i*16 + g;
            #pragma unroll
            for (int j = 0; j < 4; j++) {
                int c0 = wn*32 + j*8 + 2*t;
                *(float2*)(sY + ra * 132 + c0)     = make_float2(acc[i][j][0], acc[i][j][1]);
                *(float2*)(sY + (ra+8) * 132 + c0) = make_float2(acc[i][j][2], acc[i][j][3]);
            }
        }

        // prefetch next tile
        int ntile = tile + gridDim.x;
        if (ntile < nTiles) { ld_idx(ntile, pb ^ 1); ld_A(ntile, av); }
        __syncthreads();   // sY complete

        // software-pipelined epilogue: one warp per row, 8 rows per warp
        const int* sb = s_idx + pb * 128;
        int e0 = tile * 64;
        int base_r = wid * 8;
        float4 pv = ((const float4*)(g_P + (size_t)sb[base_r] * HID))[lane];
        float4 qv = ((const float4*)(g_Q + (size_t)sb[64 + base_r] * HID))[lane];
        #pragma unroll
        for (int rr = 0; rr < 8; rr++) {
            int r = base_r + rr;
            int d = sb[64 + r];
            float4 pc = pv, qc = qv;
            if (rr < 7) {
                pv = ((const float4*)(g_P + (size_t)sb[r + 1] * HID))[lane];
                qv = ((const float4*)(g_Q + (size_t)sb[64 + r + 1] * HID))[lane];
            }
            if (e0 + r < E) {
                float4 yv = ((const float4*)(sY + r * 132))[lane];
                float4 h;
                h.x = fmaxf(yv.x + pc.x + qc.x, 0.f);
                h.y = fmaxf(yv.y + pc.y + qc.y, 0.f);
                h.z = fmaxf(yv.z + pc.z + qc.z, 0.f);
                h.w = fmaxf(yv.w + pc.w + qc.w, 0.f);
                red4(g_aggH + (size_t)d * HID + lane * 4, h);
                if (lane == 0)
                    asm volatile("red.global.add.f32 [%0], %1;" :: "l"(g_deg + d), "f"(1.0f) : "memory");
            }
        }
        __syncthreads();   // epilogue reads done before next STS overwrites sY/A
        pb ^= 1;
    }
}

// ---------------------------------------------------------------------------
// Node kernel: u = relu(aggH@V + x@U1a + deg*vb + ub1); upd = u@U2 + ub2;
// out = LN(x + upd)
// ---------------------------------------------------------------------------
__global__ __launch_bounds__(256, 2)
void node_kernel(const float* __restrict__ x,
                 const float* __restrict__ ub1, const float* __restrict__ ub2,
                 const float* __restrict__ gamma, const float* __restrict__ beta,
                 float* __restrict__ out, int N)
{
    extern __shared__ unsigned smu[];
    unsigned* sAhB = smu + OFF_AH;
    unsigned* sAlB = smu + OFF_AL;
    unsigned* sBhB = smu + OFF_BH;
    unsigned* sBlB = smu + OFF_BL;
    unsigned* sTh  = smu + OFF_HH;
    unsigned* sTl  = smu + OFF_HL;
    float* s_mu = (float*)(smu + OFF_IX);
    float* s_rs = s_mu + BM;

    const int tid = threadIdx.x;
    const int n0 = blockIdx.x * BM;
    const int lane = tid & 31, wid = tid >> 5;
    const int wm = wid >> 2, wn = wid & 3, g = lane >> 2, t = lane & 3;

    const int arow = tid >> 2, akh = (tid & 3) * 8;
    int an = n0 + arow; if (an >= N) an = N - 1;
    const float* Ab_agg = g_aggH + (size_t)an * HID;
    const float* Ab_x   = x      + (size_t)an * HID;
    auto ldAagg = [&](int c, float4 v[2]) {
        const float4* s4 = (const float4*)(Ab_agg + c * 32 + akh);
        v[0] = s4[0]; v[1] = s4[1];
    };
    auto ldAx = [&](int c, float4 v[2]) {
        const float4* s4 = (const float4*)(Ab_x + c * 32 + akh);
        v[0] = s4[0]; v[1] = s4[1];
    };

    float acc[2][4][4];
    zero_acc(acc);
    GEMM_MAIN(ldAagg, vvh, vvl);     // acc  = aggH @ V
    GEMM_MAIN(ldAx,   u1a_h, u1a_l); // acc += x @ U1a

    // epilogue: + deg*vb + ub1, relu, split -> H tiles
    #pragma unroll
    for (int i = 0; i < 2; i++) {
        int r = wm*32 + i*16 + g;
        #pragma unroll
        for (int j = 0; j < 4; j++) {
            int c0 = wn*32 + j*8 + 2*t;
            int ci = wn*16 + j*4 + t;
            float2 bb = *(const float2*)(ub1 + c0);
            float2 vb = *(const float2*)(g_vb + c0);
            int na = n0 + r;     if (na >= N) na = N - 1;
            int nb = n0 + r + 8; if (nb >= N) nb = N - 1;
            float da = g_deg[na], db = g_deg[nb];
            float a0 = fmaxf(acc[i][j][0] + da*vb.x + bb.x, 0.f);
            float a1 = fmaxf(acc[i][j][1] + da*vb.y + bb.y, 0.f);
            float a2 = fmaxf(acc[i][j][2] + db*vb.x + bb.x, 0.f);
            float a3 = fmaxf(acc[i][j][3] + db*vb.y + bb.y, 0.f);
            unsigned h, l;
            split2(a0, a1, h, l);
            sTh[r * SH_STR + ci] = h; sTl[r * SH_STR + ci] = l;
            split2(a2, a3, h, l);
            sTh[(r+8) * SH_STR + ci] = h; sTl[(r+8) * SH_STR + ci] = l;
        }
    }
    __syncthreads();

    // ---- upd GEMM: u @ U2, K=128, A = H tiles ----
    zero_acc(acc);
    stage_w(sBhB, u2h, 0, tid); stage_w(sBlB, u2l, 0, tid); __pipeline_commit();
    __pipeline_wait_prior(0);
    __syncthreads();
    stage_w(sBhB + 16*SB_STR, u2h, 1, tid); stage_w(sBlB + 16*SB_STR, u2l, 1, tid);
    __pipeline_commit();
    int b = 0;
    #pragma unroll 1
    for (int c = 0; c < 4; c++) {
        frag_compute(sTh + c*16, sTl + c*16, SH_STR,
                     sBhB + b*(16*SB_STR), sBlB + b*(16*SB_STR), g, t, wm, wn, acc);
        if (c == 3) break;
        __pipeline_wait_prior(0);
        __syncthreads();
        if (c + 2 < 4) {
            stage_w(sBhB + b*(16*SB_STR), u2h, c + 2, tid);
            stage_w(sBlB + b*(16*SB_STR), u2l, c + 2, tid);
            __pipeline_commit();
        }
        b ^= 1;
    }

    __syncthreads();
    float* sY = (float*)sTh;   // [64][132] floats

    #pragma unroll
    for (int i = 0; i < 2; i++) {
        int ra = wm*32 + i*16 + g;
        #pragma unroll
        for (int j = 0; j < 4; j++) {
            int c0 = wn*32 + j*8 + 2*t;
            float2 bb = *(const float2*)(ub2 + c0);
            int na = n0 + ra;     if (na >= N) na = N - 1;
            int nb = n0 + ra + 8; if (nb >= N) nb = N - 1;
            float2 xa = *(const float2*)(x + (size_t)na * HID + c0);
            float2 xb = *(const float2*)(x + (size_t)nb * HID + c0);
            sY[ra * 132 + c0]         = acc[i][j][0] + bb.x + xa.x;
            sY[ra * 132 + c0 + 1]     = acc[i][j][1] + bb.y + xa.y;
            sY[(ra+8) * 132 + c0]     = acc[i][j][2] + bb.x + xb.x;
            sY[(ra+8) * 132 + c0 + 1] = acc[i][j][3] + bb.y + xb.y;
        }
    }
    __syncthreads();

    {
        int r = tid >> 2, l4 = tid & 3;
        const float* row = sY + r * 132 + l4 * 32;
        float s = 0.f;
        #pragma unroll
        for (int c = 0; c < 32; c++) s += row[c];
        s += __shfl_xor_sync(0xffffffffu, s, 2);
        s += __shfl_xor_sync(0xffffffffu, s, 1);
        float mu = s * (1.f / 128.f);
        float ss = 0.f;
        #pragma unroll
        for (int c = 0; c < 32; c++) { float d = row[c] - mu; ss = fmaf(d, d, ss); }
        ss += __shfl_xor_sync(0xffffffffu, ss, 2);
        ss += __shfl_xor_sync(0xffffffffu, ss, 1);
        float rs = rsqrtf(ss * (1.f / 128.f) + LN_EPS);
        if (l4 == 0) { s_mu[r] = mu; s_rs[r] = rs; }
    }
    __syncthreads();

    {
        float4* out4 = (float4*)out;
        const float4* gm4 = (const float4*)gamma;
        const float4* bt4 = (const float4*)beta;
        for (int i = tid; i < BM * 32; i += 256) {
            int r = i >> 5, c4 = i & 31;
            if (n0 + r < N) {
                float4 v = ((const float4*)(sY + r * 132))[c4];
                float mu = s_mu[r], rs = s_rs[r];
                float4 gv = gm4[c4], bv = bt4[c4];
                v.x = fmaf((v.x - mu) * rs, gv.x, bv.x);
                v.y = fmaf((v.y - mu) * rs, gv.y, bv.y);
                v.z = fmaf((v.z - mu) * rs, gv.z, bv.z);
                v.w = fmaf((v.w - mu) * rs, gv.w, bv.w);
                out4[(size_t)(n0 + r) * 32 + c4] = v;
            }
        }
    }
}

extern "C" void kernel_launch(void* const* d_in, const int* in_sizes, int n_in,
                              void* d_out, int out_size) {
    const float* x     = (const float*)d_in[0];
    const void*  eidx  = d_in[1];
    const float* eattr = (const float*)d_in[2];
    const float* mW1 = (const float*)d_in[3];
    const float* mb1 = (const float*)d_in[4];
    const float* mW2 = (const float*)d_in[5];
    const float* mb2 = (const float*)d_in[6];
    const float* uW1 = (const float*)d_in[7];
    const float* ub1 = (const float*)d_in[8];
    const float* uW2 = (const float*)d_in[9];
    const float* ub2 = (const float*)d_in[10];
    const float* gamma = (const float*)d_in[11];
    const float* beta  = (const float*)d_in[12];
    float* out = (float*)d_out;

    const int N = in_sizes[0] / HID;   // 50000
    const int E = in_sizes[2] / HID;   // 640000

    cudaFuncSetAttribute(gemmPQ_kernel, cudaFuncAttributeMaxDynamicSharedMemorySize, PQ_SMEM);
    cudaFuncSetAttribute(edge_fused,    cudaFuncAttributeMaxDynamicSharedMemorySize, EDGE_SMEM);
    cudaFuncSetAttribute(node_kernel,   cudaFuncAttributeMaxDynamicSharedMemorySize, NODE_SMEM);

    // zero aggH + deg, detect idx dtype (one launch)
    {
        float* aggp; cudaGetSymbolAddress((void**)&aggp, g_aggH);
        float* degp; cudaGetSymbolAddress((void**)&degp, g_deg);
        int n4a = MAXN * 32, n4d = MAXN / 4;
        zeroall_kernel<<<(n4a + n4d + 255) / 256, 256>>>((const int*)eidx, aggp, degp, n4a, n4d);
    }
    compose_V<<<64, 256>>>(mW2, uW1, mb2);
    prepack_kernel<<<192, 256>>>(mW1, uW1, uW2);

    gemmPQ_kernel<<<(N + BM - 1) / BM, 256, PQ_SMEM>>>(x, mb1, N);

    int nTiles = (E + 63) / 64;
    edge_fused<<<296, 256, EDGE_SMEM>>>(eattr, eidx, E, nTiles);

    node_kernel<<<(N + BM - 1) / BM, 256, NODE_SMEM>>>(x, ub1, ub2,
                                                       gamma, beta, out, N);
}